// round 4
// baseline (speedup 1.0000x reference)
#include <cuda_runtime.h>
#include <cuda_fp16.h>
#include <math.h>
#include <stdint.h>
#include <stddef.h>

#define DIM   128
#define NN    20000
#define NNZV  500000
#define EE    5000
#define CC    50
#define NENT  50000
#define NKEY  60000      // 3*NN
#define NHEAD 8
#define DH    16

// ----------------------------- scratch (device globals; no allocs) ----------
__device__ __align__(16) __half d_xt_h[3 * NN * DIM];   // x @ theta (fp16 payload)
__device__ __align__(16) __half d_me_h[3 * EE * DIM];   // hyperedge means (fp16)
__device__ float d_rel [NKEY * DIM];          // related = [ih; eh; wh] (fp32)
__device__ float d_Kb  [NKEY * DIM];
__device__ float d_Vb  [NKEY * DIM];
__device__ float d_qb  [CC * DIM];
__device__ __align__(16) __half d_S[NHEAD * CC * NKEY];   // attention scores (48MB)
__device__ float d_mstat[NHEAD * CC];
__device__ float d_lstat[NHEAD * CC];         // stores 1/l
__device__ float d_headout[CC * DIM];         // pre-Wo attention output (accumulated)
__device__ float d_att [CC * DIM];            // attentive = headout@Wo+bo
__device__ float d_u   [DIM];
__device__ float d_urepr[DIM];

__device__ int d_ecnt[3 * EE];
__device__ int d_eoff[3 * (EE + 1)];
__device__ int d_ecur[3 * EE];
__device__ int d_ncnt[3 * NN];
__device__ int d_noff[3 * (NN + 1)];
__device__ int d_ncur[3 * NN];
__device__ int d_csrE[3 * NNZV];              // per-edge entry lists (node ids)
__device__ int d_csrN[3 * NNZV];              // per-node entry lists (edge ids)

// tag -> device-global pointer (avoids cudaGetSymbolAddress on the host)
#define TAG_XT0 0
#define TAG_XT1 1
#define TAG_XT2 2
#define TAG_REL 3
#define TAG_K   4
#define TAG_V   5
#define TAG_Q   6
#define TAG_HO  7
#define TAG_ATT 8
__device__ __forceinline__ void* tag_ptrv(int t) {
    switch (t) {
        case TAG_XT0: return (void*)d_xt_h;
        case TAG_XT1: return (void*)(d_xt_h + (size_t)NN * DIM);
        case TAG_XT2: return (void*)(d_xt_h + (size_t)2 * NN * DIM);
        case TAG_REL: return (void*)d_rel;
        case TAG_K:   return (void*)d_Kb;
        case TAG_V:   return (void*)d_Vb;
        case TAG_Q:   return (void*)d_qb;
        case TAG_HO:  return (void*)d_headout;
        case TAG_ATT: return (void*)d_att;
    }
    return nullptr;
}

// ----------------------------- packed f32x2 helpers --------------------------
__device__ __forceinline__ void fma2(unsigned long long &acc,
                                     unsigned long long a, unsigned long long b) {
    asm("fma.rn.f32x2 %0, %1, %2, %0;" : "+l"(acc) : "l"(a), "l"(b));
}
__device__ __forceinline__ unsigned long long pack2dup(float x) {
    unsigned long long r; unsigned u = __float_as_uint(x);
    asm("mov.b64 %0, {%1, %1};" : "=l"(r) : "r"(u));
    return r;
}
__device__ __forceinline__ void unpack2(unsigned long long v, float &lo, float &hi) {
    unsigned a, b;
    asm("mov.b64 {%0, %1}, %2;" : "=r"(a), "=r"(b) : "l"(v));
    lo = __uint_as_float(a); hi = __uint_as_float(b);
}

// ----------------------------- zero accumulators ----------------------------
__global__ void zero_kernel() {
    int i = blockIdx.x * blockDim.x + threadIdx.x;
    if (i < 3 * EE)   d_ecnt[i] = 0;
    if (i < 3 * NN)   d_ncnt[i] = 0;
    if (i < CC * DIM) d_headout[i] = 0.f;
}

// ----------------------------- CSR build ------------------------------------
__global__ void count_kernel(const int* __restrict__ nodes,
                             const int* __restrict__ edges, int mod) {
    int i = blockIdx.x * blockDim.x + threadIdx.x;
    if (i >= NNZV) return;
    atomicAdd(&d_ecnt[mod * EE + edges[i]], 1);
    atomicAdd(&d_ncnt[mod * NN + nodes[i]], 1);
}

__global__ void scan_kernel() {
    __shared__ int s[1024];
    __shared__ int srun;
    int b = blockIdx.x;
    int mod = b % 3;
    bool isE = (b < 3);
    int len = isE ? EE : NN;
    const int* cnt = isE ? (d_ecnt + mod * EE) : (d_ncnt + mod * NN);
    int* off = isE ? (d_eoff + mod * (EE + 1)) : (d_noff + mod * (NN + 1));
    int* cur = isE ? (d_ecur + mod * EE) : (d_ncur + mod * NN);
    int tid = threadIdx.x;
    if (tid == 0) srun = 0;
    __syncthreads();
    for (int base = 0; base < len; base += 1024) {
        int v = (base + tid < len) ? cnt[base + tid] : 0;
        s[tid] = v;
        __syncthreads();
        for (int d = 1; d < 1024; d <<= 1) {
            int t = (tid >= d) ? s[tid - d] : 0;
            __syncthreads();
            s[tid] += t;
            __syncthreads();
        }
        int run = srun;
        if (base + tid < len) {
            int ex = run + s[tid] - v;
            off[base + tid] = ex;
            cur[base + tid] = ex;
        }
        __syncthreads();
        if (tid == 1023) srun = run + s[1023];
        __syncthreads();
    }
    if (tid == 0) off[len] = srun;
}

__global__ void scatter_kernel(const int* __restrict__ nodes,
                               const int* __restrict__ edges, int mod) {
    int i = blockIdx.x * blockDim.x + threadIdx.x;
    if (i >= NNZV) return;
    int e = edges[i], n = nodes[i];
    int pe = atomicAdd(&d_ecur[mod * EE + e], 1);
    d_csrE[mod * NNZV + pe] = n;
    int pn = atomicAdd(&d_ncur[mod * NN + n], 1);
    d_csrN[mod * NNZV + pn] = e;
}

// ----------------------------- 128x128-tile GEMM with f32x2 ------------------
// C[M,128] = A[M,128] @ W[128,128] (+ bias); 256 thr; 8x8 micro-tile / thread.
#define AS_STRIDE 40
__global__ __launch_bounds__(256, 2)
void gemm_tile(const float* __restrict__ Aext, int Atag,
               const float* __restrict__ W,
               const float* __restrict__ bias, int Ctag, int M, int half_out) {
    const float* A = (Aext != nullptr) ? Aext : (const float*)tag_ptrv(Atag);
    void* Cp = tag_ptrv(Ctag);
    __shared__ float As[128 * AS_STRIDE];    // [row][k] pad->160B stride
    __shared__ float Ws[32 * 132];           // [k][col] pad->528B stride
    int tid = threadIdx.x;
    int tx = tid & 15, ty = tid >> 4;        // 16x16 thread grid
    int row0 = blockIdx.x * 128;

    unsigned long long acc[8][4];
#pragma unroll
    for (int r = 0; r < 8; r++)
#pragma unroll
        for (int c = 0; c < 4; c++) acc[r][c] = 0ULL;

    for (int kt = 0; kt < 4; kt++) {
#pragma unroll
        for (int i = 0; i < 4; i++) {        // A tile 128x32
            int idx = tid + i * 256;
            int r = idx >> 3, kq = idx & 7;
            float4 v = make_float4(0.f, 0.f, 0.f, 0.f);
            if (row0 + r < M) v = *(const float4*)&A[(size_t)(row0 + r) * 128 + kt * 32 + kq * 4];
            *(float4*)&As[r * AS_STRIDE + kq * 4] = v;
        }
#pragma unroll
        for (int i = 0; i < 4; i++) {        // W tile 32x128
            int idx = tid + i * 256;
            int k = idx >> 5, cq = idx & 31;
            *(float4*)&Ws[k * 132 + cq * 4] = *(const float4*)&W[(size_t)(kt * 32 + k) * 128 + cq * 4];
        }
        __syncthreads();
#pragma unroll
        for (int kk = 0; kk < 32; kk++) {
            ulonglong2 bA = *(const ulonglong2*)&Ws[kk * 132 + tx * 8];
            ulonglong2 bB = *(const ulonglong2*)&Ws[kk * 132 + tx * 8 + 4];
            unsigned long long bp0 = bA.x, bp1 = bA.y, bp2 = bB.x, bp3 = bB.y;
#pragma unroll
            for (int r = 0; r < 8; r++) {
                unsigned long long ad = pack2dup(As[(ty * 8 + r) * AS_STRIDE + kk]);
                fma2(acc[r][0], ad, bp0);
                fma2(acc[r][1], ad, bp1);
                fma2(acc[r][2], ad, bp2);
                fma2(acc[r][3], ad, bp3);
            }
        }
        __syncthreads();
    }

    float b8[8];
    if (bias != nullptr) {
        float4 bb0 = *(const float4*)&bias[tx * 8];
        float4 bb1 = *(const float4*)&bias[tx * 8 + 4];
        b8[0]=bb0.x; b8[1]=bb0.y; b8[2]=bb0.z; b8[3]=bb0.w;
        b8[4]=bb1.x; b8[5]=bb1.y; b8[6]=bb1.z; b8[7]=bb1.w;
    } else {
#pragma unroll
        for (int c = 0; c < 8; c++) b8[c] = 0.f;
    }
#pragma unroll
    for (int r = 0; r < 8; r++) {
        int row = row0 + ty * 8 + r;
        if (row >= M) continue;
        float f[8];
#pragma unroll
        for (int c = 0; c < 4; c++) unpack2(acc[r][c], f[2 * c], f[2 * c + 1]);
#pragma unroll
        for (int c = 0; c < 8; c++) f[c] += b8[c];
        if (half_out) {
            __half2* dst = (__half2*)Cp + ((size_t)row * 128 + tx * 8) / 2;
            dst[0] = __floats2half2_rn(f[0], f[1]);
            dst[1] = __floats2half2_rn(f[2], f[3]);
            dst[2] = __floats2half2_rn(f[4], f[5]);
            dst[3] = __floats2half2_rn(f[6], f[7]);
        } else {
            float* dst = (float*)Cp + (size_t)row * 128 + tx * 8;
            *(float4*)dst       = make_float4(f[0], f[1], f[2], f[3]);
            *(float4*)(dst + 4) = make_float4(f[4], f[5], f[6], f[7]);
        }
    }
}

// ----------------------------- hyperedge means (warp per edge, fp16 payload) --
__global__ void edge_mean_kernel() {
    int gw = (blockIdx.x * blockDim.x + threadIdx.x) >> 5;
    int lane = threadIdx.x & 31;
    if (gw >= 3 * EE) return;
    int mod = gw / EE, e = gw - mod * EE;
    const int* __restrict__ base = d_csrE + mod * NNZV;
    int s0 = d_eoff[mod * (EE + 1) + e];
    int s1 = d_eoff[mod * (EE + 1) + e + 1];
    const uint2* __restrict__ xtm = (const uint2*)(d_xt_h + (size_t)mod * NN * DIM);
    float a0 = 0.f, a1 = 0.f, a2 = 0.f, a3 = 0.f;
    int j = s0;
    for (; j + 8 <= s1; j += 8) {
        int n[8];
#pragma unroll
        for (int u = 0; u < 8; u++) n[u] = base[j + u];
#pragma unroll
        for (int u = 0; u < 8; u++) {
            uint2 p = xtm[(size_t)n[u] * 32 + lane];
            float2 f0 = __half22float2(*(__half2*)&p.x);
            float2 f1 = __half22float2(*(__half2*)&p.y);
            a0 += f0.x; a1 += f0.y; a2 += f1.x; a3 += f1.y;
        }
    }
    for (; j < s1; j++) {
        uint2 p = xtm[(size_t)base[j] * 32 + lane];
        float2 f0 = __half22float2(*(__half2*)&p.x);
        float2 f1 = __half22float2(*(__half2*)&p.y);
        a0 += f0.x; a1 += f0.y; a2 += f1.x; a3 += f1.y;
    }
    int deg = s1 - s0; if (deg < 1) deg = 1;
    float inv = 1.f / (float)deg;
    uint2 o;
    *(__half2*)&o.x = __floats2half2_rn(a0 * inv, a1 * inv);
    *(__half2*)&o.y = __floats2half2_rn(a2 * inv, a3 * inv);
    ((uint2*)d_me_h)[((size_t)mod * EE + e) * 32 + lane] = o;
}

// ----------------------------- node output (warp per node) -------------------
__global__ void node_out_kernel(const float* __restrict__ bias_item,
                                const float* __restrict__ bias_entity,
                                const float* __restrict__ bias_word) {
    int gw = (blockIdx.x * blockDim.x + threadIdx.x) >> 5;
    int lane = threadIdx.x & 31;
    if (gw >= 3 * NN) return;
    int mod = gw / NN, n = gw - mod * NN;
    const int* __restrict__ base = d_csrN + mod * NNZV;
    int s0 = d_noff[mod * (NN + 1) + n];
    int s1 = d_noff[mod * (NN + 1) + n + 1];
    const uint2* __restrict__ mem = (const uint2*)(d_me_h + (size_t)mod * EE * DIM);
    float a0 = 0.f, a1 = 0.f, a2 = 0.f, a3 = 0.f;
    int j = s0;
    for (; j + 8 <= s1; j += 8) {
        int e8[8];
#pragma unroll
        for (int u = 0; u < 8; u++) e8[u] = base[j + u];
#pragma unroll
        for (int u = 0; u < 8; u++) {
            uint2 p = mem[(size_t)e8[u] * 32 + lane];
            float2 f0 = __half22float2(*(__half2*)&p.x);
            float2 f1 = __half22float2(*(__half2*)&p.y);
            a0 += f0.x; a1 += f0.y; a2 += f1.x; a3 += f1.y;
        }
    }
    for (; j < s1; j++) {
        uint2 p = mem[(size_t)base[j] * 32 + lane];
        float2 f0 = __half22float2(*(__half2*)&p.x);
        float2 f1 = __half22float2(*(__half2*)&p.y);
        a0 += f0.x; a1 += f0.y; a2 += f1.x; a3 += f1.y;
    }
    int deg = s1 - s0; if (deg < 1) deg = 1;
    float inv = 1.f / (float)deg;
    const float* bias = (mod == 0) ? bias_item : (mod == 1) ? bias_entity : bias_word;
    float4 bv = *(const float4*)&bias[lane * 4];
    *(float4*)&d_rel[((size_t)mod * NN + n) * DIM + lane * 4] =
        make_float4(a0 * inv + bv.x, a1 * inv + bv.y, a2 * inv + bv.z, a3 * inv + bv.w);
}

// ----------------------------- attention scores ------------------------------
#define SCORE_TILES 235
__global__ void scores_kernel() {
    int bx = blockIdx.x;
    int h = bx / SCORE_TILES;
    int k0 = (bx % SCORE_TILES) * 256;
    int key = k0 + threadIdx.x;
    __shared__ float qs[CC * DH];
    for (int i = threadIdx.x; i < CC * DH; i += 256) {
        int q = i / DH, d = i % DH;
        qs[i] = d_qb[q * DIM + h * DH + d];
    }
    float4 kv0, kv1, kv2, kv3;
    bool valid = key < NKEY;
    if (valid) {
        const float* kr = d_Kb + (size_t)key * DIM + h * DH;
        kv0 = *(const float4*)(kr + 0);
        kv1 = *(const float4*)(kr + 4);
        kv2 = *(const float4*)(kr + 8);
        kv3 = *(const float4*)(kr + 12);
    }
    __syncthreads();
    if (!valid) return;
    __half* Sh = d_S + (size_t)h * CC * NKEY + key;
#pragma unroll 5
    for (int q = 0; q < CC; q++) {
        const float4* qp = (const float4*)&qs[q * DH];
        float4 q0 = qp[0], q1 = qp[1], q2 = qp[2], q3 = qp[3];
        float acc = q0.x * kv0.x + q0.y * kv0.y + q0.z * kv0.z + q0.w * kv0.w
                  + q1.x * kv1.x + q1.y * kv1.y + q1.z * kv1.z + q1.w * kv1.w
                  + q2.x * kv2.x + q2.y * kv2.y + q2.z * kv2.z + q2.w * kv2.w
                  + q3.x * kv3.x + q3.y * kv3.y + q3.z * kv3.z + q3.w * kv3.w;
        Sh[(size_t)q * NKEY] = __float2half_rn(acc * 0.25f);   // / sqrt(16)
    }
}

// ----------------------------- softmax stats (block per (h,q)) ---------------
__global__ void stats_kernel() {
    int hq = blockIdx.x;
    const __half* row = d_S + (size_t)hq * NKEY;
    float m = -1e30f, l = 0.f;
    for (int k = threadIdx.x; k < NKEY; k += 256) {
        float s = __half2float(row[k]);
        if (s > m) { l = l * __expf(m - s) + 1.f; m = s; }
        else       { l += __expf(s - m); }
    }
    __shared__ float sm[256], sl[256];
    sm[threadIdx.x] = m; sl[threadIdx.x] = l;
    __syncthreads();
    for (int o = 128; o; o >>= 1) {
        if (threadIdx.x < o) {
            float m2 = sm[threadIdx.x + o], l2 = sl[threadIdx.x + o];
            float M = fmaxf(sm[threadIdx.x], m2);
            sl[threadIdx.x] = sl[threadIdx.x] * __expf(sm[threadIdx.x] - M)
                            + l2 * __expf(m2 - M);
            sm[threadIdx.x] = M;
        }
        __syncthreads();
    }
    if (threadIdx.x == 0) { d_mstat[hq] = sm[0]; d_lstat[hq] = 1.f / sl[0]; }
}

// ----------------------------- weighted V accumulation -----------------------
#define WV_CH 128
#define WV_CHUNKS 469
__global__ void wv_kernel() {
    int bx = blockIdx.x;
    int h = bx / WV_CHUNKS;
    int k0 = (bx % WV_CHUNKS) * WV_CH;
    int kmax = NKEY - k0; if (kmax > WV_CH) kmax = WV_CH;
    __shared__ float wsm[CC * 132];
    __shared__ float4 vsm[WV_CH * 4];
    int tid = threadIdx.x;
    for (int i = tid; i < WV_CH * 4; i += 256) {
        int k = i >> 2, dg = i & 3;
        float4 v = make_float4(0.f, 0.f, 0.f, 0.f);
        if (k < kmax) v = *(const float4*)&d_Vb[(size_t)(k0 + k) * DIM + h * DH + dg * 4];
        vsm[i] = v;
    }
    for (int i = tid; i < CC * WV_CH; i += 256) {
        int q = i / WV_CH, k = i - q * WV_CH;
        float w = 0.f;
        if (k < kmax) {
            int hq = h * CC + q;
            float s = __half2float(d_S[(size_t)hq * NKEY + k0 + k]);
            w = __expf(s - d_mstat[hq]) * d_lstat[hq];
        }
        wsm[q * 132 + k] = w;
    }
    __syncthreads();
    if (tid < CC * 4) {
        int q = tid >> 2, dg = tid & 3;
        float4 acc = make_float4(0.f, 0.f, 0.f, 0.f);
        const float* wr = wsm + q * 132;
#pragma unroll 4
        for (int k = 0; k < WV_CH; k++) {
            float w = wr[k];
            float4 v = vsm[k * 4 + dg];
            acc.x += w * v.x; acc.y += w * v.y; acc.z += w * v.z; acc.w += w * v.w;
        }
        float* dst = d_headout + q * DIM + h * DH + dg * 4;
        atomicAdd(dst + 0, acc.x); atomicAdd(dst + 1, acc.y);
        atomicAdd(dst + 2, acc.z); atomicAdd(dst + 3, acc.w);
    }
}

// ----------------------------- self attention (single block, 128 thr) --------
__global__ void selfattn_kernel(const float* __restrict__ Hext, int R, int which,
                                const float* __restrict__ A,
                                const float* __restrict__ Bv) {
    int d = threadIdx.x;
    const float* Hm = (which == 0) ? d_att : Hext;
    float* out = (which == 0) ? d_u : d_urepr;
    __shared__ float es[64];
    __shared__ float red[4];
    __shared__ float ws[64];
    for (int r = 0; r < R; r++) {
        const float* hr = (which == 1 && r == R - 1) ? d_u : (Hm + (size_t)r * DIM);
        float a0 = 0.f, a1 = 0.f, a2 = 0.f, a3 = 0.f;
#pragma unroll 8
        for (int k = 0; k < DIM; k += 4) {
            a0 += hr[k + 0] * A[(size_t)(k + 0) * DIM + d];
            a1 += hr[k + 1] * A[(size_t)(k + 1) * DIM + d];
            a2 += hr[k + 2] * A[(size_t)(k + 2) * DIM + d];
            a3 += hr[k + 3] * A[(size_t)(k + 3) * DIM + d];
        }
        float v = tanhf((a0 + a1) + (a2 + a3)) * Bv[d];
        for (int o = 16; o; o >>= 1) v += __shfl_down_sync(0xffffffffu, v, o);
        if ((d & 31) == 0) red[d >> 5] = v;
        __syncthreads();
        if (d == 0) es[r] = (red[0] + red[1]) + (red[2] + red[3]);
        __syncthreads();
    }
    if (d == 0) {
        float m = -1e30f;
        for (int r = 0; r < R; r++) m = fmaxf(m, es[r]);
        float s = 0.f;
        for (int r = 0; r < R; r++) { float w = __expf(es[r] - m); ws[r] = w; s += w; }
        float inv = 1.f / s;
        for (int r = 0; r < R; r++) ws[r] *= inv;
    }
    __syncthreads();
    float o = 0.f;
    for (int r = 0; r < R; r++) {
        const float* hr = (which == 1 && r == R - 1) ? d_u : (Hm + (size_t)r * DIM);
        o += ws[r] * hr[d];
    }
    out[d] = o;
}

// ----------------------------- final recommendation GEMV ---------------------
__global__ void recscore_kernel(const float* __restrict__ W,
                                const float* __restrict__ b,
                                float* __restrict__ out) {
    __shared__ float us[DIM];
    int tid = threadIdx.x;
    if (tid < DIM) us[tid] = d_urepr[tid];
    __syncthreads();
    int j = blockIdx.x * 256 + tid;
    if (j >= NENT) return;
    float a0 = 0.f, a1 = 0.f, a2 = 0.f, a3 = 0.f;
#pragma unroll
    for (int d = 0; d < DIM; d += 4) {
        a0 += us[d + 0] * W[(size_t)(d + 0) * NENT + j];
        a1 += us[d + 1] * W[(size_t)(d + 1) * NENT + j];
        a2 += us[d + 2] * W[(size_t)(d + 2) * NENT + j];
        a3 += us[d + 3] * W[(size_t)(d + 3) * NENT + j];
    }
    out[j] = (a0 + a1) + (a2 + a3) + b[j];
}

// ----------------------------- launch ----------------------------------------
extern "C" void kernel_launch(void* const* d_in, const int* in_sizes, int n_in,
                              void* d_out, int out_size) {
    const float* item_emb     = (const float*)d_in[0];
    const float* entity_emb   = (const float*)d_in[1];
    const float* word_emb     = (const float*)d_in[2];
    const float* context_ent  = (const float*)d_in[3];
    const float* theta_item   = (const float*)d_in[4];
    const float* bias_item    = (const float*)d_in[5];
    const float* theta_entity = (const float*)d_in[6];
    const float* bias_entity  = (const float*)d_in[7];
    const float* theta_word   = (const float*)d_in[8];
    const float* bias_word    = (const float*)d_in[9];
    const float* Wq = (const float*)d_in[10];  const float* bq = (const float*)d_in[11];
    const float* Wk = (const float*)d_in[12];  const float* bk = (const float*)d_in[13];
    const float* Wv = (const float*)d_in[14];  const float* bv = (const float*)d_in[15];
    const float* Wo = (const float*)d_in[16];  const float* bo = (const float*)d_in[17];
    const float* a_his = (const float*)d_in[18]; const float* b_his = (const float*)d_in[19];
    const float* a_kg  = (const float*)d_in[20]; const float* b_kg  = (const float*)d_in[21];
    const float* rec_W = (const float*)d_in[22]; const float* rec_b = (const float*)d_in[23];
    const int* item_nodes   = (const int*)d_in[24];
    const int* item_edges   = (const int*)d_in[25];
    const int* entity_nodes = (const int*)d_in[26];
    const int* entity_edges = (const int*)d_in[27];
    const int* word_nodes   = (const int*)d_in[28];
    const int* word_edges   = (const int*)d_in[29];
    float* out = (float*)d_out;

    // 1) zero accumulators / counters
    zero_kernel<<<(3 * NN + 255) / 256, 256>>>();

    // 2) xt = x @ theta (NO bias; fp16 output payload)
    gemm_tile<<<(NN + 127) / 128, 256>>>(item_emb,   -1, theta_item,   nullptr, TAG_XT0, NN, 1);
    gemm_tile<<<(NN + 127) / 128, 256>>>(entity_emb, -1, theta_entity, nullptr, TAG_XT1, NN, 1);
    gemm_tile<<<(NN + 127) / 128, 256>>>(word_emb,   -1, theta_word,   nullptr, TAG_XT2, NN, 1);

    // 3) CSR build
    count_kernel<<<(NNZV + 255) / 256, 256>>>(item_nodes,   item_edges,   0);
    count_kernel<<<(NNZV + 255) / 256, 256>>>(entity_nodes, entity_edges, 1);
    count_kernel<<<(NNZV + 255) / 256, 256>>>(word_nodes,   word_edges,   2);
    scan_kernel<<<6, 1024>>>();
    scatter_kernel<<<(NNZV + 255) / 256, 256>>>(item_nodes,   item_edges,   0);
    scatter_kernel<<<(NNZV + 255) / 256, 256>>>(entity_nodes, entity_edges, 1);
    scatter_kernel<<<(NNZV + 255) / 256, 256>>>(word_nodes,   word_edges,   2);

    // 4) hyperedge means, then node outputs (+bias) -> related (fp32)
    edge_mean_kernel<<<(3 * EE + 7) / 8, 256>>>();
    node_out_kernel<<<(3 * NN + 7) / 8, 256>>>(bias_item, bias_entity, bias_word);

    // 5) K/V/q projections (fp32 out)
    gemm_tile<<<(NKEY + 127) / 128, 256>>>(nullptr, TAG_REL, Wk, bk, TAG_K, NKEY, 0);
    gemm_tile<<<(NKEY + 127) / 128, 256>>>(nullptr, TAG_REL, Wv, bv, TAG_V, NKEY, 0);
    gemm_tile<<<1, 256>>>(context_ent, -1, Wq, bq, TAG_Q, CC, 0);

    // 6) attention
    scores_kernel<<<NHEAD * SCORE_TILES, 256>>>();
    stats_kernel<<<NHEAD * CC, 256>>>();
    wv_kernel<<<NHEAD * WV_CHUNKS, 256>>>();
    gemm_tile<<<1, 256>>>(nullptr, TAG_HO, Wo, bo, TAG_ATT, CC, 0);

    // 7) self attentions
    selfattn_kernel<<<1, 128>>>(nullptr,     CC,     0, a_his, b_his);
    selfattn_kernel<<<1, 128>>>(context_ent, CC + 1, 1, a_kg,  b_kg);

    // 8) final scores
    recscore_kernel<<<(NENT + 255) / 256, 256>>>(rec_W, rec_b, out);
}

// round 5
// speedup vs baseline: 1.0925x; 1.0925x over previous
#include <cuda_runtime.h>
#include <cuda_fp16.h>
#include <math.h>
#include <stdint.h>
#include <stddef.h>

#define DIM   128
#define NN    20000
#define NNZV  500000
#define EE    5000
#define CC    50
#define NENT  50000
#define NKEY  60000      // 3*NN
#define NHEAD 8
#define DH    16

// ----------------------------- scratch (device globals; no allocs) ----------
__device__ __align__(16) __half d_xt_h[3 * NN * DIM];   // x @ theta (fp16 payload)
__device__ __align__(16) __half d_me_h[3 * EE * DIM];   // hyperedge means (fp16)
__device__ float d_rel [NKEY * DIM];
__device__ float d_Kb  [NKEY * DIM];
__device__ float d_Vb  [NKEY * DIM];
__device__ float d_qb  [CC * DIM];
__device__ unsigned d_gmax[NHEAD * CC];       // ordered-uint max per (h,q)
__device__ float d_lsum[NHEAD * CC];          // sum exp per (h,q)
__device__ float d_headout[CC * DIM];         // unnormalized Σ w·V
__device__ float d_att [CC * DIM];
__device__ float d_u   [DIM];
__device__ float d_urepr[DIM];

__device__ int d_ecnt[3 * EE];
__device__ int d_eoff[3 * (EE + 1)];
__device__ int d_ecur[3 * EE];
__device__ int d_ncnt[3 * NN];
__device__ int d_noff[3 * (NN + 1)];
__device__ int d_ncur[3 * NN];
__device__ int d_csrE[3 * NNZV];
__device__ int d_csrN[3 * NNZV];

#define TAG_XT0 0
#define TAG_XT1 1
#define TAG_XT2 2
#define TAG_REL 3
#define TAG_K   4
#define TAG_V   5
#define TAG_Q   6
#define TAG_HO  7
#define TAG_ATT 8
__device__ __forceinline__ void* tag_ptrv(int t) {
    switch (t) {
        case TAG_XT0: return (void*)d_xt_h;
        case TAG_XT1: return (void*)(d_xt_h + (size_t)NN * DIM);
        case TAG_XT2: return (void*)(d_xt_h + (size_t)2 * NN * DIM);
        case TAG_REL: return (void*)d_rel;
        case TAG_K:   return (void*)d_Kb;
        case TAG_V:   return (void*)d_Vb;
        case TAG_Q:   return (void*)d_qb;
        case TAG_HO:  return (void*)d_headout;
        case TAG_ATT: return (void*)d_att;
    }
    return nullptr;
}

// ordered-uint encoding for float atomic max
__device__ __forceinline__ unsigned f2ord(float f) {
    unsigned b = __float_as_uint(f);
    return (b & 0x80000000u) ? ~b : (b | 0x80000000u);
}
__device__ __forceinline__ float ord2f(unsigned u) {
    unsigned b = (u & 0x80000000u) ? (u & 0x7FFFFFFFu) : ~u;
    return __uint_as_float(b);
}

// ----------------------------- zero / init ----------------------------------
__global__ void zero_kernel() {
    int i = blockIdx.x * blockDim.x + threadIdx.x;
    if (i < 3 * EE)        d_ecnt[i] = 0;
    if (i < 3 * NN)        d_ncnt[i] = 0;
    if (i < CC * DIM)      d_headout[i] = 0.f;
    if (i < NHEAD * CC)  { d_gmax[i] = 0u; d_lsum[i] = 0.f; }
}

// ----------------------------- CSR build (fused over modalities) ------------
__global__ void count_all(const int* __restrict__ n0, const int* __restrict__ e0,
                          const int* __restrict__ n1, const int* __restrict__ e1,
                          const int* __restrict__ n2, const int* __restrict__ e2) {
    int mod = blockIdx.y;
    const int* nodes = (mod == 0) ? n0 : (mod == 1) ? n1 : n2;
    const int* edges = (mod == 0) ? e0 : (mod == 1) ? e1 : e2;
    int i = blockIdx.x * blockDim.x + threadIdx.x;
    if (i >= NNZV) return;
    atomicAdd(&d_ecnt[mod * EE + edges[i]], 1);
    atomicAdd(&d_ncnt[mod * NN + nodes[i]], 1);
}

__device__ __forceinline__ int wscan_incl(int v, int lane) {
#pragma unroll
    for (int o = 1; o < 32; o <<= 1) {
        int t = __shfl_up_sync(0xffffffffu, v, o);
        if (lane >= o) v += t;
    }
    return v;
}

__global__ void scan_kernel() {
    __shared__ int wsum[32];
    __shared__ int srun, stot;
    int b = blockIdx.x;
    int mod = b % 3;
    bool isE = (b < 3);
    int len = isE ? EE : NN;
    const int* cnt = isE ? (d_ecnt + mod * EE) : (d_ncnt + mod * NN);
    int* off = isE ? (d_eoff + mod * (EE + 1)) : (d_noff + mod * (NN + 1));
    int* cur = isE ? (d_ecur + mod * EE) : (d_ncur + mod * NN);
    int tid = threadIdx.x, warp = tid >> 5, lane = tid & 31;
    if (tid == 0) srun = 0;
    __syncthreads();
    for (int base = 0; base < len; base += 1024) {
        int v = (base + tid < len) ? cnt[base + tid] : 0;
        int incl = wscan_incl(v, lane);
        if (lane == 31) wsum[warp] = incl;
        __syncthreads();
        if (warp == 0) {
            int s = wsum[lane];
            int wincl = wscan_incl(s, lane);
            wsum[lane] = wincl - s;
            if (lane == 31) stot = wincl;
        }
        __syncthreads();
        int run = srun;
        int ex = run + wsum[warp] + incl - v;
        if (base + tid < len) { off[base + tid] = ex; cur[base + tid] = ex; }
        __syncthreads();
        if (tid == 0) srun = run + stot;
        __syncthreads();
    }
    if (tid == 0) off[len] = srun;
}

__global__ void scatter_all(const int* __restrict__ n0, const int* __restrict__ e0,
                            const int* __restrict__ n1, const int* __restrict__ e1,
                            const int* __restrict__ n2, const int* __restrict__ e2) {
    int mod = blockIdx.y;
    const int* nodes = (mod == 0) ? n0 : (mod == 1) ? n1 : n2;
    const int* edges = (mod == 0) ? e0 : (mod == 1) ? e1 : e2;
    int i = blockIdx.x * blockDim.x + threadIdx.x;
    if (i >= NNZV) return;
    int e = edges[i], n = nodes[i];
    int pe = atomicAdd(&d_ecur[mod * EE + e], 1);
    d_csrE[mod * NNZV + pe] = n;
    int pn = atomicAdd(&d_ncur[mod * NN + n], 1);
    d_csrN[mod * NNZV + pn] = e;
}

// ----------------------------- GEMM: C[M,128]=A@W(+b) -----------------------
// 256 thr, 64 rows/block; warp=8 rows, lane=4 cols. A tile transposed to
// float4 k-quads for LDS.128 broadcast. Inner: 12 LDS.128 per 128 FFMA.
__global__ __launch_bounds__(256, 2)
void gemm_tile(const float* __restrict__ Aext, int Atag,
               const float* __restrict__ W,
               const float* __restrict__ bias, int Ctag, int M, int half_out) {
    const float* A = (Aext != nullptr) ? Aext : (const float*)tag_ptrv(Atag);
    void* Cp = tag_ptrv(Ctag);
    __shared__ float4 As4[8 * 65];           // [kq][row], pad 65 -> conflict-free
    __shared__ float Ws[32 * 132];           // [k][col]
    int tid = threadIdx.x;
    int warp = tid >> 5, lane = tid & 31;
    int row0 = blockIdx.x * 64;

    float4 acc[8];
#pragma unroll
    for (int r = 0; r < 8; r++) acc[r] = make_float4(0.f, 0.f, 0.f, 0.f);

    for (int kt = 0; kt < 4; kt++) {
#pragma unroll
        for (int i = 0; i < 2; i++) {        // A tile 64 rows x 32 k
            int idx = tid + i * 256;         // 512 float4 loads
            int r = idx >> 3, cq = idx & 7;
            float4 v = make_float4(0.f, 0.f, 0.f, 0.f);
            if (row0 + r < M) v = *(const float4*)&A[(size_t)(row0 + r) * 128 + kt * 32 + cq * 4];
            As4[cq * 65 + r] = v;
        }
#pragma unroll
        for (int i = 0; i < 4; i++) {        // W tile 32 k x 128 cols
            int idx = tid + i * 256;
            int k = idx >> 5, cq = idx & 31;
            *(float4*)&Ws[k * 132 + cq * 4] = *(const float4*)&W[(size_t)(kt * 32 + k) * 128 + cq * 4];
        }
        __syncthreads();
#pragma unroll
        for (int kq = 0; kq < 8; kq++) {
            float4 a[8];
#pragma unroll
            for (int r = 0; r < 8; r++) a[r] = As4[kq * 65 + warp * 8 + r];
#pragma unroll
            for (int j = 0; j < 4; j++) {
                int kk = kq * 4 + j;
                float4 w = *(const float4*)&Ws[kk * 132 + lane * 4];
#pragma unroll
                for (int r = 0; r < 8; r++) {
                    float av = (j == 0) ? a[r].x : (j == 1) ? a[r].y : (j == 2) ? a[r].z : a[r].w;
                    acc[r].x += av * w.x; acc[r].y += av * w.y;
                    acc[r].z += av * w.z; acc[r].w += av * w.w;
                }
            }
        }
        __syncthreads();
    }

    float4 bv = make_float4(0.f, 0.f, 0.f, 0.f);
    if (bias != nullptr) bv = *(const float4*)&bias[lane * 4];
#pragma unroll
    for (int r = 0; r < 8; r++) {
        int row = row0 + warp * 8 + r;
        if (row >= M) continue;
        float4 o = make_float4(acc[r].x + bv.x, acc[r].y + bv.y,
                               acc[r].z + bv.z, acc[r].w + bv.w);
        if (half_out) {
            __half2* dst = (__half2*)Cp + ((size_t)row * 128 + lane * 4) / 2;
            dst[0] = __floats2half2_rn(o.x, o.y);
            dst[1] = __floats2half2_rn(o.z, o.w);
        } else {
            *(float4*)((float*)Cp + (size_t)row * 128 + lane * 4) = o;
        }
    }
}

// ----------------------------- hyperedge means (warp per edge, fp16) ---------
__global__ void edge_mean_kernel() {
    int gw = (blockIdx.x * blockDim.x + threadIdx.x) >> 5;
    int lane = threadIdx.x & 31;
    if (gw >= 3 * EE) return;
    int mod = gw / EE, e = gw - mod * EE;
    const int* __restrict__ base = d_csrE + mod * NNZV;
    int s0 = d_eoff[mod * (EE + 1) + e];
    int s1 = d_eoff[mod * (EE + 1) + e + 1];
    const uint2* __restrict__ xtm = (const uint2*)(d_xt_h + (size_t)mod * NN * DIM);
    float a0 = 0.f, a1 = 0.f, a2 = 0.f, a3 = 0.f;
    int j = s0;
    for (; j + 8 <= s1; j += 8) {
        int n[8];
#pragma unroll
        for (int u = 0; u < 8; u++) n[u] = base[j + u];
#pragma unroll
        for (int u = 0; u < 8; u++) {
            uint2 p = xtm[(size_t)n[u] * 32 + lane];
            float2 f0 = __half22float2(*(__half2*)&p.x);
            float2 f1 = __half22float2(*(__half2*)&p.y);
            a0 += f0.x; a1 += f0.y; a2 += f1.x; a3 += f1.y;
        }
    }
    for (; j < s1; j++) {
        uint2 p = xtm[(size_t)base[j] * 32 + lane];
        float2 f0 = __half22float2(*(__half2*)&p.x);
        float2 f1 = __half22float2(*(__half2*)&p.y);
        a0 += f0.x; a1 += f0.y; a2 += f1.x; a3 += f1.y;
    }
    int deg = s1 - s0; if (deg < 1) deg = 1;
    float inv = 1.f / (float)deg;
    uint2 o;
    *(__half2*)&o.x = __floats2half2_rn(a0 * inv, a1 * inv);
    *(__half2*)&o.y = __floats2half2_rn(a2 * inv, a3 * inv);
    ((uint2*)d_me_h)[((size_t)mod * EE + e) * 32 + lane] = o;
}

// ----------------------------- node output (warp per node) -------------------
__global__ void node_out_kernel(const float* __restrict__ bias_item,
                                const float* __restrict__ bias_entity,
                                const float* __restrict__ bias_word) {
    int gw = (blockIdx.x * blockDim.x + threadIdx.x) >> 5;
    int lane = threadIdx.x & 31;
    if (gw >= 3 * NN) return;
    int mod = gw / NN, n = gw - mod * NN;
    const int* __restrict__ base = d_csrN + mod * NNZV;
    int s0 = d_noff[mod * (NN + 1) + n];
    int s1 = d_noff[mod * (NN + 1) + n + 1];
    const uint2* __restrict__ mem = (const uint2*)(d_me_h + (size_t)mod * EE * DIM);
    float a0 = 0.f, a1 = 0.f, a2 = 0.f, a3 = 0.f;
    int j = s0;
    for (; j + 8 <= s1; j += 8) {
        int e8[8];
#pragma unroll
        for (int u = 0; u < 8; u++) e8[u] = base[j + u];
#pragma unroll
        for (int u = 0; u < 8; u++) {
            uint2 p = mem[(size_t)e8[u] * 32 + lane];
            float2 f0 = __half22float2(*(__half2*)&p.x);
            float2 f1 = __half22float2(*(__half2*)&p.y);
            a0 += f0.x; a1 += f0.y; a2 += f1.x; a3 += f1.y;
        }
    }
    for (; j < s1; j++) {
        uint2 p = mem[(size_t)base[j] * 32 + lane];
        float2 f0 = __half22float2(*(__half2*)&p.x);
        float2 f1 = __half22float2(*(__half2*)&p.y);
        a0 += f0.x; a1 += f0.y; a2 += f1.x; a3 += f1.y;
    }
    int deg = s1 - s0; if (deg < 1) deg = 1;
    float inv = 1.f / (float)deg;
    const float* bias = (mod == 0) ? bias_item : (mod == 1) ? bias_entity : bias_word;
    float4 bv = *(const float4*)&bias[lane * 4];
    *(float4*)&d_rel[((size_t)mod * NN + n) * DIM + lane * 4] =
        make_float4(a0 * inv + bv.x, a1 * inv + bv.y, a2 * inv + bv.z, a3 * inv + bv.w);
}

// ----------------------------- flash attention pass1: row maxima -------------
#define AT_TILES 235
__global__ void attn_pass1() {
    int bx = blockIdx.x;
    int h = bx / AT_TILES;
    int key = (bx % AT_TILES) * 256 + threadIdx.x;
    int warp = threadIdx.x >> 5, lane = threadIdx.x & 31;
    __shared__ float qs[CC * DH];
    __shared__ float wred[8 * CC];
    for (int i = threadIdx.x; i < CC * DH; i += 256) {
        int q = i / DH, d = i % DH;
        qs[i] = d_qb[q * DIM + h * DH + d];
    }
    float4 kv0 = make_float4(0,0,0,0), kv1 = kv0, kv2 = kv0, kv3 = kv0;
    bool valid = key < NKEY;
    if (valid) {
        const float* kr = d_Kb + (size_t)key * DIM + h * DH;
        kv0 = *(const float4*)(kr + 0);  kv1 = *(const float4*)(kr + 4);
        kv2 = *(const float4*)(kr + 8);  kv3 = *(const float4*)(kr + 12);
    }
    __syncthreads();
#pragma unroll 5
    for (int q = 0; q < CC; q++) {
        const float4* qp = (const float4*)&qs[q * DH];
        float4 q0 = qp[0], q1 = qp[1], q2 = qp[2], q3 = qp[3];
        float s = q0.x*kv0.x + q0.y*kv0.y + q0.z*kv0.z + q0.w*kv0.w
                + q1.x*kv1.x + q1.y*kv1.y + q1.z*kv1.z + q1.w*kv1.w
                + q2.x*kv2.x + q2.y*kv2.y + q2.z*kv2.z + q2.w*kv2.w
                + q3.x*kv3.x + q3.y*kv3.y + q3.z*kv3.z + q3.w*kv3.w;
        s = valid ? s * 0.25f : -1e30f;
#pragma unroll
        for (int o = 16; o; o >>= 1) s = fmaxf(s, __shfl_xor_sync(0xffffffffu, s, o));
        if (lane == 0) wred[warp * CC + q] = s;
    }
    __syncthreads();
    if (threadIdx.x < CC) {
        float m = wred[threadIdx.x];
#pragma unroll
        for (int w = 1; w < 8; w++) m = fmaxf(m, wred[w * CC + threadIdx.x]);
        atomicMax(&d_gmax[h * CC + threadIdx.x], f2ord(m));
    }
}

// ----------------------------- flash attention pass2: w·V + Σw ---------------
#define WSTRIDE 258
__global__ void attn_pass2() {
    int bx = blockIdx.x;
    int h = bx / AT_TILES;
    int k0 = (bx % AT_TILES) * 256;
    int tid = threadIdx.x;
    int key = k0 + tid;
    __shared__ float qs[CC * DH];
    __shared__ float msm[CC];
    __shared__ __half wsm[CC * WSTRIDE];
    __shared__ float4 vsm[256 * 4];
    for (int i = tid; i < CC * DH; i += 256) {
        int q = i / DH, d = i % DH;
        qs[i] = d_qb[q * DIM + h * DH + d];
    }
    if (tid < CC) msm[tid] = ord2f(d_gmax[h * CC + tid]);
    for (int i = tid; i < 256 * 4; i += 256) {
        int k = i >> 2, dg = i & 3;
        float4 v = make_float4(0,0,0,0);
        if (k0 + k < NKEY) v = *(const float4*)&d_Vb[(size_t)(k0 + k) * DIM + h * DH + dg * 4];
        vsm[i] = v;
    }
    float4 kv0 = make_float4(0,0,0,0), kv1 = kv0, kv2 = kv0, kv3 = kv0;
    bool valid = key < NKEY;
    if (valid) {
        const float* kr = d_Kb + (size_t)key * DIM + h * DH;
        kv0 = *(const float4*)(kr + 0);  kv1 = *(const float4*)(kr + 4);
        kv2 = *(const float4*)(kr + 8);  kv3 = *(const float4*)(kr + 12);
    }
    __syncthreads();
#pragma unroll 5
    for (int q = 0; q < CC; q++) {
        const float4* qp = (const float4*)&qs[q * DH];
        float4 q0 = qp[0], q1 = qp[1], q2 = qp[2], q3 = qp[3];
        float s = q0.x*kv0.x + q0.y*kv0.y + q0.z*kv0.z + q0.w*kv0.w
                + q1.x*kv1.x + q1.y*kv1.y + q1.z*kv1.z + q1.w*kv1.w
                + q2.x*kv2.x + q2.y*kv2.y + q2.z*kv2.z + q2.w*kv2.w
                + q3.x*kv3.x + q3.y*kv3.y + q3.z*kv3.z + q3.w*kv3.w;
        float w = valid ? __expf(s * 0.25f - msm[q]) : 0.f;
        wsm[q * WSTRIDE + tid] = __float2half_rn(w);
    }
    __syncthreads();
    if (tid < CC * 4) {
        int q = tid >> 2, dg = tid & 3;
        float4 acc = make_float4(0,0,0,0);
        float lacc = 0.f;
        const __half* wr = wsm + q * WSTRIDE;
#pragma unroll 4
        for (int k = 0; k < 256; k++) {
            float w = __half2float(wr[k]);
            float4 v = vsm[k * 4 + dg];
            acc.x += w * v.x; acc.y += w * v.y; acc.z += w * v.z; acc.w += w * v.w;
            if (dg == 0) lacc += w;
        }
        float* dst = d_headout + q * DIM + h * DH + dg * 4;
        atomicAdd(dst + 0, acc.x); atomicAdd(dst + 1, acc.y);
        atomicAdd(dst + 2, acc.z); atomicAdd(dst + 3, acc.w);
        if (dg == 0) atomicAdd(&d_lsum[h * CC + q], lacc);
    }
}

__global__ void normalize_kernel() {
    int i = blockIdx.x * blockDim.x + threadIdx.x;
    if (i >= CC * DIM) return;
    int q = i >> 7, d = i & 127;
    int h = d >> 4;
    d_headout[i] *= (1.f / d_lsum[h * CC + q]);
}

// ----------------------------- self attention (1024 thr, warp/row) ----------
__global__ void selfattn_kernel(const float* __restrict__ Hext, int R, int which,
                                const float* __restrict__ A,
                                const float* __restrict__ Bv) {
    int tid = threadIdx.x;
    int warp = tid >> 5, lane = tid & 31;
    const float* Hm = (which == 0) ? d_att : Hext;
    float* out = (which == 0) ? d_u : d_urepr;
    __shared__ float es[64];
    __shared__ float ws[64];
    for (int r = warp; r < R; r += 32) {
        const float* hr = (which == 1 && r == R - 1) ? d_u : (Hm + (size_t)r * DIM);
        float4 acc = make_float4(0,0,0,0);
        for (int k = 0; k < DIM; k++) {
            float hk = hr[k];
            float4 a = *(const float4*)&A[(size_t)k * DIM + lane * 4];
            acc.x += hk * a.x; acc.y += hk * a.y; acc.z += hk * a.z; acc.w += hk * a.w;
        }
        float4 b4 = *(const float4*)&Bv[lane * 4];  // b is [D,1] -> b[d]
        float v = tanhf(acc.x) * b4.x + tanhf(acc.y) * b4.y
                + tanhf(acc.z) * b4.z + tanhf(acc.w) * b4.w;
#pragma unroll
        for (int o = 16; o; o >>= 1) v += __shfl_xor_sync(0xffffffffu, v, o);
        if (lane == 0) es[r] = v;
    }
    __syncthreads();
    if (tid == 0) {
        float m = -1e30f;
        for (int r = 0; r < R; r++) m = fmaxf(m, es[r]);
        float s = 0.f;
        for (int r = 0; r < R; r++) { float w = __expf(es[r] - m); ws[r] = w; s += w; }
        float inv = 1.f / s;
        for (int r = 0; r < R; r++) ws[r] *= inv;
    }
    __syncthreads();
    if (tid < DIM) {
        float o = 0.f;
        for (int r = 0; r < R; r++) {
            const float* hr = (which == 1 && r == R - 1) ? d_u : (Hm + (size_t)r * DIM);
            o += ws[r] * hr[tid];
        }
        out[tid] = o;
    }
}

// ----------------------------- final recommendation GEMV ---------------------
__global__ void recscore_kernel(const float* __restrict__ W,
                                const float* __restrict__ b,
                                float* __restrict__ out) {
    __shared__ float us[DIM];
    int tid = threadIdx.x;
    if (tid < DIM) us[tid] = d_urepr[tid];
    __syncthreads();
    int j = blockIdx.x * 256 + tid;
    if (j >= NENT) return;
    float a0 = 0.f, a1 = 0.f, a2 = 0.f, a3 = 0.f;
#pragma unroll
    for (int d = 0; d < DIM; d += 4) {
        a0 += us[d + 0] * W[(size_t)(d + 0) * NENT + j];
        a1 += us[d + 1] * W[(size_t)(d + 1) * NENT + j];
        a2 += us[d + 2] * W[(size_t)(d + 2) * NENT + j];
        a3 += us[d + 3] * W[(size_t)(d + 3) * NENT + j];
    }
    out[j] = (a0 + a1) + (a2 + a3) + b[j];
}

// ----------------------------- launch ----------------------------------------
extern "C" void kernel_launch(void* const* d_in, const int* in_sizes, int n_in,
                              void* d_out, int out_size) {
    const float* item_emb     = (const float*)d_in[0];
    const float* entity_emb   = (const float*)d_in[1];
    const float* word_emb     = (const float*)d_in[2];
    const float* context_ent  = (const float*)d_in[3];
    const float* theta_item   = (const float*)d_in[4];
    const float* bias_item    = (const float*)d_in[5];
    const float* theta_entity = (const float*)d_in[6];
    const float* bias_entity  = (const float*)d_in[7];
    const float* theta_word   = (const float*)d_in[8];
    const float* bias_word    = (const float*)d_in[9];
    const float* Wq = (const float*)d_in[10];  const float* bq = (const float*)d_in[11];
    const float* Wk = (const float*)d_in[12];  const float* bk = (const float*)d_in[13];
    const float* Wv = (const float*)d_in[14];  const float* bv = (const float*)d_in[15];
    const float* Wo = (const float*)d_in[16];  const float* bo = (const float*)d_in[17];
    const float* a_his = (const float*)d_in[18]; const float* b_his = (const float*)d_in[19];
    const float* a_kg  = (const float*)d_in[20]; const float* b_kg  = (const float*)d_in[21];
    const float* rec_W = (const float*)d_in[22]; const float* rec_b = (const float*)d_in[23];
    const int* item_nodes   = (const int*)d_in[24];
    const int* item_edges   = (const int*)d_in[25];
    const int* entity_nodes = (const int*)d_in[26];
    const int* entity_edges = (const int*)d_in[27];
    const int* word_nodes   = (const int*)d_in[28];
    const int* word_edges   = (const int*)d_in[29];
    float* out = (float*)d_out;

    zero_kernel<<<(3 * NN + 255) / 256, 256>>>();

    // xt = x @ theta (no bias; fp16 payload)
    gemm_tile<<<(NN + 63) / 64, 256>>>(item_emb,   -1, theta_item,   nullptr, TAG_XT0, NN, 1);
    gemm_tile<<<(NN + 63) / 64, 256>>>(entity_emb, -1, theta_entity, nullptr, TAG_XT1, NN, 1);
    gemm_tile<<<(NN + 63) / 64, 256>>>(word_emb,   -1, theta_word,   nullptr, TAG_XT2, NN, 1);

    // CSR build
    dim3 cgrid((NNZV + 255) / 256, 3);
    count_all<<<cgrid, 256>>>(item_nodes, item_edges, entity_nodes, entity_edges,
                              word_nodes, word_edges);
    scan_kernel<<<6, 1024>>>();
    scatter_all<<<cgrid, 256>>>(item_nodes, item_edges, entity_nodes, entity_edges,
                                word_nodes, word_edges);

    // hypergraph aggregation
    edge_mean_kernel<<<(3 * EE + 7) / 8, 256>>>();
    node_out_kernel<<<(3 * NN + 7) / 8, 256>>>(bias_item, bias_entity, bias_word);

    // K/V/q projections
    gemm_tile<<<(NKEY + 63) / 64, 256>>>(nullptr, TAG_REL, Wk, bk, TAG_K, NKEY, 0);
    gemm_tile<<<(NKEY + 63) / 64, 256>>>(nullptr, TAG_REL, Wv, bv, TAG_V, NKEY, 0);
    gemm_tile<<<1, 256>>>(context_ent, -1, Wq, bq, TAG_Q, CC, 0);

    // flash attention (no materialized S)
    attn_pass1<<<NHEAD * AT_TILES, 256>>>();
    attn_pass2<<<NHEAD * AT_TILES, 256>>>();
    normalize_kernel<<<(CC * DIM + 255) / 256, 256>>>();
    gemm_tile<<<1, 256>>>(nullptr, TAG_HO, Wo, bo, TAG_ATT, CC, 0);

    // self attentions
    selfattn_kernel<<<1, 1024>>>(nullptr,     CC,     0, a_his, b_his);
    selfattn_kernel<<<1, 1024>>>(context_ent, CC + 1, 1, a_kg,  b_kg);

    // final scores
    recscore_kernel<<<(NENT + 255) / 256, 256>>>(rec_W, rec_b, out);
}

// round 7
// speedup vs baseline: 2.0856x; 1.9090x over previous
#include <cuda_runtime.h>
#include <cuda_fp16.h>
#include <cuda_bf16.h>
#include <math.h>
#include <stdint.h>
#include <stddef.h>

#define DIM   128
#define NN    20000
#define NNZV  500000
#define EE    5000
#define CC    50
#define NENT  50000
#define NKEY  60000
#define NHEAD 8
#define DH    16

#define NN_PAD   20096      // 157 tiles * 128
#define NKEY_PAD 60032      // 469 tiles * 128
#define NTILE_NN   157
#define NTILE_NKEY 469

// ===================== helpers ==============================================
__device__ __forceinline__ uint32_t smem_u32(const void* p) {
    uint32_t a;
    asm("{ .reg .u64 t; cvta.to.shared.u64 t, %1; cvt.u32.u64 %0, t; }"
        : "=r"(a) : "l"(p));
    return a;
}
__device__ __forceinline__ void ldsm4(uint32_t& r0, uint32_t& r1,
                                      uint32_t& r2, uint32_t& r3, uint32_t addr) {
    asm volatile("ldmatrix.sync.aligned.m8n8.x4.shared.b16 {%0,%1,%2,%3}, [%4];"
                 : "=r"(r0), "=r"(r1), "=r"(r2), "=r"(r3) : "r"(addr));
}
__device__ __forceinline__ void mma16816(float* c,
        uint32_t a0, uint32_t a1, uint32_t a2, uint32_t a3,
        uint32_t b0, uint32_t b1) {
    asm volatile("mma.sync.aligned.m16n8k16.row.col.f32.bf16.bf16.f32 "
                 "{%0,%1,%2,%3}, {%4,%5,%6,%7}, {%8,%9}, {%0,%1,%2,%3};"
                 : "+f"(c[0]), "+f"(c[1]), "+f"(c[2]), "+f"(c[3])
                 : "r"(a0), "r"(a1), "r"(a2), "r"(a3), "r"(b0), "r"(b1));
}

// ===================== scratch =============================================
__device__ __align__(16) __nv_bfloat16 d_xtA[3 * NN_PAD * DIM];  // bf16 A rows
__device__ __align__(16) __nv_bfloat16 d_relb[NKEY_PAD * DIM];   // related bf16
__device__ __align__(16) __nv_bfloat16 d_WT[5][DIM * DIM];       // W^T row-major [n][k]
__device__ __align__(16) __half d_xt_h[3 * NN * DIM];
__device__ __align__(16) __half d_me_h[3 * EE * DIM];
__device__ float d_Kb  [NKEY * DIM];
__device__ float d_Vb  [NKEY * DIM];
__device__ float d_qb  [CC * DIM];
__device__ float d_lsum[NHEAD * CC];
__device__ float d_headout[CC * DIM];
__device__ float d_att [CC * DIM];
__device__ float d_u   [DIM];
__device__ float d_urepr[DIM];

__device__ int d_ecnt[3 * EE];
__device__ int d_eoff[3 * (EE + 1)];
__device__ int d_ecur[3 * EE];
__device__ int d_ncnt[3 * NN];
__device__ int d_noff[3 * (NN + 1)];
__device__ int d_ncur[3 * NN];
__device__ int d_csrE[3 * NNZV];
__device__ int d_csrN[3 * NNZV];

// tags
#define TAG_Q   0
#define TAG_HO  1
#define TAG_ATT 2
__device__ __forceinline__ float* tag_f32(int t) {
    switch (t) {
        case TAG_Q:   return d_qb;
        case TAG_HO:  return d_headout;
        case TAG_ATT: return d_att;
    }
    return nullptr;
}
// GEMM A tags: 0..2 xtA mods, 3 relb ; C tags: 0..2 xt_h mods, 3 K, 4 V
__device__ __forceinline__ const __nv_bfloat16* atag_ptr(int t) {
    if (t < 3) return d_xtA + (size_t)t * NN_PAD * DIM;
    return d_relb;
}
__device__ __forceinline__ void* ctag_ptr(int t) {
    switch (t) {
        case 0: return (void*)d_xt_h;
        case 1: return (void*)(d_xt_h + (size_t)NN * DIM);
        case 2: return (void*)(d_xt_h + (size_t)2 * NN * DIM);
        case 3: return (void*)d_Kb;
        case 4: return (void*)d_Vb;
    }
    return nullptr;
}

// ===================== init =================================================
__global__ void zero_kernel() {
    int i = blockIdx.x * blockDim.x + threadIdx.x;
    if (i < 3 * EE)       d_ecnt[i] = 0;
    if (i < 3 * NN)       d_ncnt[i] = 0;
    if (i < CC * DIM)     d_headout[i] = 0.f;
    if (i < NHEAD * CC)   d_lsum[i] = 0.f;
    if (i < (NKEY_PAD - NKEY) * DIM / 2)
        ((unsigned*)d_relb)[(size_t)NKEY * DIM / 2 + i] = 0u;
}

// ===================== weight pre-convert: W^T row-major bf16 ===============
__global__ void convW_kernel(const float* __restrict__ w0, const float* __restrict__ w1,
                             const float* __restrict__ w2, const float* __restrict__ w3,
                             const float* __restrict__ w4) {
    const float* W = (blockIdx.x == 0) ? w0 : (blockIdx.x == 1) ? w1 :
                     (blockIdx.x == 2) ? w2 : (blockIdx.x == 3) ? w3 : w4;
    __nv_bfloat16* out = d_WT[blockIdx.x];
    int n = threadIdx.x;                       // 128 threads; WT[n][k] = W[k][n]
    for (int k = 0; k < DIM; k++)
        out[(size_t)n * DIM + k] = __float2bfloat16(W[(size_t)k * DIM + n]);
}

// ===================== A pre-convert: fp32 -> bf16 row-major (padded) =======
__global__ void convA_kernel(const float* __restrict__ a0, const float* __restrict__ a1,
                             const float* __restrict__ a2) {
    int gid = blockIdx.x * blockDim.x + threadIdx.x;   // one per 8 elements
    if (gid >= 3 * NN_PAD * 16) return;
    int row = gid >> 4, cg = gid & 15;
    int mod = row / NN_PAD, r = row - mod * NN_PAD;
    __nv_bfloat162 h[4];
    if (r < NN) {
        const float* src = ((mod == 0) ? a0 : (mod == 1) ? a1 : a2) + (size_t)r * DIM + cg * 8;
        float4 v0 = *(const float4*)src;
        float4 v1 = *(const float4*)(src + 4);
        h[0] = __floats2bfloat162_rn(v0.x, v0.y);
        h[1] = __floats2bfloat162_rn(v0.z, v0.w);
        h[2] = __floats2bfloat162_rn(v1.x, v1.y);
        h[3] = __floats2bfloat162_rn(v1.z, v1.w);
    } else {
        h[0] = h[1] = h[2] = h[3] = __floats2bfloat162_rn(0.f, 0.f);
    }
    *(uint4*)((char*)d_xtA + (size_t)gid * 16) = *(uint4*)h;
}

// ===================== bf16 mma.sync GEMM: C[M,128] = A@W (+bias) ===========
// 256 thr = 8 warps; CTA tile 128x128, K=128. Warp = 16 rows.
// A fragments from gmem (mma register mapping); B = WT tile in smem,
// stride 136 halves (272B) -> conflict-free ldmatrix.
#define WS_STRIDE 136
__global__ __launch_bounds__(256, 2)
void mmagemm(int Atag, int Widx, const float* __restrict__ bias,
             int Ctag, int M, int half_out) {
    __shared__ __align__(16) __nv_bfloat16 Ws[128 * WS_STRIDE];
    __shared__ float bias_s[128];
    int tid = threadIdx.x, wid = tid >> 5, lane = tid & 31;
    const __nv_bfloat16* A = atag_ptr(Atag);
    void* Cout = ctag_ptr(Ctag);
    if (tid < 128) bias_s[tid] = (bias != nullptr) ? bias[tid] : 0.f;
    {   // WT tile (row n = 128 bf16 = 16 uint4) -> smem
        const uint4* src = (const uint4*)d_WT[Widx];
        for (int c = tid; c < 2048; c += 256) {
            int n = c >> 4, kq = c & 15;
            *(uint4*)&Ws[n * WS_STRIDE + kq * 8] = src[c];
        }
    }
    __syncthreads();

    int g = lane >> 2, t2 = (lane & 3) * 2;
    int m0 = blockIdx.x * 128 + wid * 16;
    const __nv_bfloat16* Ag0 = A + (size_t)(m0 + g) * DIM + t2;
    const __nv_bfloat16* Ag8 = Ag0 + 8 * DIM;
    int nofs = (lane & 7) + ((lane >> 4) << 3);
    int kofs = lane & 8;
    uint32_t wbase = smem_u32(Ws);

    float acc[16][4];
#pragma unroll
    for (int i = 0; i < 16; i++)
#pragma unroll
        for (int j = 0; j < 4; j++) acc[i][j] = 0.f;

#pragma unroll
    for (int kc = 0; kc < 8; kc++) {
        int k0 = kc * 16;
        uint32_t a0 = *(const uint32_t*)(Ag0 + k0);
        uint32_t a1 = *(const uint32_t*)(Ag8 + k0);
        uint32_t a2 = *(const uint32_t*)(Ag0 + k0 + 8);
        uint32_t a3 = *(const uint32_t*)(Ag8 + k0 + 8);
#pragma unroll
        for (int nb = 0; nb < 8; nb++) {
            uint32_t b0, b1, b2, b3;
            uint32_t ad = wbase +
                (uint32_t)(((nb * 16 + nofs) * WS_STRIDE + k0 + kofs) * 2);
            ldsm4(b0, b1, b2, b3, ad);
            mma16816(acc[nb * 2],     a0, a1, a2, a3, b0, b1);
            mma16816(acc[nb * 2 + 1], a0, a1, a2, a3, b2, b3);
        }
    }

    int row0 = m0 + g, row1 = row0 + 8;
#pragma unroll
    for (int nc = 0; nc < 16; nc++) {
        int col = nc * 8 + t2;
        float f0 = acc[nc][0] + bias_s[col];
        float f1 = acc[nc][1] + bias_s[col + 1];
        float f2 = acc[nc][2] + bias_s[col];
        float f3 = acc[nc][3] + bias_s[col + 1];
        if (half_out) {
            if (row0 < M)
                *(__half2*)((__half*)Cout + (size_t)row0 * DIM + col) = __floats2half2_rn(f0, f1);
            if (row1 < M)
                *(__half2*)((__half*)Cout + (size_t)row1 * DIM + col) = __floats2half2_rn(f2, f3);
        } else {
            if (row0 < M)
                *(float2*)((float*)Cout + (size_t)row0 * DIM + col) = make_float2(f0, f1);
            if (row1 < M)
                *(float2*)((float*)Cout + (size_t)row1 * DIM + col) = make_float2(f2, f3);
        }
    }
}

// ===================== CSR build ============================================
__global__ void count_all(const int* __restrict__ n0, const int* __restrict__ e0,
                          const int* __restrict__ n1, const int* __restrict__ e1,
                          const int* __restrict__ n2, const int* __restrict__ e2) {
    int mod = blockIdx.y;
    const int* nodes = (mod == 0) ? n0 : (mod == 1) ? n1 : n2;
    const int* edges = (mod == 0) ? e0 : (mod == 1) ? e1 : e2;
    int i = blockIdx.x * blockDim.x + threadIdx.x;
    if (i >= NNZV) return;
    atomicAdd(&d_ecnt[mod * EE + edges[i]], 1);
    atomicAdd(&d_ncnt[mod * NN + nodes[i]], 1);
}

__device__ __forceinline__ int wscan_incl(int v, int lane) {
#pragma unroll
    for (int o = 1; o < 32; o <<= 1) {
        int t = __shfl_up_sync(0xffffffffu, v, o);
        if (lane >= o) v += t;
    }
    return v;
}

__global__ void scan_kernel() {
    __shared__ int wsum[32];
    __shared__ int srun, stot;
    int b = blockIdx.x;
    int mod = b % 3;
    bool isE = (b < 3);
    int len = isE ? EE : NN;
    const int* cnt = isE ? (d_ecnt + mod * EE) : (d_ncnt + mod * NN);
    int* off = isE ? (d_eoff + mod * (EE + 1)) : (d_noff + mod * (NN + 1));
    int* cur = isE ? (d_ecur + mod * EE) : (d_ncur + mod * NN);
    int tid = threadIdx.x, warp = tid >> 5, lane = tid & 31;
    if (tid == 0) srun = 0;
    __syncthreads();
    for (int base = 0; base < len; base += 1024) {
        int v = (base + tid < len) ? cnt[base + tid] : 0;
        int incl = wscan_incl(v, lane);
        if (lane == 31) wsum[warp] = incl;
        __syncthreads();
        if (warp == 0) {
            int s = wsum[lane];
            int wincl = wscan_incl(s, lane);
            wsum[lane] = wincl - s;
            if (lane == 31) stot = wincl;
        }
        __syncthreads();
        int run = srun;
        int ex = run + wsum[warp] + incl - v;
        if (base + tid < len) { off[base + tid] = ex; cur[base + tid] = ex; }
        __syncthreads();
        if (tid == 0) srun = run + stot;
        __syncthreads();
    }
    if (tid == 0) off[len] = srun;
}

__global__ void scatter_all(const int* __restrict__ n0, const int* __restrict__ e0,
                            const int* __restrict__ n1, const int* __restrict__ e1,
                            const int* __restrict__ n2, const int* __restrict__ e2) {
    int mod = blockIdx.y;
    const int* nodes = (mod == 0) ? n0 : (mod == 1) ? n1 : n2;
    const int* edges = (mod == 0) ? e0 : (mod == 1) ? e1 : e2;
    int i = blockIdx.x * blockDim.x + threadIdx.x;
    if (i >= NNZV) return;
    int e = edges[i], n = nodes[i];
    int pe = atomicAdd(&d_ecur[mod * EE + e], 1);
    d_csrE[mod * NNZV + pe] = n;
    int pn = atomicAdd(&d_ncur[mod * NN + n], 1);
    d_csrN[mod * NNZV + pn] = e;
}

// ===================== small SIMT GEMM (Q / Wo) ==============================
__global__ __launch_bounds__(256, 2)
void gemm_tile(const float* __restrict__ Aext, int Atag,
               const float* __restrict__ W,
               const float* __restrict__ bias, int Ctag, int M) {
    const float* A = (Aext != nullptr) ? Aext : tag_f32(Atag);
    float* C = tag_f32(Ctag);
    __shared__ float4 As4[8 * 65];
    __shared__ float Ws[32 * 132];
    int tid = threadIdx.x;
    int warp = tid >> 5, lane = tid & 31;
    int row0 = blockIdx.x * 64;
    float4 acc[8];
#pragma unroll
    for (int r = 0; r < 8; r++) acc[r] = make_float4(0.f, 0.f, 0.f, 0.f);
    for (int kt = 0; kt < 4; kt++) {
#pragma unroll
        for (int i = 0; i < 2; i++) {
            int idx = tid + i * 256;
            int r = idx >> 3, cq = idx & 7;
            float4 v = make_float4(0.f, 0.f, 0.f, 0.f);
            if (row0 + r < M) v = *(const float4*)&A[(size_t)(row0 + r) * 128 + kt * 32 + cq * 4];
            As4[cq * 65 + r] = v;
        }
#pragma unroll
        for (int i = 0; i < 4; i++) {
            int idx = tid + i * 256;
            int k = idx >> 5, cq = idx & 31;
            *(float4*)&Ws[k * 132 + cq * 4] = *(const float4*)&W[(size_t)(kt * 32 + k) * 128 + cq * 4];
        }
        __syncthreads();
#pragma unroll
        for (int kq = 0; kq < 8; kq++) {
            float4 a[8];
#pragma unroll
            for (int r = 0; r < 8; r++) a[r] = As4[kq * 65 + warp * 8 + r];
#pragma unroll
            for (int j = 0; j < 4; j++) {
                int kk = kq * 4 + j;
                float4 w = *(const float4*)&Ws[kk * 132 + lane * 4];
#pragma unroll
                for (int r = 0; r < 8; r++) {
                    float av = (j == 0) ? a[r].x : (j == 1) ? a[r].y : (j == 2) ? a[r].z : a[r].w;
                    acc[r].x += av * w.x; acc[r].y += av * w.y;
                    acc[r].z += av * w.z; acc[r].w += av * w.w;
                }
            }
        }
        __syncthreads();
    }
    float4 bv = make_float4(0.f, 0.f, 0.f, 0.f);
    if (bias != nullptr) bv = *(const float4*)&bias[lane * 4];
#pragma unroll
    for (int r = 0; r < 8; r++) {
        int row = row0 + warp * 8 + r;
        if (row >= M) continue;
        *(float4*)&C[(size_t)row * 128 + lane * 4] =
            make_float4(acc[r].x + bv.x, acc[r].y + bv.y, acc[r].z + bv.z, acc[r].w + bv.w);
    }
}

// ===================== hypergraph gathers ===================================
__global__ void edge_mean_kernel() {
    int gw = (blockIdx.x * blockDim.x + threadIdx.x) >> 5;
    int lane = threadIdx.x & 31;
    if (gw >= 3 * EE) return;
    int mod = gw / EE, e = gw - mod * EE;
    const int* __restrict__ base = d_csrE + mod * NNZV;
    int s0 = d_eoff[mod * (EE + 1) + e];
    int s1 = d_eoff[mod * (EE + 1) + e + 1];
    const uint2* __restrict__ xtm = (const uint2*)(d_xt_h + (size_t)mod * NN * DIM);
    float a0 = 0.f, a1 = 0.f, a2 = 0.f, a3 = 0.f;
    int j = s0;
    for (; j + 8 <= s1; j += 8) {
        int n[8];
#pragma unroll
        for (int u = 0; u < 8; u++) n[u] = base[j + u];
#pragma unroll
        for (int u = 0; u < 8; u++) {
            uint2 p = xtm[(size_t)n[u] * 32 + lane];
            float2 f0 = __half22float2(*(__half2*)&p.x);
            float2 f1 = __half22float2(*(__half2*)&p.y);
            a0 += f0.x; a1 += f0.y; a2 += f1.x; a3 += f1.y;
        }
    }
    for (; j < s1; j++) {
        uint2 p = xtm[(size_t)base[j] * 32 + lane];
        float2 f0 = __half22float2(*(__half2*)&p.x);
        float2 f1 = __half22float2(*(__half2*)&p.y);
        a0 += f0.x; a1 += f0.y; a2 += f1.x; a3 += f1.y;
    }
    int deg = s1 - s0; if (deg < 1) deg = 1;
    float inv = 1.f / (float)deg;
    uint2 o;
    *(__half2*)&o.x = __floats2half2_rn(a0 * inv, a1 * inv);
    *(__half2*)&o.y = __floats2half2_rn(a2 * inv, a3 * inv);
    ((uint2*)d_me_h)[((size_t)mod * EE + e) * 32 + lane] = o;
}

__global__ void node_out_kernel(const float* __restrict__ bias_item,
                                const float* __restrict__ bias_entity,
                                const float* __restrict__ bias_word) {
    int gw = (blockIdx.x * blockDim.x + threadIdx.x) >> 5;
    int lane = threadIdx.x & 31;
    if (gw >= 3 * NN) return;
    int mod = gw / NN, n = gw - mod * NN;
    const int* __restrict__ base = d_csrN + mod * NNZV;
    int s0 = d_noff[mod * (NN + 1) + n];
    int s1 = d_noff[mod * (NN + 1) + n + 1];
    const uint2* __restrict__ mem = (const uint2*)(d_me_h + (size_t)mod * EE * DIM);
    float a0 = 0.f, a1 = 0.f, a2 = 0.f, a3 = 0.f;
    int j = s0;
    for (; j + 8 <= s1; j += 8) {
        int e8[8];
#pragma unroll
        for (int u = 0; u < 8; u++) e8[u] = base[j + u];
#pragma unroll
        for (int u = 0; u < 8; u++) {
            uint2 p = mem[(size_t)e8[u] * 32 + lane];
            float2 f0 = __half22float2(*(__half2*)&p.x);
            float2 f1 = __half22float2(*(__half2*)&p.y);
            a0 += f0.x; a1 += f0.y; a2 += f1.x; a3 += f1.y;
        }
    }
    for (; j < s1; j++) {
        uint2 p = mem[(size_t)base[j] * 32 + lane];
        float2 f0 = __half22float2(*(__half2*)&p.x);
        float2 f1 = __half22float2(*(__half2*)&p.y);
        a0 += f0.x; a1 += f0.y; a2 += f1.x; a3 += f1.y;
    }
    int deg = s1 - s0; if (deg < 1) deg = 1;
    float inv = 1.f / (float)deg;
    const float* bias = (mod == 0) ? bias_item : (mod == 1) ? bias_entity : bias_word;
    float4 bv = *(const float4*)&bias[lane * 4];
    __nv_bfloat162 b01 = __floats2bfloat162_rn(a0 * inv + bv.x, a1 * inv + bv.y);
    __nv_bfloat162 b23 = __floats2bfloat162_rn(a2 * inv + bv.z, a3 * inv + bv.w);
    uint2 o; o.x = *(uint32_t*)&b01; o.y = *(uint32_t*)&b23;
    ((uint2*)d_relb)[((size_t)mod * NN + n) * 32 + lane] = o;
}

// ===================== attention (single pass, no max) ======================
#define AT_TILES 235
#define WSTRIDE 258
__global__ void attn_kernel() {
    int bx = blockIdx.x;
    int h = bx / AT_TILES;
    int k0 = (bx % AT_TILES) * 256;
    int tid = threadIdx.x;
    int key = k0 + tid;
    __shared__ float qs[CC * DH];
    __shared__ __half wsm[CC * WSTRIDE];
    __shared__ float4 vsm[256 * 4];
    for (int i = tid; i < CC * DH; i += 256) {
        int q = i / DH, d = i % DH;
        qs[i] = d_qb[q * DIM + h * DH + d];
    }
    for (int i = tid; i < 256 * 4; i += 256) {
        int k = i >> 2, dg = i & 3;
        float4 v = make_float4(0, 0, 0, 0);
        if (k0 + k < NKEY) v = *(const float4*)&d_Vb[(size_t)(k0 + k) * DIM + h * DH + dg * 4];
        vsm[i] = v;
    }
    float4 kv0 = make_float4(0, 0, 0, 0), kv1 = kv0, kv2 = kv0, kv3 = kv0;
    bool valid = key < NKEY;
    if (valid) {
        const float* kr = d_Kb + (size_t)key * DIM + h * DH;
        kv0 = *(const float4*)(kr + 0);  kv1 = *(const float4*)(kr + 4);
        kv2 = *(const float4*)(kr + 8);  kv3 = *(const float4*)(kr + 12);
    }
    __syncthreads();
#pragma unroll 5
    for (int q = 0; q < CC; q++) {
        const float4* qp = (const float4*)&qs[q * DH];
        float4 q0 = qp[0], q1 = qp[1], q2 = qp[2], q3 = qp[3];
        float s = q0.x*kv0.x + q0.y*kv0.y + q0.z*kv0.z + q0.w*kv0.w
                + q1.x*kv1.x + q1.y*kv1.y + q1.z*kv1.z + q1.w*kv1.w
                + q2.x*kv2.x + q2.y*kv2.y + q2.z*kv2.z + q2.w*kv2.w
                + q3.x*kv3.x + q3.y*kv3.y + q3.z*kv3.z + q3.w*kv3.w;
        float w = valid ? __expf(s * 0.25f) : 0.f;   // scores tiny; no max needed
        wsm[q * WSTRIDE + tid] = __float2half_rn(w);
    }
    __syncthreads();
    if (tid < CC * 4) {
        int q = tid >> 2, dg = tid & 3;
        float4 acc = make_float4(0, 0, 0, 0);
        float lacc = 0.f;
        const __half* wr = wsm + q * WSTRIDE;
#pragma unroll 4
        for (int k = 0; k < 256; k++) {
            float w = __half2float(wr[k]);
            float4 v = vsm[k * 4 + dg];
            acc.x += w * v.x; acc.y += w * v.y; acc.z += w * v.z; acc.w += w * v.w;
            if (dg == 0) lacc += w;
        }
        float* dst = d_headout + q * DIM + h * DH + dg * 4;
        atomicAdd(dst + 0, acc.x); atomicAdd(dst + 1, acc.y);
        atomicAdd(dst + 2, acc.z); atomicAdd(dst + 3, acc.w);
        if (dg == 0) atomicAdd(&d_lsum[h * CC + q], lacc);
    }
}

__global__ void normalize_kernel() {
    int i = blockIdx.x * blockDim.x + threadIdx.x;
    if (i >= CC * DIM) return;
    int q = i >> 7, d = i & 127;
    int h = d >> 4;
    d_headout[i] *= (1.f / d_lsum[h * CC + q]);
}

// ===================== self attention =======================================
__global__ void selfattn_kernel(const float* __restrict__ Hext, int R, int which,
                                const float* __restrict__ A,
                                const float* __restrict__ Bv) {
    int tid = threadIdx.x;
    int warp = tid >> 5, lane = tid & 31;
    const float* Hm = (which == 0) ? d_att : Hext;
    float* out = (which == 0) ? d_u : d_urepr;
    __shared__ float es[64];
    __shared__ float ws[64];
    for (int r = warp; r < R; r += 32) {
        const float* hr = (which == 1 && r == R - 1) ? d_u : (Hm + (size_t)r * DIM);
        float4 acc = make_float4(0, 0, 0, 0);
        for (int k = 0; k < DIM; k++) {
            float hk = hr[k];
            float4 a = *(const float4*)&A[(size_t)k * DIM + lane * 4];
            acc.x += hk * a.x; acc.y += hk * a.y; acc.z += hk * a.z; acc.w += hk * a.w;
        }
        float4 b4 = *(const float4*)&Bv[lane * 4];
        float v = tanhf(acc.x) * b4.x + tanhf(acc.y) * b4.y
                + tanhf(acc.z) * b4.z + tanhf(acc.w) * b4.w;
#pragma unroll
        for (int o = 16; o; o >>= 1) v += __shfl_xor_sync(0xffffffffu, v, o);
        if (lane == 0) es[r] = v;
    }
    __syncthreads();
    if (tid == 0) {
        float m = -1e30f;
        for (int r = 0; r < R; r++) m = fmaxf(m, es[r]);
        float s = 0.f;
        for (int r = 0; r < R; r++) { float w = __expf(es[r] - m); ws[r] = w; s += w; }
        float inv = 1.f / s;
        for (int r = 0; r < R; r++) ws[r] *= inv;
    }
    __syncthreads();
    if (tid < DIM) {
        float o = 0.f;
        for (int r = 0; r < R; r++) {
            const float* hr = (which == 1 && r == R - 1) ? d_u : (Hm + (size_t)r * DIM);
            o += ws[r] * hr[tid];
        }
        out[tid] = o;
    }
}

// ===================== final scores =========================================
__global__ void recscore_kernel(const float* __restrict__ W,
                                const float* __restrict__ b,
                                float* __restrict__ out) {
    __shared__ float us[DIM];
    int tid = threadIdx.x;
    if (tid < DIM) us[tid] = d_urepr[tid];
    __syncthreads();
    int j = blockIdx.x * 256 + tid;
    if (j >= NENT) return;
    float a0 = 0.f, a1 = 0.f, a2 = 0.f, a3 = 0.f;
#pragma unroll
    for (int d = 0; d < DIM; d += 4) {
        a0 += us[d + 0] * W[(size_t)(d + 0) * NENT + j];
        a1 += us[d + 1] * W[(size_t)(d + 1) * NENT + j];
        a2 += us[d + 2] * W[(size_t)(d + 2) * NENT + j];
        a3 += us[d + 3] * W[(size_t)(d + 3) * NENT + j];
    }
    out[j] = (a0 + a1) + (a2 + a3) + b[j];
}

// ===================== launch ===============================================
extern "C" void kernel_launch(void* const* d_in, const int* in_sizes, int n_in,
                              void* d_out, int out_size) {
    const float* item_emb     = (const float*)d_in[0];
    const float* entity_emb   = (const float*)d_in[1];
    const float* word_emb     = (const float*)d_in[2];
    const float* context_ent  = (const float*)d_in[3];
    const float* theta_item   = (const float*)d_in[4];
    const float* bias_item    = (const float*)d_in[5];
    const float* theta_entity = (const float*)d_in[6];
    const float* bias_entity  = (const float*)d_in[7];
    const float* theta_word   = (const float*)d_in[8];
    const float* bias_word    = (const float*)d_in[9];
    const float* Wq = (const float*)d_in[10];  const float* bq = (const float*)d_in[11];
    const float* Wk = (const float*)d_in[12];  const float* bk = (const float*)d_in[13];
    const float* Wv = (const float*)d_in[14];  const float* bv = (const float*)d_in[15];
    const float* Wo = (const float*)d_in[16];  const float* bo = (const float*)d_in[17];
    const float* a_his = (const float*)d_in[18]; const float* b_his = (const float*)d_in[19];
    const float* a_kg  = (const float*)d_in[20]; const float* b_kg  = (const float*)d_in[21];
    const float* rec_W = (const float*)d_in[22]; const float* rec_b = (const float*)d_in[23];
    const int* item_nodes   = (const int*)d_in[24];
    const int* item_edges   = (const int*)d_in[25];
    const int* entity_nodes = (const int*)d_in[26];
    const int* entity_edges = (const int*)d_in[27];
    const int* word_nodes   = (const int*)d_in[28];
    const int* word_edges   = (const int*)d_in[29];
    float* out = (float*)d_out;

    zero_kernel<<<(3 * NN + 255) / 256, 256>>>();

    // weight + activation pre-conversion
    convW_kernel<<<5, 128>>>(theta_item, theta_entity, theta_word, Wk, Wv);
    convA_kernel<<<(3 * NN_PAD * 16 + 127) / 128, 128>>>(item_emb, entity_emb, word_emb);

    // xt = x @ theta (HMMA; fp16 output payload, no bias)
    mmagemm<<<NTILE_NN, 256>>>(0, 0, nullptr, 0, NN, 1);
    mmagemm<<<NTILE_NN, 256>>>(1, 1, nullptr, 1, NN, 1);
    mmagemm<<<NTILE_NN, 256>>>(2, 2, nullptr, 2, NN, 1);

    // CSR build
    dim3 cgrid((NNZV + 255) / 256, 3);
    count_all<<<cgrid, 256>>>(item_nodes, item_edges, entity_nodes, entity_edges,
                              word_nodes, word_edges);
    scan_kernel<<<6, 1024>>>();
    scatter_all<<<cgrid, 256>>>(item_nodes, item_edges, entity_nodes, entity_edges,
                                word_nodes, word_edges);

    // hypergraph aggregation (rel emitted as bf16 rows)
    edge_mean_kernel<<<(3 * EE + 7) / 8, 256>>>();
    node_out_kernel<<<(3 * NN + 7) / 8, 256>>>(bias_item, bias_entity, bias_word);

    // K/V projections (HMMA, fp32 out)
    mmagemm<<<NTILE_NKEY, 256>>>(3, 3, bk, 3, NKEY, 0);
    mmagemm<<<NTILE_NKEY, 256>>>(3, 4, bv, 4, NKEY, 0);

    // Q projection (small SIMT)
    gemm_tile<<<1, 256>>>(context_ent, -1, Wq, bq, TAG_Q, CC);

    // attention (single pass) + normalize + Wo
    attn_kernel<<<NHEAD * AT_TILES, 256>>>();
    normalize_kernel<<<(CC * DIM + 255) / 256, 256>>>();
    gemm_tile<<<1, 256>>>(nullptr, TAG_HO, Wo, bo, TAG_ATT, CC);

    // self attentions
    selfattn_kernel<<<1, 1024>>>(nullptr,     CC,     0, a_his, b_his);
    selfattn_kernel<<<1, 1024>>>(context_ent, CC + 1, 1, a_kg,  b_kg);

    // final scores
    recscore_kernel<<<(NENT + 255) / 256, 256>>>(rec_W, rec_b, out);
}

// round 8
// speedup vs baseline: 2.1620x; 1.0366x over previous
#include <cuda_runtime.h>
#include <cuda_fp16.h>
#include <cuda_bf16.h>
#include <math.h>
#include <stdint.h>
#include <stddef.h>

#define DIM   128
#define NN    20000
#define NNZV  500000
#define EE    5000
#define CC    50
#define NENT  50000
#define NKEY  60000
#define NHEAD 8
#define DH    16

#define NN_PAD   20096      // 314 * 64
#define NKEY_PAD 60032      // 938 * 64
#define NT64_NN   314
#define NT64_NKEY 938

// ===================== helpers ==============================================
__device__ __forceinline__ uint32_t smem_u32(const void* p) {
    uint32_t a;
    asm("{ .reg .u64 t; cvta.to.shared.u64 t, %1; cvt.u32.u64 %0, t; }"
        : "=r"(a) : "l"(p));
    return a;
}
__device__ __forceinline__ void ldsm4(uint32_t& r0, uint32_t& r1,
                                      uint32_t& r2, uint32_t& r3, uint32_t addr) {
    asm volatile("ldmatrix.sync.aligned.m8n8.x4.shared.b16 {%0,%1,%2,%3}, [%4];"
                 : "=r"(r0), "=r"(r1), "=r"(r2), "=r"(r3) : "r"(addr));
}
__device__ __forceinline__ void mma16816(float* c,
        uint32_t a0, uint32_t a1, uint32_t a2, uint32_t a3,
        uint32_t b0, uint32_t b1) {
    asm volatile("mma.sync.aligned.m16n8k16.row.col.f32.bf16.bf16.f32 "
                 "{%0,%1,%2,%3}, {%4,%5,%6,%7}, {%8,%9}, {%0,%1,%2,%3};"
                 : "+f"(c[0]), "+f"(c[1]), "+f"(c[2]), "+f"(c[3])
                 : "r"(a0), "r"(a1), "r"(a2), "r"(a3), "r"(b0), "r"(b1));
}

// ===================== scratch =============================================
__device__ __align__(16) __nv_bfloat16 d_xtA[3 * NN_PAD * DIM];  // bf16 A rows
__device__ __align__(16) __nv_bfloat16 d_relb[NKEY_PAD * DIM];   // related bf16
__device__ __align__(16) __nv_bfloat16 d_WT[5][DIM * DIM];       // W^T row-major [n][k]
__device__ __align__(16) __half d_xt_h[3 * NN * DIM];
__device__ __align__(16) __half d_me_h[3 * EE * DIM];
__device__ float d_Kb  [NKEY * DIM];
__device__ float d_Vb  [NKEY * DIM];
__device__ float d_qb  [CC * DIM];
__device__ float d_lsum[NHEAD * CC];
__device__ float d_headout[CC * DIM];
__device__ float d_att [CC * DIM];
__device__ float d_u   [DIM];
__device__ float d_urepr[DIM];

__device__ int d_ecnt[3 * EE];
__device__ int d_eoff[3 * (EE + 1)];
__device__ int d_ecur[3 * EE];
__device__ int d_ncnt[3 * NN];
__device__ int d_noff[3 * (NN + 1)];
__device__ int d_ncur[3 * NN];
__device__ int d_csrE[3 * NNZV];
__device__ int d_csrN[3 * NNZV];

// tags for small SIMT gemm
#define TAG_Q   0
#define TAG_HO  1
#define TAG_ATT 2
__device__ __forceinline__ float* tag_f32(int t) {
    switch (t) {
        case TAG_Q:   return d_qb;
        case TAG_HO:  return d_headout;
        case TAG_ATT: return d_att;
    }
    return nullptr;
}

// ===================== init =================================================
__global__ void zero_kernel() {
    int i = blockIdx.x * blockDim.x + threadIdx.x;
    if (i < 3 * EE)       d_ecnt[i] = 0;
    if (i < 3 * NN)       d_ncnt[i] = 0;
    if (i < CC * DIM)     d_headout[i] = 0.f;
    if (i < NHEAD * CC)   d_lsum[i] = 0.f;
    if (i < (NKEY_PAD - NKEY) * DIM / 2)
        ((unsigned*)d_relb)[(size_t)NKEY * DIM / 2 + i] = 0u;
}

// ===================== weight pre-convert: W^T row-major bf16 ===============
__global__ void convW_kernel(const float* __restrict__ w0, const float* __restrict__ w1,
                             const float* __restrict__ w2, const float* __restrict__ w3,
                             const float* __restrict__ w4) {
    const float* W = (blockIdx.x == 0) ? w0 : (blockIdx.x == 1) ? w1 :
                     (blockIdx.x == 2) ? w2 : (blockIdx.x == 3) ? w3 : w4;
    __nv_bfloat16* out = d_WT[blockIdx.x];
    int n = threadIdx.x;                       // 128 threads; WT[n][k] = W[k][n]
    for (int k = 0; k < DIM; k++)
        out[(size_t)n * DIM + k] = __float2bfloat16(W[(size_t)k * DIM + n]);
}

// ===================== A pre-convert: fp32 -> bf16 row-major (padded) =======
__global__ void convA_kernel(const float* __restrict__ a0, const float* __restrict__ a1,
                             const float* __restrict__ a2) {
    int gid = blockIdx.x * blockDim.x + threadIdx.x;   // one per 8 elements
    if (gid >= 3 * NN_PAD * 16) return;
    int row = gid >> 4, cg = gid & 15;
    int mod = row / NN_PAD, r = row - mod * NN_PAD;
    __nv_bfloat162 h[4];
    if (r < NN) {
        const float* src = ((mod == 0) ? a0 : (mod == 1) ? a1 : a2) + (size_t)r * DIM + cg * 8;
        float4 v0 = *(const float4*)src;
        float4 v1 = *(const float4*)(src + 4);
        h[0] = __floats2bfloat162_rn(v0.x, v0.y);
        h[1] = __floats2bfloat162_rn(v0.z, v0.w);
        h[2] = __floats2bfloat162_rn(v1.x, v1.y);
        h[3] = __floats2bfloat162_rn(v1.z, v1.w);
    } else {
        h[0] = h[1] = h[2] = h[3] = __floats2bfloat162_rn(0.f, 0.f);
    }
    *(uint4*)((char*)d_xtA + (size_t)gid * 16) = *(uint4*)h;
}

// ===================== bf16 mma.sync GEMM (64-row tiles, smem-staged A) =====
// 256 thr = 8 warps. CTA tile 64x128, K=128. Warp = 16 rows x 64 cols.
// Both A and B fragments via ldmatrix from stride-136 smem (conflict-free).
// mode 0: fused xt GEMMs, blockIdx.y = modality (half_out, no bias).
// mode 1: fused K/V GEMMs, blockIdx.y = {0:K,1:V} (fp32 out, bias bk/bv).
#define TS 136
__global__ __launch_bounds__(256, 3)
void mmagemm(int mode, const float* __restrict__ bk, const float* __restrict__ bv) {
    __shared__ __align__(16) __nv_bfloat16 As[64 * TS];
    __shared__ __align__(16) __nv_bfloat16 Ws[128 * TS];
    __shared__ float bias_s[128];
    int y = blockIdx.y;
    const __nv_bfloat16* A;
    const __nv_bfloat16* Wp;
    void* Cout;
    const float* bias;
    int M, half_out;
    if (mode == 0) {
        A = d_xtA + (size_t)y * NN_PAD * DIM;
        Wp = d_WT[y];
        Cout = (void*)(d_xt_h + (size_t)y * NN * DIM);
        bias = nullptr; M = NN; half_out = 1;
    } else {
        A = d_relb;
        Wp = d_WT[3 + y];
        Cout = y ? (void*)d_Vb : (void*)d_Kb;
        bias = y ? bv : bk; M = NKEY; half_out = 0;
    }
    int tid = threadIdx.x, wid = tid >> 5, lane = tid & 31;
    if (tid < 128) bias_s[tid] = (bias != nullptr) ? bias[tid] : 0.f;
    {   // A tile 64x128 (1024 uint4), coalesced
        const uint4* src = (const uint4*)(A + (size_t)blockIdx.x * 64 * DIM);
        for (int c = tid; c < 1024; c += 256) {
            int r = c >> 4, kq = c & 15;
            *(uint4*)&As[r * TS + kq * 8] = src[c];
        }
    }
    {   // B tile 128x128 (2048 uint4)
        const uint4* src = (const uint4*)Wp;
        for (int c = tid; c < 2048; c += 256) {
            int n = c >> 4, kq = c & 15;
            *(uint4*)&Ws[n * TS + kq * 8] = src[c];
        }
    }
    __syncthreads();

    int rg = wid >> 1, nh = wid & 1;           // row-group 0..3, N-half 0..1
    uint32_t abase = smem_u32(As), wbase = smem_u32(Ws);
    int nofs = (lane & 7) + ((lane >> 4) << 3);
    int kofs = lane & 8;
    int arow = rg * 16 + (lane & 15);
    int akof = (lane >> 4) << 3;

    float acc[8][4];
#pragma unroll
    for (int i = 0; i < 8; i++)
#pragma unroll
        for (int j = 0; j < 4; j++) acc[i][j] = 0.f;

#pragma unroll
    for (int kc = 0; kc < 8; kc++) {
        int k0 = kc * 16;
        uint32_t a0, a1, a2, a3;
        ldsm4(a0, a1, a2, a3, abase + (uint32_t)((arow * TS + k0 + akof) * 2));
#pragma unroll
        for (int nb = 0; nb < 4; nb++) {
            uint32_t b0, b1, b2, b3;
            uint32_t ad = wbase +
                (uint32_t)(((nh * 64 + nb * 16 + nofs) * TS + k0 + kofs) * 2);
            ldsm4(b0, b1, b2, b3, ad);
            mma16816(acc[nb * 2],     a0, a1, a2, a3, b0, b1);
            mma16816(acc[nb * 2 + 1], a0, a1, a2, a3, b2, b3);
        }
    }

    int g = lane >> 2, t2 = (lane & 3) * 2;
    int row0 = blockIdx.x * 64 + rg * 16 + g, row1 = row0 + 8;
#pragma unroll
    for (int nc = 0; nc < 8; nc++) {
        int col = nh * 64 + nc * 8 + t2;
        float f0 = acc[nc][0] + bias_s[col];
        float f1 = acc[nc][1] + bias_s[col + 1];
        float f2 = acc[nc][2] + bias_s[col];
        float f3 = acc[nc][3] + bias_s[col + 1];
        if (half_out) {
            if (row0 < M)
                *(__half2*)((__half*)Cout + (size_t)row0 * DIM + col) = __floats2half2_rn(f0, f1);
            if (row1 < M)
                *(__half2*)((__half*)Cout + (size_t)row1 * DIM + col) = __floats2half2_rn(f2, f3);
        } else {
            if (row0 < M)
                *(float2*)((float*)Cout + (size_t)row0 * DIM + col) = make_float2(f0, f1);
            if (row1 < M)
                *(float2*)((float*)Cout + (size_t)row1 * DIM + col) = make_float2(f2, f3);
        }
    }
}

// ===================== CSR build ============================================
__global__ void count_all(const int* __restrict__ n0, const int* __restrict__ e0,
                          const int* __restrict__ n1, const int* __restrict__ e1,
                          const int* __restrict__ n2, const int* __restrict__ e2) {
    int mod = blockIdx.y;
    const int* nodes = (mod == 0) ? n0 : (mod == 1) ? n1 : n2;
    const int* edges = (mod == 0) ? e0 : (mod == 1) ? e1 : e2;
    int i = blockIdx.x * blockDim.x + threadIdx.x;
    if (i >= NNZV) return;
    atomicAdd(&d_ecnt[mod * EE + edges[i]], 1);
    atomicAdd(&d_ncnt[mod * NN + nodes[i]], 1);
}

__device__ __forceinline__ int wscan_incl(int v, int lane) {
#pragma unroll
    for (int o = 1; o < 32; o <<= 1) {
        int t = __shfl_up_sync(0xffffffffu, v, o);
        if (lane >= o) v += t;
    }
    return v;
}

__global__ void scan_kernel() {
    __shared__ int wsum[32];
    __shared__ int srun, stot;
    int b = blockIdx.x;
    int mod = b % 3;
    bool isE = (b < 3);
    int len = isE ? EE : NN;
    const int* cnt = isE ? (d_ecnt + mod * EE) : (d_ncnt + mod * NN);
    int* off = isE ? (d_eoff + mod * (EE + 1)) : (d_noff + mod * (NN + 1));
    int* cur = isE ? (d_ecur + mod * EE) : (d_ncur + mod * NN);
    int tid = threadIdx.x, warp = tid >> 5, lane = tid & 31;
    if (tid == 0) srun = 0;
    __syncthreads();
    for (int base = 0; base < len; base += 1024) {
        int v = (base + tid < len) ? cnt[base + tid] : 0;
        int incl = wscan_incl(v, lane);
        if (lane == 31) wsum[warp] = incl;
        __syncthreads();
        if (warp == 0) {
            int s = wsum[lane];
            int wincl = wscan_incl(s, lane);
            wsum[lane] = wincl - s;
            if (lane == 31) stot = wincl;
        }
        __syncthreads();
        int run = srun;
        int ex = run + wsum[warp] + incl - v;
        if (base + tid < len) { off[base + tid] = ex; cur[base + tid] = ex; }
        __syncthreads();
        if (tid == 0) srun = run + stot;
        __syncthreads();
    }
    if (tid == 0) off[len] = srun;
}

__global__ void scatter_all(const int* __restrict__ n0, const int* __restrict__ e0,
                            const int* __restrict__ n1, const int* __restrict__ e1,
                            const int* __restrict__ n2, const int* __restrict__ e2) {
    int mod = blockIdx.y;
    const int* nodes = (mod == 0) ? n0 : (mod == 1) ? n1 : n2;
    const int* edges = (mod == 0) ? e0 : (mod == 1) ? e1 : e2;
    int i = blockIdx.x * blockDim.x + threadIdx.x;
    if (i >= NNZV) return;
    int e = edges[i], n = nodes[i];
    int pe = atomicAdd(&d_ecur[mod * EE + e], 1);
    d_csrE[mod * NNZV + pe] = n;
    int pn = atomicAdd(&d_ncur[mod * NN + n], 1);
    d_csrN[mod * NNZV + pn] = e;
}

// ===================== small SIMT GEMM (Q / Wo) ==============================
__global__ __launch_bounds__(256, 2)
void gemm_tile(const float* __restrict__ Aext, int Atag,
               const float* __restrict__ W,
               const float* __restrict__ bias, int Ctag, int M) {
    const float* A = (Aext != nullptr) ? Aext : tag_f32(Atag);
    float* C = tag_f32(Ctag);
    __shared__ float4 As4[8 * 65];
    __shared__ float Ws[32 * 132];
    int tid = threadIdx.x;
    int warp = tid >> 5, lane = tid & 31;
    int row0 = blockIdx.x * 64;
    float4 acc[8];
#pragma unroll
    for (int r = 0; r < 8; r++) acc[r] = make_float4(0.f, 0.f, 0.f, 0.f);
    for (int kt = 0; kt < 4; kt++) {
#pragma unroll
        for (int i = 0; i < 2; i++) {
            int idx = tid + i * 256;
            int r = idx >> 3, cq = idx & 7;
            float4 v = make_float4(0.f, 0.f, 0.f, 0.f);
            if (row0 + r < M) v = *(const float4*)&A[(size_t)(row0 + r) * 128 + kt * 32 + cq * 4];
            As4[cq * 65 + r] = v;
        }
#pragma unroll
        for (int i = 0; i < 4; i++) {
            int idx = tid + i * 256;
            int k = idx >> 5, cq = idx & 31;
            *(float4*)&Ws[k * 132 + cq * 4] = *(const float4*)&W[(size_t)(kt * 32 + k) * 128 + cq * 4];
        }
        __syncthreads();
#pragma unroll
        for (int kq = 0; kq < 8; kq++) {
            float4 a[8];
#pragma unroll
            for (int r = 0; r < 8; r++) a[r] = As4[kq * 65 + warp * 8 + r];
#pragma unroll
            for (int j = 0; j < 4; j++) {
                int kk = kq * 4 + j;
                float4 w = *(const float4*)&Ws[kk * 132 + lane * 4];
#pragma unroll
                for (int r = 0; r < 8; r++) {
                    float av = (j == 0) ? a[r].x : (j == 1) ? a[r].y : (j == 2) ? a[r].z : a[r].w;
                    acc[r].x += av * w.x; acc[r].y += av * w.y;
                    acc[r].z += av * w.z; acc[r].w += av * w.w;
                }
            }
        }
        __syncthreads();
    }
    float4 bv = make_float4(0.f, 0.f, 0.f, 0.f);
    if (bias != nullptr) bv = *(const float4*)&bias[lane * 4];
#pragma unroll
    for (int r = 0; r < 8; r++) {
        int row = row0 + warp * 8 + r;
        if (row >= M) continue;
        *(float4*)&C[(size_t)row * 128 + lane * 4] =
            make_float4(acc[r].x + bv.x, acc[r].y + bv.y, acc[r].z + bv.z, acc[r].w + bv.w);
    }
}

// ===================== hypergraph gathers ===================================
__global__ void edge_mean_kernel() {
    int gw = (blockIdx.x * blockDim.x + threadIdx.x) >> 5;
    int lane = threadIdx.x & 31;
    if (gw >= 3 * EE) return;
    int mod = gw / EE, e = gw - mod * EE;
    const int* __restrict__ base = d_csrE + mod * NNZV;
    int s0 = d_eoff[mod * (EE + 1) + e];
    int s1 = d_eoff[mod * (EE + 1) + e + 1];
    const uint2* __restrict__ xtm = (const uint2*)(d_xt_h + (size_t)mod * NN * DIM);
    float a0 = 0.f, a1 = 0.f, a2 = 0.f, a3 = 0.f;
    int j = s0;
    for (; j + 8 <= s1; j += 8) {
        int n[8];
#pragma unroll
        for (int u = 0; u < 8; u++) n[u] = base[j + u];
#pragma unroll
        for (int u = 0; u < 8; u++) {
            uint2 p = xtm[(size_t)n[u] * 32 + lane];
            float2 f0 = __half22float2(*(__half2*)&p.x);
            float2 f1 = __half22float2(*(__half2*)&p.y);
            a0 += f0.x; a1 += f0.y; a2 += f1.x; a3 += f1.y;
        }
    }
    for (; j < s1; j++) {
        uint2 p = xtm[(size_t)base[j] * 32 + lane];
        float2 f0 = __half22float2(*(__half2*)&p.x);
        float2 f1 = __half22float2(*(__half2*)&p.y);
        a0 += f0.x; a1 += f0.y; a2 += f1.x; a3 += f1.y;
    }
    int deg = s1 - s0; if (deg < 1) deg = 1;
    float inv = 1.f / (float)deg;
    uint2 o;
    *(__half2*)&o.x = __floats2half2_rn(a0 * inv, a1 * inv);
    *(__half2*)&o.y = __floats2half2_rn(a2 * inv, a3 * inv);
    ((uint2*)d_me_h)[((size_t)mod * EE + e) * 32 + lane] = o;
}

__global__ void node_out_kernel(const float* __restrict__ bias_item,
                                const float* __restrict__ bias_entity,
                                const float* __restrict__ bias_word) {
    int gw = (blockIdx.x * blockDim.x + threadIdx.x) >> 5;
    int lane = threadIdx.x & 31;
    if (gw >= 3 * NN) return;
    int mod = gw / NN, n = gw - mod * NN;
    const int* __restrict__ base = d_csrN + mod * NNZV;
    int s0 = d_noff[mod * (NN + 1) + n];
    int s1 = d_noff[mod * (NN + 1) + n + 1];
    const uint2* __restrict__ mem = (const uint2*)(d_me_h + (size_t)mod * EE * DIM);
    float a0 = 0.f, a1 = 0.f, a2 = 0.f, a3 = 0.f;
    int j = s0;
    for (; j + 8 <= s1; j += 8) {
        int e8[8];
#pragma unroll
        for (int u = 0; u < 8; u++) e8[u] = base[j + u];
#pragma unroll
        for (int u = 0; u < 8; u++) {
            uint2 p = mem[(size_t)e8[u] * 32 + lane];
            float2 f0 = __half22float2(*(__half2*)&p.x);
            float2 f1 = __half22float2(*(__half2*)&p.y);
            a0 += f0.x; a1 += f0.y; a2 += f1.x; a3 += f1.y;
        }
    }
    for (; j < s1; j++) {
        uint2 p = mem[(size_t)base[j] * 32 + lane];
        float2 f0 = __half22float2(*(__half2*)&p.x);
        float2 f1 = __half22float2(*(__half2*)&p.y);
        a0 += f0.x; a1 += f0.y; a2 += f1.x; a3 += f1.y;
    }
    int deg = s1 - s0; if (deg < 1) deg = 1;
    float inv = 1.f / (float)deg;
    const float* bias = (mod == 0) ? bias_item : (mod == 1) ? bias_entity : bias_word;
    float4 bv = *(const float4*)&bias[lane * 4];
    __nv_bfloat162 b01 = __floats2bfloat162_rn(a0 * inv + bv.x, a1 * inv + bv.y);
    __nv_bfloat162 b23 = __floats2bfloat162_rn(a2 * inv + bv.z, a3 * inv + bv.w);
    uint2 o; o.x = *(uint32_t*)&b01; o.y = *(uint32_t*)&b23;
    ((uint2*)d_relb)[((size_t)mod * NN + n) * 32 + lane] = o;
}

// ===================== attention (single pass, no max) ======================
#define AT_TILES 235
#define WSTRIDE 258
__global__ void attn_kernel() {
    int bx = blockIdx.x;
    int h = bx / AT_TILES;
    int k0 = (bx % AT_TILES) * 256;
    int tid = threadIdx.x;
    int key = k0 + tid;
    __shared__ float qs[CC * DH];
    __shared__ __half wsm[CC * WSTRIDE];
    __shared__ float4 vsm[256 * 4];
    for (int i = tid; i < CC * DH; i += 256) {
        int q = i / DH, d = i % DH;
        qs[i] = d_qb[q * DIM + h * DH + d];
    }
    for (int i = tid; i < 256 * 4; i += 256) {
        int k = i >> 2, dg = i & 3;
        float4 v = make_float4(0, 0, 0, 0);
        if (k0 + k < NKEY) v = *(const float4*)&d_Vb[(size_t)(k0 + k) * DIM + h * DH + dg * 4];
        vsm[i] = v;
    }
    float4 kv0 = make_float4(0, 0, 0, 0), kv1 = kv0, kv2 = kv0, kv3 = kv0;
    bool valid = key < NKEY;
    if (valid) {
        const float* kr = d_Kb + (size_t)key * DIM + h * DH;
        kv0 = *(const float4*)(kr + 0);  kv1 = *(const float4*)(kr + 4);
        kv2 = *(const float4*)(kr + 8);  kv3 = *(const float4*)(kr + 12);
    }
    __syncthreads();
#pragma unroll 5
    for (int q = 0; q < CC; q++) {
        const float4* qp = (const float4*)&qs[q * DH];
        float4 q0 = qp[0], q1 = qp[1], q2 = qp[2], q3 = qp[3];
        float s = q0.x*kv0.x + q0.y*kv0.y + q0.z*kv0.z + q0.w*kv0.w
                + q1.x*kv1.x + q1.y*kv1.y + q1.z*kv1.z + q1.w*kv1.w
                + q2.x*kv2.x + q2.y*kv2.y + q2.z*kv2.z + q2.w*kv2.w
                + q3.x*kv3.x + q3.y*kv3.y + q3.z*kv3.z + q3.w*kv3.w;
        float w = valid ? __expf(s * 0.25f) : 0.f;   // scores tiny; no max needed
        wsm[q * WSTRIDE + tid] = __float2half_rn(w);
    }
    __syncthreads();
    if (tid < CC * 4) {
        int q = tid >> 2, dg = tid & 3;
        float4 acc = make_float4(0, 0, 0, 0);
        float lacc = 0.f;
        const __half* wr = wsm + q * WSTRIDE;
#pragma unroll 4
        for (int k = 0; k < 256; k++) {
            float w = __half2float(wr[k]);
            float4 v = vsm[k * 4 + dg];
            acc.x += w * v.x; acc.y += w * v.y; acc.z += w * v.z; acc.w += w * v.w;
            if (dg == 0) lacc += w;
        }
        float* dst = d_headout + q * DIM + h * DH + dg * 4;
        atomicAdd(dst + 0, acc.x); atomicAdd(dst + 1, acc.y);
        atomicAdd(dst + 2, acc.z); atomicAdd(dst + 3, acc.w);
        if (dg == 0) atomicAdd(&d_lsum[h * CC + q], lacc);
    }
}

__global__ void normalize_kernel() {
    int i = blockIdx.x * blockDim.x + threadIdx.x;
    if (i >= CC * DIM) return;
    int q = i >> 7, d = i & 127;
    int h = d >> 4;
    d_headout[i] *= (1.f / d_lsum[h * CC + q]);
}

// ===================== self attention =======================================
__global__ void selfattn_kernel(const float* __restrict__ Hext, int R, int which,
                                const float* __restrict__ A,
                                const float* __restrict__ Bv) {
    int tid = threadIdx.x;
    int warp = tid >> 5, lane = tid & 31;
    const float* Hm = (which == 0) ? d_att : Hext;
    float* out = (which == 0) ? d_u : d_urepr;
    __shared__ float es[64];
    __shared__ float ws[64];
    for (int r = warp; r < R; r += 32) {
        const float* hr = (which == 1 && r == R - 1) ? d_u : (Hm + (size_t)r * DIM);
        float4 acc = make_float4(0, 0, 0, 0);
        for (int k = 0; k < DIM; k++) {
            float hk = hr[k];
            float4 a = *(const float4*)&A[(size_t)k * DIM + lane * 4];
            acc.x += hk * a.x; acc.y += hk * a.y; acc.z += hk * a.z; acc.w += hk * a.w;
        }
        float4 b4 = *(const float4*)&Bv[lane * 4];
        float v = tanhf(acc.x) * b4.x + tanhf(acc.y) * b4.y
                + tanhf(acc.z) * b4.z + tanhf(acc.w) * b4.w;
#pragma unroll
        for (int o = 16; o; o >>= 1) v += __shfl_xor_sync(0xffffffffu, v, o);
        if (lane == 0) es[r] = v;
    }
    __syncthreads();
    if (tid == 0) {
        float m = -1e30f;
        for (int r = 0; r < R; r++) m = fmaxf(m, es[r]);
        float s = 0.f;
        for (int r = 0; r < R; r++) { float w = __expf(es[r] - m); ws[r] = w; s += w; }
        float inv = 1.f / s;
        for (int r = 0; r < R; r++) ws[r] *= inv;
    }
    __syncthreads();
    if (tid < DIM) {
        float o = 0.f;
        for (int r = 0; r < R; r++) {
            const float* hr = (which == 1 && r == R - 1) ? d_u : (Hm + (size_t)r * DIM);
            o += ws[r] * hr[tid];
        }
        out[tid] = o;
    }
}

// ===================== final scores =========================================
__global__ void recscore_kernel(const float* __restrict__ W,
                                const float* __restrict__ b,
                                float* __restrict__ out) {
    __shared__ float us[DIM];
    int tid = threadIdx.x;
    if (tid < DIM) us[tid] = d_urepr[tid];
    __syncthreads();
    int j = blockIdx.x * 256 + tid;
    if (j >= NENT) return;
    float a0 = 0.f, a1 = 0.f, a2 = 0.f, a3 = 0.f;
#pragma unroll
    for (int d = 0; d < DIM; d += 4) {
        a0 += us[d + 0] * W[(size_t)(d + 0) * NENT + j];
        a1 += us[d + 1] * W[(size_t)(d + 1) * NENT + j];
        a2 += us[d + 2] * W[(size_t)(d + 2) * NENT + j];
        a3 += us[d + 3] * W[(size_t)(d + 3) * NENT + j];
    }
    out[j] = (a0 + a1) + (a2 + a3) + b[j];
}

// ===================== launch ===============================================
extern "C" void kernel_launch(void* const* d_in, const int* in_sizes, int n_in,
                              void* d_out, int out_size) {
    const float* item_emb     = (const float*)d_in[0];
    const float* entity_emb   = (const float*)d_in[1];
    const float* word_emb     = (const float*)d_in[2];
    const float* context_ent  = (const float*)d_in[3];
    const float* theta_item   = (const float*)d_in[4];
    const float* bias_item    = (const float*)d_in[5];
    const float* theta_entity = (const float*)d_in[6];
    const float* bias_entity  = (const float*)d_in[7];
    const float* theta_word   = (const float*)d_in[8];
    const float* bias_word    = (const float*)d_in[9];
    const float* Wq = (const float*)d_in[10];  const float* bq = (const float*)d_in[11];
    const float* Wk = (const float*)d_in[12];  const float* bk = (const float*)d_in[13];
    const float* Wv = (const float*)d_in[14];  const float* bv = (const float*)d_in[15];
    const float* Wo = (const float*)d_in[16];  const float* bo = (const float*)d_in[17];
    const float* a_his = (const float*)d_in[18]; const float* b_his = (const float*)d_in[19];
    const float* a_kg  = (const float*)d_in[20]; const float* b_kg  = (const float*)d_in[21];
    const float* rec_W = (const float*)d_in[22]; const float* rec_b = (const float*)d_in[23];
    const int* item_nodes   = (const int*)d_in[24];
    const int* item_edges   = (const int*)d_in[25];
    const int* entity_nodes = (const int*)d_in[26];
    const int* entity_edges = (const int*)d_in[27];
    const int* word_nodes   = (const int*)d_in[28];
    const int* word_edges   = (const int*)d_in[29];
    float* out = (float*)d_out;

    zero_kernel<<<(3 * NN + 255) / 256, 256>>>();

    // weight + activation pre-conversion
    convW_kernel<<<5, 128>>>(theta_item, theta_entity, theta_word, Wk, Wv);
    convA_kernel<<<(3 * NN_PAD * 16 + 127) / 128, 128>>>(item_emb, entity_emb, word_emb);

    // xt = x @ theta for all 3 modalities in ONE fused launch
    mmagemm<<<dim3(NT64_NN, 3), 256>>>(0, nullptr, nullptr);

    // CSR build
    dim3 cgrid((NNZV + 255) / 256, 3);
    count_all<<<cgrid, 256>>>(item_nodes, item_edges, entity_nodes, entity_edges,
                              word_nodes, word_edges);
    scan_kernel<<<6, 1024>>>();
    scatter_all<<<cgrid, 256>>>(item_nodes, item_edges, entity_nodes, entity_edges,
                                word_nodes, word_edges);

    // hypergraph aggregation (rel emitted as bf16 rows)
    edge_mean_kernel<<<(3 * EE + 7) / 8, 256>>>();
    node_out_kernel<<<(3 * NN + 7) / 8, 256>>>(bias_item, bias_entity, bias_word);

    // K and V projections in ONE fused launch
    mmagemm<<<dim3(NT64_NKEY, 2), 256>>>(1, bk, bv);

    // Q projection (small SIMT)
    gemm_tile<<<1, 256>>>(context_ent, -1, Wq, bq, TAG_Q, CC);

    // attention (single pass) + normalize + Wo
    attn_kernel<<<NHEAD * AT_TILES, 256>>>();
    normalize_kernel<<<(CC * DIM + 255) / 256, 256>>>();
    gemm_tile<<<1, 256>>>(nullptr, TAG_HO, Wo, bo, TAG_ATT, CC);

    // self attentions
    selfattn_kernel<<<1, 1024>>>(nullptr,     CC,     0, a_his, b_his);
    selfattn_kernel<<<1, 1024>>>(context_ent, CC + 1, 1, a_kg,  b_kg);

    // final scores
    recscore_kernel<<<(NENT + 255) / 256, 256>>>(rec_W, rec_b, out);
}

// round 9
// speedup vs baseline: 2.1703x; 1.0039x over previous
#include <cuda_runtime.h>
#include <cuda_fp16.h>
#include <cuda_bf16.h>
#include <math.h>
#include <stdint.h>
#include <stddef.h>

#define DIM   128
#define NN    20000
#define NNZV  500000
#define EE    5000
#define CC    50
#define NENT  50000
#define NKEY  60000
#define NHEAD 8
#define DH    16

#define NN_PAD   20096      // 314 * 64
#define NKEY_PAD 60032      // 938 * 64
#define NT64_NN   314
#define NT64_NKEY 938

#define FP8_SCALE 16.0f

// ===================== helpers ==============================================
__device__ __forceinline__ uint32_t smem_u32(const void* p) {
    uint32_t a;
    asm("{ .reg .u64 t; cvta.to.shared.u64 t, %1; cvt.u32.u64 %0, t; }"
        : "=r"(a) : "l"(p));
    return a;
}
__device__ __forceinline__ void ldsm4(uint32_t& r0, uint32_t& r1,
                                      uint32_t& r2, uint32_t& r3, uint32_t addr) {
    asm volatile("ldmatrix.sync.aligned.m8n8.x4.shared.b16 {%0,%1,%2,%3}, [%4];"
                 : "=r"(r0), "=r"(r1), "=r"(r2), "=r"(r3) : "r"(addr));
}
__device__ __forceinline__ void mma16816(float* c,
        uint32_t a0, uint32_t a1, uint32_t a2, uint32_t a3,
        uint32_t b0, uint32_t b1) {
    asm volatile("mma.sync.aligned.m16n8k16.row.col.f32.bf16.bf16.f32 "
                 "{%0,%1,%2,%3}, {%4,%5,%6,%7}, {%8,%9}, {%0,%1,%2,%3};"
                 : "+f"(c[0]), "+f"(c[1]), "+f"(c[2]), "+f"(c[3])
                 : "r"(a0), "r"(a1), "r"(a2), "r"(a3), "r"(b0), "r"(b1));
}
// fp8 e4m3 pack/unpack (hi = first arg, lo = second; decode lo->.x)
__device__ __forceinline__ uint16_t f32x2_to_e4m3x2(float hi, float lo) {
    uint16_t r;
    asm("cvt.rn.satfinite.e4m3x2.f32 %0, %1, %2;" : "=h"(r) : "f"(hi), "f"(lo));
    return r;
}
__device__ __forceinline__ float2 e4m3x2_to_f32x2(uint16_t v) {
    uint32_t h2;
    asm("cvt.rn.f16x2.e4m3x2 %0, %1;" : "=r"(h2) : "h"(v));
    return __half22float2(*(__half2*)&h2);
}

// ===================== scratch =============================================
__device__ __align__(16) __nv_bfloat16 d_xtA[3 * NN_PAD * DIM];  // bf16 A rows
__device__ __align__(16) __nv_bfloat16 d_relb[NKEY_PAD * DIM];   // related bf16
__device__ __align__(16) __nv_bfloat16 d_WT[5][DIM * DIM];       // W^T row-major [n][k]
__device__ __align__(16) uint8_t d_xt8[3 * NN * DIM];            // xt fp8 (x16 scale)
__device__ __align__(16) uint8_t d_me8[3 * EE * DIM];            // means fp8 (x16)
__device__ __align__(16) __nv_bfloat16 d_Kbh[NKEY * DIM];
__device__ __align__(16) __nv_bfloat16 d_Vbh[NKEY * DIM];
__device__ float d_qb  [CC * DIM];
__device__ float d_lsum[NHEAD * CC];
__device__ float d_headout[CC * DIM];
__device__ float d_att [CC * DIM];
__device__ float d_urepr[DIM];

__device__ int d_ecnt[3 * EE];
__device__ int d_eoff[3 * (EE + 1)];
__device__ int d_ecur[3 * EE];
__device__ int d_ncnt[3 * NN];
__device__ int d_noff[3 * (NN + 1)];
__device__ int d_ncur[3 * NN];
__device__ int d_csrE[3 * NNZV];
__device__ int d_csrN[3 * NNZV];

// tags for small SIMT gemm
#define TAG_Q   0
#define TAG_HO  1
#define TAG_ATT 2
__device__ __forceinline__ float* tag_f32(int t) {
    switch (t) {
        case TAG_Q:   return d_qb;
        case TAG_HO:  return d_headout;
        case TAG_ATT: return d_att;
    }
    return nullptr;
}

// ===================== init =================================================
__global__ void zero_kernel() {
    int i = blockIdx.x * blockDim.x + threadIdx.x;
    if (i < 3 * EE)       d_ecnt[i] = 0;
    if (i < 3 * NN)       d_ncnt[i] = 0;
    if (i < CC * DIM)     d_headout[i] = 0.f;
    if (i < NHEAD * CC)   d_lsum[i] = 0.f;
    if (i < (NKEY_PAD - NKEY) * DIM / 2)
        ((unsigned*)d_relb)[(size_t)NKEY * DIM / 2 + i] = 0u;
}

// ===================== weight pre-convert: W^T row-major bf16 ===============
__global__ void convW_kernel(const float* __restrict__ w0, const float* __restrict__ w1,
                             const float* __restrict__ w2, const float* __restrict__ w3,
                             const float* __restrict__ w4) {
    const float* W = (blockIdx.x == 0) ? w0 : (blockIdx.x == 1) ? w1 :
                     (blockIdx.x == 2) ? w2 : (blockIdx.x == 3) ? w3 : w4;
    __nv_bfloat16* out = d_WT[blockIdx.x];
    int n = threadIdx.x;                       // 128 threads; WT[n][k] = W[k][n]
    for (int k = 0; k < DIM; k++)
        out[(size_t)n * DIM + k] = __float2bfloat16(W[(size_t)k * DIM + n]);
}

// ===================== A pre-convert: fp32 -> bf16 row-major (padded) =======
__global__ void convA_kernel(const float* __restrict__ a0, const float* __restrict__ a1,
                             const float* __restrict__ a2) {
    int gid = blockIdx.x * blockDim.x + threadIdx.x;   // one per 8 elements
    if (gid >= 3 * NN_PAD * 16) return;
    int row = gid >> 4, cg = gid & 15;
    int mod = row / NN_PAD, r = row - mod * NN_PAD;
    __nv_bfloat162 h[4];
    if (r < NN) {
        const float* src = ((mod == 0) ? a0 : (mod == 1) ? a1 : a2) + (size_t)r * DIM + cg * 8;
        float4 v0 = *(const float4*)src;
        float4 v1 = *(const float4*)(src + 4);
        h[0] = __floats2bfloat162_rn(v0.x, v0.y);
        h[1] = __floats2bfloat162_rn(v0.z, v0.w);
        h[2] = __floats2bfloat162_rn(v1.x, v1.y);
        h[3] = __floats2bfloat162_rn(v1.z, v1.w);
    } else {
        h[0] = h[1] = h[2] = h[3] = __floats2bfloat162_rn(0.f, 0.f);
    }
    *(uint4*)((char*)d_xtA + (size_t)gid * 16) = *(uint4*)h;
}

// ===================== bf16 mma.sync GEMM (64-row tiles, smem-staged A) =====
// mode 0: fused xt GEMMs, blockIdx.y = modality -> fp8(e4m3, x16) out, no bias.
// mode 1: fused K/V GEMMs, blockIdx.y = {0:K,1:V} -> bf16 out, bias bk/bv.
#define TS 136
__global__ __launch_bounds__(256, 3)
void mmagemm(int mode, const float* __restrict__ bk, const float* __restrict__ bv) {
    __shared__ __align__(16) __nv_bfloat16 As[64 * TS];
    __shared__ __align__(16) __nv_bfloat16 Ws[128 * TS];
    __shared__ float bias_s[128];
    int y = blockIdx.y;
    const __nv_bfloat16* A;
    const __nv_bfloat16* Wp;
    void* Cout;
    const float* bias;
    int M;
    if (mode == 0) {
        A = d_xtA + (size_t)y * NN_PAD * DIM;
        Wp = d_WT[y];
        Cout = (void*)(d_xt8 + (size_t)y * NN * DIM);
        bias = nullptr; M = NN;
    } else {
        A = d_relb;
        Wp = d_WT[3 + y];
        Cout = y ? (void*)d_Vbh : (void*)d_Kbh;
        bias = y ? bv : bk; M = NKEY;
    }
    int tid = threadIdx.x, wid = tid >> 5, lane = tid & 31;
    if (tid < 128) bias_s[tid] = (bias != nullptr) ? bias[tid] : 0.f;
    {   // A tile 64x128 (1024 uint4), coalesced
        const uint4* src = (const uint4*)(A + (size_t)blockIdx.x * 64 * DIM);
        for (int c = tid; c < 1024; c += 256) {
            int r = c >> 4, kq = c & 15;
            *(uint4*)&As[r * TS + kq * 8] = src[c];
        }
    }
    {   // B tile 128x128 (2048 uint4)
        const uint4* src = (const uint4*)Wp;
        for (int c = tid; c < 2048; c += 256) {
            int n = c >> 4, kq = c & 15;
            *(uint4*)&Ws[n * TS + kq * 8] = src[c];
        }
    }
    __syncthreads();

    int rg = wid >> 1, nh = wid & 1;           // row-group 0..3, N-half 0..1
    uint32_t abase = smem_u32(As), wbase = smem_u32(Ws);
    int nofs = (lane & 7) + ((lane >> 4) << 3);
    int kofs = lane & 8;
    int arow = rg * 16 + (lane & 15);
    int akof = (lane >> 4) << 3;

    float acc[8][4];
#pragma unroll
    for (int i = 0; i < 8; i++)
#pragma unroll
        for (int j = 0; j < 4; j++) acc[i][j] = 0.f;

#pragma unroll
    for (int kc = 0; kc < 8; kc++) {
        int k0 = kc * 16;
        uint32_t a0, a1, a2, a3;
        ldsm4(a0, a1, a2, a3, abase + (uint32_t)((arow * TS + k0 + akof) * 2));
#pragma unroll
        for (int nb = 0; nb < 4; nb++) {
            uint32_t b0, b1, b2, b3;
            uint32_t ad = wbase +
                (uint32_t)(((nh * 64 + nb * 16 + nofs) * TS + k0 + kofs) * 2);
            ldsm4(b0, b1, b2, b3, ad);
            mma16816(acc[nb * 2],     a0, a1, a2, a3, b0, b1);
            mma16816(acc[nb * 2 + 1], a0, a1, a2, a3, b2, b3);
        }
    }

    int g = lane >> 2, t2 = (lane & 3) * 2;
    int row0 = blockIdx.x * 64 + rg * 16 + g, row1 = row0 + 8;
#pragma unroll
    for (int nc = 0; nc < 8; nc++) {
        int col = nh * 64 + nc * 8 + t2;
        float f0 = acc[nc][0] + bias_s[col];
        float f1 = acc[nc][1] + bias_s[col + 1];
        float f2 = acc[nc][2] + bias_s[col];
        float f3 = acc[nc][3] + bias_s[col + 1];
        if (mode == 0) {
            if (row0 < M)
                *(uint16_t*)((uint8_t*)Cout + (size_t)row0 * DIM + col) =
                    f32x2_to_e4m3x2(f1 * FP8_SCALE, f0 * FP8_SCALE);
            if (row1 < M)
                *(uint16_t*)((uint8_t*)Cout + (size_t)row1 * DIM + col) =
                    f32x2_to_e4m3x2(f3 * FP8_SCALE, f2 * FP8_SCALE);
        } else {
            if (row0 < M)
                *(__nv_bfloat162*)((__nv_bfloat16*)Cout + (size_t)row0 * DIM + col) =
                    __floats2bfloat162_rn(f0, f1);
            if (row1 < M)
                *(__nv_bfloat162*)((__nv_bfloat16*)Cout + (size_t)row1 * DIM + col) =
                    __floats2bfloat162_rn(f2, f3);
        }
    }
}

// ===================== CSR build ============================================
__global__ void count_all(const int* __restrict__ n0, const int* __restrict__ e0,
                          const int* __restrict__ n1, const int* __restrict__ e1,
                          const int* __restrict__ n2, const int* __restrict__ e2) {
    int mod = blockIdx.y;
    const int* nodes = (mod == 0) ? n0 : (mod == 1) ? n1 : n2;
    const int* edges = (mod == 0) ? e0 : (mod == 1) ? e1 : e2;
    int i = blockIdx.x * blockDim.x + threadIdx.x;
    if (i >= NNZV) return;
    atomicAdd(&d_ecnt[mod * EE + edges[i]], 1);
    atomicAdd(&d_ncnt[mod * NN + nodes[i]], 1);
}

__device__ __forceinline__ int wscan_incl(int v, int lane) {
#pragma unroll
    for (int o = 1; o < 32; o <<= 1) {
        int t = __shfl_up_sync(0xffffffffu, v, o);
        if (lane >= o) v += t;
    }
    return v;
}

__global__ void scan_kernel() {
    __shared__ int wsum[32];
    __shared__ int srun, stot;
    int b = blockIdx.x;
    int mod = b % 3;
    bool isE = (b < 3);
    int len = isE ? EE : NN;
    const int* cnt = isE ? (d_ecnt + mod * EE) : (d_ncnt + mod * NN);
    int* off = isE ? (d_eoff + mod * (EE + 1)) : (d_noff + mod * (NN + 1));
    int* cur = isE ? (d_ecur + mod * EE) : (d_ncur + mod * NN);
    int tid = threadIdx.x, warp = tid >> 5, lane = tid & 31;
    if (tid == 0) srun = 0;
    __syncthreads();
    for (int base = 0; base < len; base += 1024) {
        int v = (base + tid < len) ? cnt[base + tid] : 0;
        int incl = wscan_incl(v, lane);
        if (lane == 31) wsum[warp] = incl;
        __syncthreads();
        if (warp == 0) {
            int s = wsum[lane];
            int wincl = wscan_incl(s, lane);
            wsum[lane] = wincl - s;
            if (lane == 31) stot = wincl;
        }
        __syncthreads();
        int run = srun;
        int ex = run + wsum[warp] + incl - v;
        if (base + tid < len) { off[base + tid] = ex; cur[base + tid] = ex; }
        __syncthreads();
        if (tid == 0) srun = run + stot;
        __syncthreads();
    }
    if (tid == 0) off[len] = srun;
}

__global__ void scatter_all(const int* __restrict__ n0, const int* __restrict__ e0,
                            const int* __restrict__ n1, const int* __restrict__ e1,
                            const int* __restrict__ n2, const int* __restrict__ e2) {
    int mod = blockIdx.y;
    const int* nodes = (mod == 0) ? n0 : (mod == 1) ? n1 : n2;
    const int* edges = (mod == 0) ? e0 : (mod == 1) ? e1 : e2;
    int i = blockIdx.x * blockDim.x + threadIdx.x;
    if (i >= NNZV) return;
    int e = edges[i], n = nodes[i];
    int pe = atomicAdd(&d_ecur[mod * EE + e], 1);
    d_csrE[mod * NNZV + pe] = n;
    int pn = atomicAdd(&d_ncur[mod * NN + n], 1);
    d_csrN[mod * NNZV + pn] = e;
}

// ===================== small SIMT GEMM (Q / Wo) ==============================
// normA: divide A[row][d] by d_lsum[(d>>4)*CC + row] while loading (Wo path).
__global__ __launch_bounds__(256, 2)
void gemm_tile(const float* __restrict__ Aext, int Atag,
               const float* __restrict__ W,
               const float* __restrict__ bias, int Ctag, int M, int normA) {
    const float* A = (Aext != nullptr) ? Aext : tag_f32(Atag);
    float* C = tag_f32(Ctag);
    __shared__ float4 As4[8 * 65];
    __shared__ float Ws[32 * 132];
    int tid = threadIdx.x;
    int warp = tid >> 5, lane = tid & 31;
    int row0 = blockIdx.x * 64;
    float4 acc[8];
#pragma unroll
    for (int r = 0; r < 8; r++) acc[r] = make_float4(0.f, 0.f, 0.f, 0.f);
    for (int kt = 0; kt < 4; kt++) {
#pragma unroll
        for (int i = 0; i < 2; i++) {
            int idx = tid + i * 256;
            int r = idx >> 3, cq = idx & 7;
            float4 v = make_float4(0.f, 0.f, 0.f, 0.f);
            if (row0 + r < M) {
                v = *(const float4*)&A[(size_t)(row0 + r) * 128 + kt * 32 + cq * 4];
                if (normA) {
                    int dbase = kt * 32 + cq * 4;
                    float is = 1.f / d_lsum[(dbase >> 4) * CC + (row0 + r)];
                    v.x *= is; v.y *= is; v.z *= is; v.w *= is;
                }
            }
            As4[cq * 65 + r] = v;
        }
#pragma unroll
        for (int i = 0; i < 4; i++) {
            int idx = tid + i * 256;
            int k = idx >> 5, cq = idx & 31;
            *(float4*)&Ws[k * 132 + cq * 4] = *(const float4*)&W[(size_t)(kt * 32 + k) * 128 + cq * 4];
        }
        __syncthreads();
#pragma unroll
        for (int kq = 0; kq < 8; kq++) {
            float4 a[8];
#pragma unroll
            for (int r = 0; r < 8; r++) a[r] = As4[kq * 65 + warp * 8 + r];
#pragma unroll
            for (int j = 0; j < 4; j++) {
                int kk = kq * 4 + j;
                float4 w = *(const float4*)&Ws[kk * 132 + lane * 4];
#pragma unroll
                for (int r = 0; r < 8; r++) {
                    float av = (j == 0) ? a[r].x : (j == 1) ? a[r].y : (j == 2) ? a[r].z : a[r].w;
                    acc[r].x += av * w.x; acc[r].y += av * w.y;
                    acc[r].z += av * w.z; acc[r].w += av * w.w;
                }
            }
        }
        __syncthreads();
    }
    float4 bv = make_float4(0.f, 0.f, 0.f, 0.f);
    if (bias != nullptr) bv = *(const float4*)&bias[lane * 4];
#pragma unroll
    for (int r = 0; r < 8; r++) {
        int row = row0 + warp * 8 + r;
        if (row >= M) continue;
        *(float4*)&C[(size_t)row * 128 + lane * 4] =
            make_float4(acc[r].x + bv.x, acc[r].y + bv.y, acc[r].z + bv.z, acc[r].w + bv.w);
    }
}

// ===================== hypergraph gathers (fp8 payloads) ====================
__global__ void edge_mean_kernel() {
    int gw = (blockIdx.x * blockDim.x + threadIdx.x) >> 5;
    int lane = threadIdx.x & 31;
    if (gw >= 3 * EE) return;
    int mod = gw / EE, e = gw - mod * EE;
    const int* __restrict__ base = d_csrE + mod * NNZV;
    int s0 = d_eoff[mod * (EE + 1) + e];
    int s1 = d_eoff[mod * (EE + 1) + e + 1];
    const uint32_t* __restrict__ xtm = (const uint32_t*)(d_xt8 + (size_t)mod * NN * DIM);
    float a0 = 0.f, a1 = 0.f, a2 = 0.f, a3 = 0.f;
    int j = s0;
    for (; j + 8 <= s1; j += 8) {
        int n[8];
#pragma unroll
        for (int u = 0; u < 8; u++) n[u] = base[j + u];
#pragma unroll
        for (int u = 0; u < 8; u++) {
            uint32_t p = xtm[(size_t)n[u] * 32 + lane];
            float2 f0 = e4m3x2_to_f32x2((uint16_t)(p & 0xFFFF));
            float2 f1 = e4m3x2_to_f32x2((uint16_t)(p >> 16));
            a0 += f0.x; a1 += f0.y; a2 += f1.x; a3 += f1.y;
        }
    }
    for (; j < s1; j++) {
        uint32_t p = xtm[(size_t)base[j] * 32 + lane];
        float2 f0 = e4m3x2_to_f32x2((uint16_t)(p & 0xFFFF));
        float2 f1 = e4m3x2_to_f32x2((uint16_t)(p >> 16));
        a0 += f0.x; a1 += f0.y; a2 += f1.x; a3 += f1.y;
    }
    int deg = s1 - s0; if (deg < 1) deg = 1;
    float inv = 1.f / (float)deg;                 // keep x16 scale in me
    uint16_t w0 = f32x2_to_e4m3x2(a1 * inv, a0 * inv);
    uint16_t w1 = f32x2_to_e4m3x2(a3 * inv, a2 * inv);
    ((uint32_t*)d_me8)[((size_t)mod * EE + e) * 32 + lane] =
        (uint32_t)w0 | ((uint32_t)w1 << 16);
}

__global__ void node_out_kernel(const float* __restrict__ bias_item,
                                const float* __restrict__ bias_entity,
                                const float* __restrict__ bias_word) {
    int gw = (blockIdx.x * blockDim.x + threadIdx.x) >> 5;
    int lane = threadIdx.x & 31;
    if (gw >= 3 * NN) return;
    int mod = gw / NN, n = gw - mod * NN;
    const int* __restrict__ base = d_csrN + mod * NNZV;
    int s0 = d_noff[mod * (NN + 1) + n];
    int s1 = d_noff[mod * (NN + 1) + n + 1];
    const uint32_t* __restrict__ mem = (const uint32_t*)(d_me8 + (size_t)mod * EE * DIM);
    float a0 = 0.f, a1 = 0.f, a2 = 0.f, a3 = 0.f;
    int j = s0;
    for (; j + 8 <= s1; j += 8) {
        int e8[8];
#pragma unroll
        for (int u = 0; u < 8; u++) e8[u] = base[j + u];
#pragma unroll
        for (int u = 0; u < 8; u++) {
            uint32_t p = mem[(size_t)e8[u] * 32 + lane];
            float2 f0 = e4m3x2_to_f32x2((uint16_t)(p & 0xFFFF));
            float2 f1 = e4m3x2_to_f32x2((uint16_t)(p >> 16));
            a0 += f0.x; a1 += f0.y; a2 += f1.x; a3 += f1.y;
        }
    }
    for (; j < s1; j++) {
        uint32_t p = mem[(size_t)base[j] * 32 + lane];
        float2 f0 = e4m3x2_to_f32x2((uint16_t)(p & 0xFFFF));
        float2 f1 = e4m3x2_to_f32x2((uint16_t)(p >> 16));
        a0 += f0.x; a1 += f0.y; a2 += f1.x; a3 += f1.y;
    }
    int deg = s1 - s0; if (deg < 1) deg = 1;
    float inv = 1.f / ((float)deg * FP8_SCALE);   // undo fp8 scale here
    const float* bias = (mod == 0) ? bias_item : (mod == 1) ? bias_entity : bias_word;
    float4 bv = *(const float4*)&bias[lane * 4];
    __nv_bfloat162 b01 = __floats2bfloat162_rn(a0 * inv + bv.x, a1 * inv + bv.y);
    __nv_bfloat162 b23 = __floats2bfloat162_rn(a2 * inv + bv.z, a3 * inv + bv.w);
    uint2 o; o.x = *(uint32_t*)&b01; o.y = *(uint32_t*)&b23;
    ((uint2*)d_relb)[((size_t)mod * NN + n) * 32 + lane] = o;
}

// ===================== attention (single pass, no max; bf16 K/V) ============
#define AT_TILES 235
#define WSTRIDE 258
__global__ void attn_kernel() {
    int bx = blockIdx.x;
    int h = bx / AT_TILES;
    int k0 = (bx % AT_TILES) * 256;
    int tid = threadIdx.x;
    int key = k0 + tid;
    __shared__ float qs[CC * DH];
    __shared__ __half wsm[CC * WSTRIDE];
    __shared__ float4 vsm[256 * 4];
    for (int i = tid; i < CC * DH; i += 256) {
        int q = i / DH, d = i % DH;
        qs[i] = d_qb[q * DIM + h * DH + d];
    }
    for (int i = tid; i < 256 * 4; i += 256) {
        int k = i >> 2, dg = i & 3;
        float4 v = make_float4(0, 0, 0, 0);
        if (k0 + k < NKEY) {
            uint2 p = *(const uint2*)&d_Vbh[(size_t)(k0 + k) * DIM + h * DH + dg * 4];
            float2 f0 = __bfloat1622float2(*(__nv_bfloat162*)&p.x);
            float2 f1 = __bfloat1622float2(*(__nv_bfloat162*)&p.y);
            v = make_float4(f0.x, f0.y, f1.x, f1.y);
        }
        vsm[i] = v;
    }
    float kv[16];
    bool valid = key < NKEY;
    if (valid) {
        const __nv_bfloat16* kr = d_Kbh + (size_t)key * DIM + h * DH;
        uint4 kA = *(const uint4*)kr;
        uint4 kB = *(const uint4*)(kr + 8);
        const uint32_t* kw = (const uint32_t*)&kA;
#pragma unroll
        for (int j = 0; j < 4; j++) {
            float2 f = __bfloat1622float2(*(__nv_bfloat162*)&kw[j]);
            kv[2 * j] = f.x; kv[2 * j + 1] = f.y;
        }
        const uint32_t* kw2 = (const uint32_t*)&kB;
#pragma unroll
        for (int j = 0; j < 4; j++) {
            float2 f = __bfloat1622float2(*(__nv_bfloat162*)&kw2[j]);
            kv[8 + 2 * j] = f.x; kv[8 + 2 * j + 1] = f.y;
        }
    } else {
#pragma unroll
        for (int j = 0; j < 16; j++) kv[j] = 0.f;
    }
    __syncthreads();
#pragma unroll 5
    for (int q = 0; q < CC; q++) {
        const float* qp = &qs[q * DH];
        float s = 0.f;
#pragma unroll
        for (int j = 0; j < 16; j++) s += qp[j] * kv[j];
        float w = valid ? __expf(s * 0.25f) : 0.f;   // scores tiny; no max needed
        wsm[q * WSTRIDE + tid] = __float2half_rn(w);
    }
    __syncthreads();
    if (tid < CC * 4) {
        int q = tid >> 2, dg = tid & 3;
        float4 acc = make_float4(0, 0, 0, 0);
        float lacc = 0.f;
        const __half* wr = wsm + q * WSTRIDE;
#pragma unroll 4
        for (int k = 0; k < 256; k++) {
            float w = __half2float(wr[k]);
            float4 v = vsm[k * 4 + dg];
            acc.x += w * v.x; acc.y += w * v.y; acc.z += w * v.z; acc.w += w * v.w;
            if (dg == 0) lacc += w;
        }
        float* dst = d_headout + q * DIM + h * DH + dg * 4;
        atomicAdd(dst + 0, acc.x); atomicAdd(dst + 1, acc.y);
        atomicAdd(dst + 2, acc.z); atomicAdd(dst + 3, acc.w);
        if (dg == 0) atomicAdd(&d_lsum[h * CC + q], lacc);
    }
}

// ===================== fused double self-attention ==========================
// stage 1: u = selfattn(d_att [CC rows], a_his, b_his)
// stage 2: urepr = selfattn([ctx; u] [CC+1 rows], a_kg, b_kg)
__global__ void selfattn2_kernel(const float* __restrict__ ctx,
                                 const float* __restrict__ A1, const float* __restrict__ B1,
                                 const float* __restrict__ A2, const float* __restrict__ B2) {
    int tid = threadIdx.x;
    int warp = tid >> 5, lane = tid & 31;
    __shared__ float es[64];
    __shared__ float ws[64];
    __shared__ float u_s[DIM];
    // ---- stage 1 ----
    for (int r = warp; r < CC; r += 32) {
        const float* hr = d_att + (size_t)r * DIM;
        float4 acc = make_float4(0, 0, 0, 0);
        for (int k = 0; k < DIM; k++) {
            float hk = hr[k];
            float4 a = *(const float4*)&A1[(size_t)k * DIM + lane * 4];
            acc.x += hk * a.x; acc.y += hk * a.y; acc.z += hk * a.z; acc.w += hk * a.w;
        }
        float4 b4 = *(const float4*)&B1[lane * 4];
        float v = tanhf(acc.x) * b4.x + tanhf(acc.y) * b4.y
                + tanhf(acc.z) * b4.z + tanhf(acc.w) * b4.w;
#pragma unroll
        for (int o = 16; o; o >>= 1) v += __shfl_xor_sync(0xffffffffu, v, o);
        if (lane == 0) es[r] = v;
    }
    __syncthreads();
    if (tid == 0) {
        float m = -1e30f;
        for (int r = 0; r < CC; r++) m = fmaxf(m, es[r]);
        float s = 0.f;
        for (int r = 0; r < CC; r++) { float w = __expf(es[r] - m); ws[r] = w; s += w; }
        float inv = 1.f / s;
        for (int r = 0; r < CC; r++) ws[r] *= inv;
    }
    __syncthreads();
    if (tid < DIM) {
        float o = 0.f;
        for (int r = 0; r < CC; r++) o += ws[r] * d_att[(size_t)r * DIM + tid];
        u_s[tid] = o;
    }
    __syncthreads();
    // ---- stage 2 ----
    for (int r = warp; r < CC + 1; r += 32) {
        const float* hr = (r == CC) ? u_s : (ctx + (size_t)r * DIM);
        float4 acc = make_float4(0, 0, 0, 0);
        for (int k = 0; k < DIM; k++) {
            float hk = hr[k];
            float4 a = *(const float4*)&A2[(size_t)k * DIM + lane * 4];
            acc.x += hk * a.x; acc.y += hk * a.y; acc.z += hk * a.z; acc.w += hk * a.w;
        }
        float4 b4 = *(const float4*)&B2[lane * 4];
        float v = tanhf(acc.x) * b4.x + tanhf(acc.y) * b4.y
                + tanhf(acc.z) * b4.z + tanhf(acc.w) * b4.w;
#pragma unroll
        for (int o = 16; o; o >>= 1) v += __shfl_xor_sync(0xffffffffu, v, o);
        if (lane == 0) es[r] = v;
    }
    __syncthreads();
    if (tid == 0) {
        float m = -1e30f;
        for (int r = 0; r < CC + 1; r++) m = fmaxf(m, es[r]);
        float s = 0.f;
        for (int r = 0; r < CC + 1; r++) { float w = __expf(es[r] - m); ws[r] = w; s += w; }
        float inv = 1.f / s;
        for (int r = 0; r < CC + 1; r++) ws[r] *= inv;
    }
    __syncthreads();
    if (tid < DIM) {
        float o = 0.f;
        for (int r = 0; r < CC; r++) o += ws[r] * ctx[(size_t)r * DIM + tid];
        o += ws[CC] * u_s[tid];
        d_urepr[tid] = o;
    }
}

// ===================== final scores =========================================
__global__ void recscore_kernel(const float* __restrict__ W,
                                const float* __restrict__ b,
                                float* __restrict__ out) {
    __shared__ float us[DIM];
    int tid = threadIdx.x;
    if (tid < DIM) us[tid] = d_urepr[tid];
    __syncthreads();
    int j = blockIdx.x * 256 + tid;
    if (j >= NENT) return;
    float a0 = 0.f, a1 = 0.f, a2 = 0.f, a3 = 0.f;
#pragma unroll
    for (int d = 0; d < DIM; d += 4) {
        a0 += us[d + 0] * W[(size_t)(d + 0) * NENT + j];
        a1 += us[d + 1] * W[(size_t)(d + 1) * NENT + j];
        a2 += us[d + 2] * W[(size_t)(d + 2) * NENT + j];
        a3 += us[d + 3] * W[(size_t)(d + 3) * NENT + j];
    }
    out[j] = (a0 + a1) + (a2 + a3) + b[j];
}

// ===================== launch ===============================================
extern "C" void kernel_launch(void* const* d_in, const int* in_sizes, int n_in,
                              void* d_out, int out_size) {
    const float* item_emb     = (const float*)d_in[0];
    const float* entity_emb   = (const float*)d_in[1];
    const float* word_emb     = (const float*)d_in[2];
    const float* context_ent  = (const float*)d_in[3];
    const float* theta_item   = (const float*)d_in[4];
    const float* bias_item    = (const float*)d_in[5];
    const float* theta_entity = (const float*)d_in[6];
    const float* bias_entity  = (const float*)d_in[7];
    const float* theta_word   = (const float*)d_in[8];
    const float* bias_word    = (const float*)d_in[9];
    const float* Wq = (const float*)d_in[10];  const float* bq = (const float*)d_in[11];
    const float* Wk = (const float*)d_in[12];  const float* bk = (const float*)d_in[13];
    const float* Wv = (const float*)d_in[14];  const float* bv = (const float*)d_in[15];
    const float* Wo = (const float*)d_in[16];  const float* bo = (const float*)d_in[17];
    const float* a_his = (const float*)d_in[18]; const float* b_his = (const float*)d_in[19];
    const float* a_kg  = (const float*)d_in[20]; const float* b_kg  = (const float*)d_in[21];
    const float* rec_W = (const float*)d_in[22]; const float* rec_b = (const float*)d_in[23];
    const int* item_nodes   = (const int*)d_in[24];
    const int* item_edges   = (const int*)d_in[25];
    const int* entity_nodes = (const int*)d_in[26];
    const int* entity_edges = (const int*)d_in[27];
    const int* word_nodes   = (const int*)d_in[28];
    const int* word_edges   = (const int*)d_in[29];
    float* out = (float*)d_out;

    zero_kernel<<<(3 * NN + 255) / 256, 256>>>();

    // weight + activation pre-conversion
    convW_kernel<<<5, 128>>>(theta_item, theta_entity, theta_word, Wk, Wv);
    convA_kernel<<<(3 * NN_PAD * 16 + 127) / 128, 128>>>(item_emb, entity_emb, word_emb);

    // xt = x @ theta for all 3 modalities (fp8 payload out)
    mmagemm<<<dim3(NT64_NN, 3), 256>>>(0, nullptr, nullptr);

    // CSR build
    dim3 cgrid((NNZV + 255) / 256, 3);
    count_all<<<cgrid, 256>>>(item_nodes, item_edges, entity_nodes, entity_edges,
                              word_nodes, word_edges);
    scan_kernel<<<6, 1024>>>();
    scatter_all<<<cgrid, 256>>>(item_nodes, item_edges, entity_nodes, entity_edges,
                                word_nodes, word_edges);

    // hypergraph aggregation (fp8 payloads; rel emitted as bf16 rows)
    edge_mean_kernel<<<(3 * EE + 7) / 8, 256>>>();
    node_out_kernel<<<(3 * NN + 7) / 8, 256>>>(bias_item, bias_entity, bias_word);

    // K and V projections (bf16 out)
    mmagemm<<<dim3(NT64_NKEY, 2), 256>>>(1, bk, bv);

    // Q projection (small SIMT)
    gemm_tile<<<1, 256>>>(context_ent, -1, Wq, bq, TAG_Q, CC, 0);

    // attention (single pass) + Wo (with fused normalization)
    attn_kernel<<<NHEAD * AT_TILES, 256>>>();
    gemm_tile<<<1, 256>>>(nullptr, TAG_HO, Wo, bo, TAG_ATT, CC, 1);

    // fused double self-attention
    selfattn2_kernel<<<1, 1024>>>(context_ent, a_his, b_his, a_kg, b_kg);

    // final scores
    recscore_kernel<<<(NENT + 255) / 256, 256>>>(rec_W, rec_b, out);
}

// round 10
// speedup vs baseline: 2.2390x; 1.0317x over previous
#include <cuda_runtime.h>
#include <cuda_fp16.h>
#include <cuda_bf16.h>
#include <math.h>
#include <stdint.h>
#include <stddef.h>

#define DIM   128
#define NN    20000
#define NNZV  500000
#define EE    5000
#define CC    50
#define NENT  50000
#define NKEY  60000
#define NHEAD 8
#define DH    16

#define NN_PAD   20096      // 314 * 64
#define NKEY_PAD 60032      // 938 * 64
#define NT64_NN   314
#define NT64_NKEY 938

#define FP8_SCALE 16.0f

// ===================== helpers ==============================================
__device__ __forceinline__ uint32_t smem_u32(const void* p) {
    uint32_t a;
    asm("{ .reg .u64 t; cvta.to.shared.u64 t, %1; cvt.u32.u64 %0, t; }"
        : "=r"(a) : "l"(p));
    return a;
}
__device__ __forceinline__ void ldsm4(uint32_t& r0, uint32_t& r1,
                                      uint32_t& r2, uint32_t& r3, uint32_t addr) {
    asm volatile("ldmatrix.sync.aligned.m8n8.x4.shared.b16 {%0,%1,%2,%3}, [%4];"
                 : "=r"(r0), "=r"(r1), "=r"(r2), "=r"(r3) : "r"(addr));
}
__device__ __forceinline__ void mma16816(float* c,
        uint32_t a0, uint32_t a1, uint32_t a2, uint32_t a3,
        uint32_t b0, uint32_t b1) {
    asm volatile("mma.sync.aligned.m16n8k16.row.col.f32.bf16.bf16.f32 "
                 "{%0,%1,%2,%3}, {%4,%5,%6,%7}, {%8,%9}, {%0,%1,%2,%3};"
                 : "+f"(c[0]), "+f"(c[1]), "+f"(c[2]), "+f"(c[3])
                 : "r"(a0), "r"(a1), "r"(a2), "r"(a3), "r"(b0), "r"(b1));
}
// fp8 e4m3 pack/unpack (hi = first arg, lo = second; decode lo->.x)
__device__ __forceinline__ uint16_t f32x2_to_e4m3x2(float hi, float lo) {
    uint16_t r;
    asm("cvt.rn.satfinite.e4m3x2.f32 %0, %1, %2;" : "=h"(r) : "f"(hi), "f"(lo));
    return r;
}
__device__ __forceinline__ float2 e4m3x2_to_f32x2(uint16_t v) {
    uint32_t h2;
    asm("cvt.rn.f16x2.e4m3x2 %0, %1;" : "=r"(h2) : "h"(v));
    return __half22float2(*(__half2*)&h2);
}
// FMA-pipe exp for small |x| (degree-6 Taylor/Horner); avoids the MUFU.EX2
// throughput wall (74 ops/cyc chip-wide). Fallback for |x|>1 (rare).
__device__ __forceinline__ float fast_exp(float x) {
    if (fabsf(x) > 1.0f) return __expf(x);
    float p = 1.3888889e-3f;                 // 1/720
    p = fmaf(p, x, 8.3333333e-3f);           // 1/120
    p = fmaf(p, x, 4.1666667e-2f);           // 1/24
    p = fmaf(p, x, 1.6666667e-1f);           // 1/6
    p = fmaf(p, x, 0.5f);
    p = fmaf(p, x, 1.0f);
    p = fmaf(p, x, 1.0f);
    return p;
}

// ===================== scratch =============================================
__device__ __align__(16) __nv_bfloat16 d_xtA[3 * NN_PAD * DIM];  // bf16 A rows
__device__ __align__(16) __nv_bfloat16 d_relb[NKEY_PAD * DIM];   // related bf16
__device__ __align__(16) __nv_bfloat16 d_WT[5][DIM * DIM];       // W^T row-major [n][k]
__device__ __align__(16) uint8_t d_xt8[3 * NN * DIM];            // xt fp8 (x16 scale)
__device__ __align__(16) uint8_t d_me8[3 * EE * DIM];            // means fp8 (x16)
__device__ __align__(16) __nv_bfloat16 d_Kbh[NKEY * DIM];
__device__ __align__(16) __nv_bfloat16 d_Vbh[NKEY * DIM];
__device__ float d_qb  [CC * DIM];
__device__ float d_lsum[NHEAD * CC];
__device__ float d_headout[CC * DIM];
__device__ float d_att [CC * DIM];
__device__ float d_urepr[DIM];

__device__ int d_ecnt[3 * EE];
__device__ int d_eoff[3 * (EE + 1)];
__device__ int d_ecur[3 * EE];
__device__ int d_ncnt[3 * NN];
__device__ int d_noff[3 * (NN + 1)];
__device__ int d_ncur[3 * NN];
__device__ int d_csrE[3 * NNZV];
__device__ int d_csrN[3 * NNZV];

// tags for small SIMT gemm
#define TAG_Q   0
#define TAG_HO  1
#define TAG_ATT 2
__device__ __forceinline__ float* tag_f32(int t) {
    switch (t) {
        case TAG_Q:   return d_qb;
        case TAG_HO:  return d_headout;
        case TAG_ATT: return d_att;
    }
    return nullptr;
}

// ===================== init =================================================
__global__ void zero_kernel() {
    int i = blockIdx.x * blockDim.x + threadIdx.x;
    if (i < 3 * EE)       d_ecnt[i] = 0;
    if (i < 3 * NN)       d_ncnt[i] = 0;
    if (i < CC * DIM)     d_headout[i] = 0.f;
    if (i < NHEAD * CC)   d_lsum[i] = 0.f;
    if (i < (NKEY_PAD - NKEY) * DIM / 2)
        ((unsigned*)d_relb)[(size_t)NKEY * DIM / 2 + i] = 0u;
}

// ===================== weight pre-convert: W^T row-major bf16 ===============
__global__ void convW_kernel(const float* __restrict__ w0, const float* __restrict__ w1,
                             const float* __restrict__ w2, const float* __restrict__ w3,
                             const float* __restrict__ w4) {
    const float* W = (blockIdx.x == 0) ? w0 : (blockIdx.x == 1) ? w1 :
                     (blockIdx.x == 2) ? w2 : (blockIdx.x == 3) ? w3 : w4;
    __nv_bfloat16* out = d_WT[blockIdx.x];
    int n = threadIdx.x;                       // 128 threads; WT[n][k] = W[k][n]
    for (int k = 0; k < DIM; k++)
        out[(size_t)n * DIM + k] = __float2bfloat16(W[(size_t)k * DIM + n]);
}

// ===================== A pre-convert: fp32 -> bf16 row-major (padded) =======
__global__ void convA_kernel(const float* __restrict__ a0, const float* __restrict__ a1,
                             const float* __restrict__ a2) {
    int gid = blockIdx.x * blockDim.x + threadIdx.x;   // one per 8 elements
    if (gid >= 3 * NN_PAD * 16) return;
    int row = gid >> 4, cg = gid & 15;
    int mod = row / NN_PAD, r = row - mod * NN_PAD;
    __nv_bfloat162 h[4];
    if (r < NN) {
        const float* src = ((mod == 0) ? a0 : (mod == 1) ? a1 : a2) + (size_t)r * DIM + cg * 8;
        float4 v0 = *(const float4*)src;
        float4 v1 = *(const float4*)(src + 4);
        h[0] = __floats2bfloat162_rn(v0.x, v0.y);
        h[1] = __floats2bfloat162_rn(v0.z, v0.w);
        h[2] = __floats2bfloat162_rn(v1.x, v1.y);
        h[3] = __floats2bfloat162_rn(v1.z, v1.w);
    } else {
        h[0] = h[1] = h[2] = h[3] = __floats2bfloat162_rn(0.f, 0.f);
    }
    *(uint4*)((char*)d_xtA + (size_t)gid * 16) = *(uint4*)h;
}

// ===================== bf16 mma.sync GEMM (64-row tiles, smem-staged A) =====
// mode 0: fused xt GEMMs, blockIdx.y = modality -> fp8(e4m3, x16) out, no bias.
// mode 1: fused K/V GEMMs, blockIdx.y = {0:K,1:V} -> bf16 out, bias bk/bv.
#define TS 136
__global__ __launch_bounds__(256, 3)
void mmagemm(int mode, const float* __restrict__ bk, const float* __restrict__ bv) {
    __shared__ __align__(16) __nv_bfloat16 As[64 * TS];
    __shared__ __align__(16) __nv_bfloat16 Ws[128 * TS];
    __shared__ float bias_s[128];
    int y = blockIdx.y;
    const __nv_bfloat16* A;
    const __nv_bfloat16* Wp;
    void* Cout;
    const float* bias;
    int M;
    if (mode == 0) {
        A = d_xtA + (size_t)y * NN_PAD * DIM;
        Wp = d_WT[y];
        Cout = (void*)(d_xt8 + (size_t)y * NN * DIM);
        bias = nullptr; M = NN;
    } else {
        A = d_relb;
        Wp = d_WT[3 + y];
        Cout = y ? (void*)d_Vbh : (void*)d_Kbh;
        bias = y ? bv : bk; M = NKEY;
    }
    int tid = threadIdx.x, wid = tid >> 5, lane = tid & 31;
    if (tid < 128) bias_s[tid] = (bias != nullptr) ? bias[tid] : 0.f;
    {   // A tile 64x128 (1024 uint4), coalesced
        const uint4* src = (const uint4*)(A + (size_t)blockIdx.x * 64 * DIM);
        for (int c = tid; c < 1024; c += 256) {
            int r = c >> 4, kq = c & 15;
            *(uint4*)&As[r * TS + kq * 8] = src[c];
        }
    }
    {   // B tile 128x128 (2048 uint4)
        const uint4* src = (const uint4*)Wp;
        for (int c = tid; c < 2048; c += 256) {
            int n = c >> 4, kq = c & 15;
            *(uint4*)&Ws[n * TS + kq * 8] = src[c];
        }
    }
    __syncthreads();

    int rg = wid >> 1, nh = wid & 1;           // row-group 0..3, N-half 0..1
    uint32_t abase = smem_u32(As), wbase = smem_u32(Ws);
    int nofs = (lane & 7) + ((lane >> 4) << 3);
    int kofs = lane & 8;
    int arow = rg * 16 + (lane & 15);
    int akof = (lane >> 4) << 3;

    float acc[8][4];
#pragma unroll
    for (int i = 0; i < 8; i++)
#pragma unroll
        for (int j = 0; j < 4; j++) acc[i][j] = 0.f;

#pragma unroll
    for (int kc = 0; kc < 8; kc++) {
        int k0 = kc * 16;
        uint32_t a0, a1, a2, a3;
        ldsm4(a0, a1, a2, a3, abase + (uint32_t)((arow * TS + k0 + akof) * 2));
#pragma unroll
        for (int nb = 0; nb < 4; nb++) {
            uint32_t b0, b1, b2, b3;
            uint32_t ad = wbase +
                (uint32_t)(((nh * 64 + nb * 16 + nofs) * TS + k0 + kofs) * 2);
            ldsm4(b0, b1, b2, b3, ad);
            mma16816(acc[nb * 2],     a0, a1, a2, a3, b0, b1);
            mma16816(acc[nb * 2 + 1], a0, a1, a2, a3, b2, b3);
        }
    }

    int g = lane >> 2, t2 = (lane & 3) * 2;
    int row0 = blockIdx.x * 64 + rg * 16 + g, row1 = row0 + 8;
#pragma unroll
    for (int nc = 0; nc < 8; nc++) {
        int col = nh * 64 + nc * 8 + t2;
        float f0 = acc[nc][0] + bias_s[col];
        float f1 = acc[nc][1] + bias_s[col + 1];
        float f2 = acc[nc][2] + bias_s[col];
        float f3 = acc[nc][3] + bias_s[col + 1];
        if (mode == 0) {
            if (row0 < M)
                *(uint16_t*)((uint8_t*)Cout + (size_t)row0 * DIM + col) =
                    f32x2_to_e4m3x2(f1 * FP8_SCALE, f0 * FP8_SCALE);
            if (row1 < M)
                *(uint16_t*)((uint8_t*)Cout + (size_t)row1 * DIM + col) =
                    f32x2_to_e4m3x2(f3 * FP8_SCALE, f2 * FP8_SCALE);
        } else {
            if (row0 < M)
                *(__nv_bfloat162*)((__nv_bfloat16*)Cout + (size_t)row0 * DIM + col) =
                    __floats2bfloat162_rn(f0, f1);
            if (row1 < M)
                *(__nv_bfloat162*)((__nv_bfloat16*)Cout + (size_t)row1 * DIM + col) =
                    __floats2bfloat162_rn(f2, f3);
        }
    }
}

// ===================== CSR build ============================================
__global__ void count_all(const int* __restrict__ n0, const int* __restrict__ e0,
                          const int* __restrict__ n1, const int* __restrict__ e1,
                          const int* __restrict__ n2, const int* __restrict__ e2) {
    int mod = blockIdx.y;
    const int* nodes = (mod == 0) ? n0 : (mod == 1) ? n1 : n2;
    const int* edges = (mod == 0) ? e0 : (mod == 1) ? e1 : e2;
    int i = blockIdx.x * blockDim.x + threadIdx.x;
    if (i >= NNZV) return;
    atomicAdd(&d_ecnt[mod * EE + edges[i]], 1);
    atomicAdd(&d_ncnt[mod * NN + nodes[i]], 1);
}

__device__ __forceinline__ int wscan_incl(int v, int lane) {
#pragma unroll
    for (int o = 1; o < 32; o <<= 1) {
        int t = __shfl_up_sync(0xffffffffu, v, o);
        if (lane >= o) v += t;
    }
    return v;
}

__global__ void scan_kernel() {
    __shared__ int wsum[32];
    __shared__ int srun, stot;
    int b = blockIdx.x;
    int mod = b % 3;
    bool isE = (b < 3);
    int len = isE ? EE : NN;
    const int* cnt = isE ? (d_ecnt + mod * EE) : (d_ncnt + mod * NN);
    int* off = isE ? (d_eoff + mod * (EE + 1)) : (d_noff + mod * (NN + 1));
    int* cur = isE ? (d_ecur + mod * EE) : (d_ncur + mod * NN);
    int tid = threadIdx.x, warp = tid >> 5, lane = tid & 31;
    if (tid == 0) srun = 0;
    __syncthreads();
    for (int base = 0; base < len; base += 1024) {
        int v = (base + tid < len) ? cnt[base + tid] : 0;
        int incl = wscan_incl(v, lane);
        if (lane == 31) wsum[warp] = incl;
        __syncthreads();
        if (warp == 0) {
            int s = wsum[lane];
            int wincl = wscan_incl(s, lane);
            wsum[lane] = wincl - s;
            if (lane == 31) stot = wincl;
        }
        __syncthreads();
        int run = srun;
        int ex = run + wsum[warp] + incl - v;
        if (base + tid < len) { off[base + tid] = ex; cur[base + tid] = ex; }
        __syncthreads();
        if (tid == 0) srun = run + stot;
        __syncthreads();
    }
    if (tid == 0) off[len] = srun;
}

__global__ void scatter_all(const int* __restrict__ n0, const int* __restrict__ e0,
                            const int* __restrict__ n1, const int* __restrict__ e1,
                            const int* __restrict__ n2, const int* __restrict__ e2) {
    int mod = blockIdx.y;
    const int* nodes = (mod == 0) ? n0 : (mod == 1) ? n1 : n2;
    const int* edges = (mod == 0) ? e0 : (mod == 1) ? e1 : e2;
    int i = blockIdx.x * blockDim.x + threadIdx.x;
    if (i >= NNZV) return;
    int e = edges[i], n = nodes[i];
    int pe = atomicAdd(&d_ecur[mod * EE + e], 1);
    d_csrE[mod * NNZV + pe] = n;
    int pn = atomicAdd(&d_ncur[mod * NN + n], 1);
    d_csrN[mod * NNZV + pn] = e;
}

// ===================== small SIMT GEMM (Q / Wo) ==============================
// normA: divide A[row][d] by d_lsum[(d>>4)*CC + row] while loading (Wo path).
__global__ __launch_bounds__(256, 2)
void gemm_tile(const float* __restrict__ Aext, int Atag,
               const float* __restrict__ W,
               const float* __restrict__ bias, int Ctag, int M, int normA) {
    const float* A = (Aext != nullptr) ? Aext : tag_f32(Atag);
    float* C = tag_f32(Ctag);
    __shared__ float4 As4[8 * 65];
    __shared__ float Ws[32 * 132];
    int tid = threadIdx.x;
    int warp = tid >> 5, lane = tid & 31;
    int row0 = blockIdx.x * 64;
    float4 acc[8];
#pragma unroll
    for (int r = 0; r < 8; r++) acc[r] = make_float4(0.f, 0.f, 0.f, 0.f);
    for (int kt = 0; kt < 4; kt++) {
#pragma unroll
        for (int i = 0; i < 2; i++) {
            int idx = tid + i * 256;
            int r = idx >> 3, cq = idx & 7;
            float4 v = make_float4(0.f, 0.f, 0.f, 0.f);
            if (row0 + r < M) {
                v = *(const float4*)&A[(size_t)(row0 + r) * 128 + kt * 32 + cq * 4];
                if (normA) {
                    int dbase = kt * 32 + cq * 4;
                    float is = 1.f / d_lsum[(dbase >> 4) * CC + (row0 + r)];
                    v.x *= is; v.y *= is; v.z *= is; v.w *= is;
                }
            }
            As4[cq * 65 + r] = v;
        }
#pragma unroll
        for (int i = 0; i < 4; i++) {
            int idx = tid + i * 256;
            int k = idx >> 5, cq = idx & 31;
            *(float4*)&Ws[k * 132 + cq * 4] = *(const float4*)&W[(size_t)(kt * 32 + k) * 128 + cq * 4];
        }
        __syncthreads();
#pragma unroll
        for (int kq = 0; kq < 8; kq++) {
            float4 a[8];
#pragma unroll
            for (int r = 0; r < 8; r++) a[r] = As4[kq * 65 + warp * 8 + r];
#pragma unroll
            for (int j = 0; j < 4; j++) {
                int kk = kq * 4 + j;
                float4 w = *(const float4*)&Ws[kk * 132 + lane * 4];
#pragma unroll
                for (int r = 0; r < 8; r++) {
                    float av = (j == 0) ? a[r].x : (j == 1) ? a[r].y : (j == 2) ? a[r].z : a[r].w;
                    acc[r].x += av * w.x; acc[r].y += av * w.y;
                    acc[r].z += av * w.z; acc[r].w += av * w.w;
                }
            }
        }
        __syncthreads();
    }
    float4 bv = make_float4(0.f, 0.f, 0.f, 0.f);
    if (bias != nullptr) bv = *(const float4*)&bias[lane * 4];
#pragma unroll
    for (int r = 0; r < 8; r++) {
        int row = row0 + warp * 8 + r;
        if (row >= M) continue;
        *(float4*)&C[(size_t)row * 128 + lane * 4] =
            make_float4(acc[r].x + bv.x, acc[r].y + bv.y, acc[r].z + bv.z, acc[r].w + bv.w);
    }
}

// ===================== hypergraph gathers (fp8 payloads) ====================
__global__ void edge_mean_kernel() {
    int gw = (blockIdx.x * blockDim.x + threadIdx.x) >> 5;
    int lane = threadIdx.x & 31;
    if (gw >= 3 * EE) return;
    int mod = gw / EE, e = gw - mod * EE;
    const int* __restrict__ base = d_csrE + mod * NNZV;
    int s0 = d_eoff[mod * (EE + 1) + e];
    int s1 = d_eoff[mod * (EE + 1) + e + 1];
    const uint32_t* __restrict__ xtm = (const uint32_t*)(d_xt8 + (size_t)mod * NN * DIM);
    float a0 = 0.f, a1 = 0.f, a2 = 0.f, a3 = 0.f;
    int j = s0;
    for (; j + 8 <= s1; j += 8) {
        int n[8];
#pragma unroll
        for (int u = 0; u < 8; u++) n[u] = base[j + u];
#pragma unroll
        for (int u = 0; u < 8; u++) {
            uint32_t p = xtm[(size_t)n[u] * 32 + lane];
            float2 f0 = e4m3x2_to_f32x2((uint16_t)(p & 0xFFFF));
            float2 f1 = e4m3x2_to_f32x2((uint16_t)(p >> 16));
            a0 += f0.x; a1 += f0.y; a2 += f1.x; a3 += f1.y;
        }
    }
    for (; j < s1; j++) {
        uint32_t p = xtm[(size_t)base[j] * 32 + lane];
        float2 f0 = e4m3x2_to_f32x2((uint16_t)(p & 0xFFFF));
        float2 f1 = e4m3x2_to_f32x2((uint16_t)(p >> 16));
        a0 += f0.x; a1 += f0.y; a2 += f1.x; a3 += f1.y;
    }
    int deg = s1 - s0; if (deg < 1) deg = 1;
    float inv = 1.f / (float)deg;                 // keep x16 scale in me
    uint16_t w0 = f32x2_to_e4m3x2(a1 * inv, a0 * inv);
    uint16_t w1 = f32x2_to_e4m3x2(a3 * inv, a2 * inv);
    ((uint32_t*)d_me8)[((size_t)mod * EE + e) * 32 + lane] =
        (uint32_t)w0 | ((uint32_t)w1 << 16);
}

__global__ void node_out_kernel(const float* __restrict__ bias_item,
                                const float* __restrict__ bias_entity,
                                const float* __restrict__ bias_word) {
    int gw = (blockIdx.x * blockDim.x + threadIdx.x) >> 5;
    int lane = threadIdx.x & 31;
    if (gw >= 3 * NN) return;
    int mod = gw / NN, n = gw - mod * NN;
    const int* __restrict__ base = d_csrN + mod * NNZV;
    int s0 = d_noff[mod * (NN + 1) + n];
    int s1 = d_noff[mod * (NN + 1) + n + 1];
    const uint32_t* __restrict__ mem = (const uint32_t*)(d_me8 + (size_t)mod * EE * DIM);
    float a0 = 0.f, a1 = 0.f, a2 = 0.f, a3 = 0.f;
    int j = s0;
    for (; j + 8 <= s1; j += 8) {
        int e8[8];
#pragma unroll
        for (int u = 0; u < 8; u++) e8[u] = base[j + u];
#pragma unroll
        for (int u = 0; u < 8; u++) {
            uint32_t p = mem[(size_t)e8[u] * 32 + lane];
            float2 f0 = e4m3x2_to_f32x2((uint16_t)(p & 0xFFFF));
            float2 f1 = e4m3x2_to_f32x2((uint16_t)(p >> 16));
            a0 += f0.x; a1 += f0.y; a2 += f1.x; a3 += f1.y;
        }
    }
    for (; j < s1; j++) {
        uint32_t p = mem[(size_t)base[j] * 32 + lane];
        float2 f0 = e4m3x2_to_f32x2((uint16_t)(p & 0xFFFF));
        float2 f1 = e4m3x2_to_f32x2((uint16_t)(p >> 16));
        a0 += f0.x; a1 += f0.y; a2 += f1.x; a3 += f1.y;
    }
    int deg = s1 - s0; if (deg < 1) deg = 1;
    float inv = 1.f / ((float)deg * FP8_SCALE);   // undo fp8 scale here
    const float* bias = (mod == 0) ? bias_item : (mod == 1) ? bias_entity : bias_word;
    float4 bv = *(const float4*)&bias[lane * 4];
    __nv_bfloat162 b01 = __floats2bfloat162_rn(a0 * inv + bv.x, a1 * inv + bv.y);
    __nv_bfloat162 b23 = __floats2bfloat162_rn(a2 * inv + bv.z, a3 * inv + bv.w);
    uint2 o; o.x = *(uint32_t*)&b01; o.y = *(uint32_t*)&b23;
    ((uint2*)d_relb)[((size_t)mod * NN + n) * 32 + lane] = o;
}

// ===================== attention (single pass, no max; bf16 K/V) ============
#define AT_TILES 235
#define WSTRIDE 258
__global__ void attn_kernel() {
    int bx = blockIdx.x;
    int h = bx / AT_TILES;
    int k0 = (bx % AT_TILES) * 256;
    int tid = threadIdx.x;
    int key = k0 + tid;
    __shared__ float qs[CC * DH];
    __shared__ __half wsm[CC * WSTRIDE];
    __shared__ float4 vsm[256 * 4];
    for (int i = tid; i < CC * DH; i += 256) {
        int q = i / DH, d = i % DH;
        qs[i] = d_qb[q * DIM + h * DH + d];
    }
    for (int i = tid; i < 256 * 4; i += 256) {
        int k = i >> 2, dg = i & 3;
        float4 v = make_float4(0, 0, 0, 0);
        if (k0 + k < NKEY) {
            uint2 p = *(const uint2*)&d_Vbh[(size_t)(k0 + k) * DIM + h * DH + dg * 4];
            float2 f0 = __bfloat1622float2(*(__nv_bfloat162*)&p.x);
            float2 f1 = __bfloat1622float2(*(__nv_bfloat162*)&p.y);
            v = make_float4(f0.x, f0.y, f1.x, f1.y);
        }
        vsm[i] = v;
    }
    float kv[16];
    bool valid = key < NKEY;
    if (valid) {
        const __nv_bfloat16* kr = d_Kbh + (size_t)key * DIM + h * DH;
        uint4 kA = *(const uint4*)kr;
        uint4 kB = *(const uint4*)(kr + 8);
        const uint32_t* kw = (const uint32_t*)&kA;
#pragma unroll
        for (int j = 0; j < 4; j++) {
            float2 f = __bfloat1622float2(*(__nv_bfloat162*)&kw[j]);
            kv[2 * j] = f.x; kv[2 * j + 1] = f.y;
        }
        const uint32_t* kw2 = (const uint32_t*)&kB;
#pragma unroll
        for (int j = 0; j < 4; j++) {
            float2 f = __bfloat1622float2(*(__nv_bfloat162*)&kw2[j]);
            kv[8 + 2 * j] = f.x; kv[8 + 2 * j + 1] = f.y;
        }
    } else {
#pragma unroll
        for (int j = 0; j < 16; j++) kv[j] = 0.f;
    }
    __syncthreads();
#pragma unroll 5
    for (int q = 0; q < CC; q++) {
        const float* qp = &qs[q * DH];
        float s = 0.f;
#pragma unroll
        for (int j = 0; j < 16; j++) s += qp[j] * kv[j];
        float w = valid ? fast_exp(s * 0.25f) : 0.f;   // FMA-pipe exp (no MUFU wall)
        wsm[q * WSTRIDE + tid] = __float2half_rn(w);
    }
    __syncthreads();
    if (tid < CC * 4) {
        int q = tid >> 2, dg = tid & 3;
        float4 acc = make_float4(0, 0, 0, 0);
        float lacc = 0.f;
        const __half* wr = wsm + q * WSTRIDE;
#pragma unroll 4
        for (int k = 0; k < 256; k++) {
            float w = __half2float(wr[k]);
            float4 v = vsm[k * 4 + dg];
            acc.x += w * v.x; acc.y += w * v.y; acc.z += w * v.z; acc.w += w * v.w;
            if (dg == 0) lacc += w;
        }
        float* dst = d_headout + q * DIM + h * DH + dg * 4;
        atomicAdd(dst + 0, acc.x); atomicAdd(dst + 1, acc.y);
        atomicAdd(dst + 2, acc.z); atomicAdd(dst + 3, acc.w);
        if (dg == 0) atomicAdd(&d_lsum[h * CC + q], lacc);
    }
}

// ===================== fused double self-attention ==========================
__global__ void selfattn2_kernel(const float* __restrict__ ctx,
                                 const float* __restrict__ A1, const float* __restrict__ B1,
                                 const float* __restrict__ A2, const float* __restrict__ B2) {
    int tid = threadIdx.x;
    int warp = tid >> 5, lane = tid & 31;
    __shared__ float es[64];
    __shared__ float ws[64];
    __shared__ float u_s[DIM];
    // ---- stage 1 ----
    for (int r = warp; r < CC; r += 32) {
        const float* hr = d_att + (size_t)r * DIM;
        float4 acc = make_float4(0, 0, 0, 0);
        for (int k = 0; k < DIM; k++) {
            float hk = hr[k];
            float4 a = *(const float4*)&A1[(size_t)k * DIM + lane * 4];
            acc.x += hk * a.x; acc.y += hk * a.y; acc.z += hk * a.z; acc.w += hk * a.w;
        }
        float4 b4 = *(const float4*)&B1[lane * 4];
        float v = tanhf(acc.x) * b4.x + tanhf(acc.y) * b4.y
                + tanhf(acc.z) * b4.z + tanhf(acc.w) * b4.w;
#pragma unroll
        for (int o = 16; o; o >>= 1) v += __shfl_xor_sync(0xffffffffu, v, o);
        if (lane == 0) es[r] = v;
    }
    __syncthreads();
    if (tid == 0) {
        float m = -1e30f;
        for (int r = 0; r < CC; r++) m = fmaxf(m, es[r]);
        float s = 0.f;
        for (int r = 0; r < CC; r++) { float w = __expf(es[r] - m); ws[r] = w; s += w; }
        float inv = 1.f / s;
        for (int r = 0; r < CC; r++) ws[r] *= inv;
    }
    __syncthreads();
    if (tid < DIM) {
        float o = 0.f;
        for (int r = 0; r < CC; r++) o += ws[r] * d_att[(size_t)r * DIM + tid];
        u_s[tid] = o;
    }
    __syncthreads();
    // ---- stage 2 ----
    for (int r = warp; r < CC + 1; r += 32) {
        const float* hr = (r == CC) ? u_s : (ctx + (size_t)r * DIM);
        float4 acc = make_float4(0, 0, 0, 0);
        for (int k = 0; k < DIM; k++) {
            float hk = hr[k];
            float4 a = *(const float4*)&A2[(size_t)k * DIM + lane * 4];
            acc.x += hk * a.x; acc.y += hk * a.y; acc.z += hk * a.z; acc.w += hk * a.w;
        }
        float4 b4 = *(const float4*)&B2[lane * 4];
        float v = tanhf(acc.x) * b4.x + tanhf(acc.y) * b4.y
                + tanhf(acc.z) * b4.z + tanhf(acc.w) * b4.w;
#pragma unroll
        for (int o = 16; o; o >>= 1) v += __shfl_xor_sync(0xffffffffu, v, o);
        if (lane == 0) es[r] = v;
    }
    __syncthreads();
    if (tid == 0) {
        float m = -1e30f;
        for (int r = 0; r < CC + 1; r++) m = fmaxf(m, es[r]);
        float s = 0.f;
        for (int r = 0; r < CC + 1; r++) { float w = __expf(es[r] - m); ws[r] = w; s += w; }
        float inv = 1.f / s;
        for (int r = 0; r < CC + 1; r++) ws[r] *= inv;
    }
    __syncthreads();
    if (tid < DIM) {
        float o = 0.f;
        for (int r = 0; r < CC; r++) o += ws[r] * ctx[(size_t)r * DIM + tid];
        o += ws[CC] * u_s[tid];
        d_urepr[tid] = o;
    }
}

// ===================== final scores =========================================
__global__ void recscore_kernel(const float* __restrict__ W,
                                const float* __restrict__ b,
                                float* __restrict__ out) {
    __shared__ float us[DIM];
    int tid = threadIdx.x;
    if (tid < DIM) us[tid] = d_urepr[tid];
    __syncthreads();
    int j = blockIdx.x * 256 + tid;
    if (j >= NENT) return;
    float a0 = 0.f, a1 = 0.f, a2 = 0.f, a3 = 0.f;
#pragma unroll
    for (int d = 0; d < DIM; d += 4) {
        a0 += us[d + 0] * W[(size_t)(d + 0) * NENT + j];
        a1 += us[d + 1] * W[(size_t)(d + 1) * NENT + j];
        a2 += us[d + 2] * W[(size_t)(d + 2) * NENT + j];
        a3 += us[d + 3] * W[(size_t)(d + 3) * NENT + j];
    }
    out[j] = (a0 + a1) + (a2 + a3) + b[j];
}

// ===================== launch ===============================================
extern "C" void kernel_launch(void* const* d_in, const int* in_sizes, int n_in,
                              void* d_out, int out_size) {
    const float* item_emb     = (const float*)d_in[0];
    const float* entity_emb   = (const float*)d_in[1];
    const float* word_emb     = (const float*)d_in[2];
    const float* context_ent  = (const float*)d_in[3];
    const float* theta_item   = (const float*)d_in[4];
    const float* bias_item    = (const float*)d_in[5];
    const float* theta_entity = (const float*)d_in[6];
    const float* bias_entity  = (const float*)d_in[7];
    const float* theta_word   = (const float*)d_in[8];
    const float* bias_word    = (const float*)d_in[9];
    const float* Wq = (const float*)d_in[10];  const float* bq = (const float*)d_in[11];
    const float* Wk = (const float*)d_in[12];  const float* bk = (const float*)d_in[13];
    const float* Wv = (const float*)d_in[14];  const float* bv = (const float*)d_in[15];
    const float* Wo = (const float*)d_in[16];  const float* bo = (const float*)d_in[17];
    const float* a_his = (const float*)d_in[18]; const float* b_his = (const float*)d_in[19];
    const float* a_kg  = (const float*)d_in[20]; const float* b_kg  = (const float*)d_in[21];
    const float* rec_W = (const float*)d_in[22]; const float* rec_b = (const float*)d_in[23];
    const int* item_nodes   = (const int*)d_in[24];
    const int* item_edges   = (const int*)d_in[25];
    const int* entity_nodes = (const int*)d_in[26];
    const int* entity_edges = (const int*)d_in[27];
    const int* word_nodes   = (const int*)d_in[28];
    const int* word_edges   = (const int*)d_in[29];
    float* out = (float*)d_out;

    zero_kernel<<<(3 * NN + 255) / 256, 256>>>();

    // weight + activation pre-conversion
    convW_kernel<<<5, 128>>>(theta_item, theta_entity, theta_word, Wk, Wv);
    convA_kernel<<<(3 * NN_PAD * 16 + 127) / 128, 128>>>(item_emb, entity_emb, word_emb);

    // xt = x @ theta for all 3 modalities (fp8 payload out)
    mmagemm<<<dim3(NT64_NN, 3), 256>>>(0, nullptr, nullptr);

    // CSR build
    dim3 cgrid((NNZV + 255) / 256, 3);
    count_all<<<cgrid, 256>>>(item_nodes, item_edges, entity_nodes, entity_edges,
                              word_nodes, word_edges);
    scan_kernel<<<6, 1024>>>();
    scatter_all<<<cgrid, 256>>>(item_nodes, item_edges, entity_nodes, entity_edges,
                                word_nodes, word_edges);

    // hypergraph aggregation (fp8 payloads; rel emitted as bf16 rows)
    edge_mean_kernel<<<(3 * EE + 7) / 8, 256>>>();
    node_out_kernel<<<(3 * NN + 7) / 8, 256>>>(bias_item, bias_entity, bias_word);

    // K and V projections (bf16 out)
    mmagemm<<<dim3(NT64_NKEY, 2), 256>>>(1, bk, bv);

    // Q projection (small SIMT)
    gemm_tile<<<1, 256>>>(context_ent, -1, Wq, bq, TAG_Q, CC, 0);

    // attention (single pass) + Wo (with fused normalization)
    attn_kernel<<<NHEAD * AT_TILES, 256>>>();
    gemm_tile<<<1, 256>>>(nullptr, TAG_HO, Wo, bo, TAG_ATT, CC, 1);

    // fused double self-attention
    selfattn2_kernel<<<1, 1024>>>(context_ent, a_his, b_his, a_kg, b_kg);

    // final scores
    recscore_kernel<<<(NENT + 255) / 256, 256>>>(rec_W, rec_b, out);
}

// round 11
// speedup vs baseline: 2.3694x; 1.0582x over previous
#include <cuda_runtime.h>
#include <cuda_fp16.h>
#include <cuda_bf16.h>
#include <math.h>
#include <stdint.h>
#include <stddef.h>

#define DIM   128
#define NN    20000
#define NNZV  500000
#define EE    5000
#define CC    50
#define NENT  50000
#define NKEY  60000
#define NHEAD 8
#define DH    16

#define NN_PAD   20096      // 314 * 64
#define NKEY_PAD 60032      // 938 * 64
#define NT64_NN   314
#define NT64_NKEY 938
#define TPC 4               // A-tiles per GEMM CTA

#define FP8_SCALE 16.0f

// ===================== helpers ==============================================
__device__ __forceinline__ uint32_t smem_u32(const void* p) {
    uint32_t a;
    asm("{ .reg .u64 t; cvta.to.shared.u64 t, %1; cvt.u32.u64 %0, t; }"
        : "=r"(a) : "l"(p));
    return a;
}
__device__ __forceinline__ void ldsm4(uint32_t& r0, uint32_t& r1,
                                      uint32_t& r2, uint32_t& r3, uint32_t addr) {
    asm volatile("ldmatrix.sync.aligned.m8n8.x4.shared.b16 {%0,%1,%2,%3}, [%4];"
                 : "=r"(r0), "=r"(r1), "=r"(r2), "=r"(r3) : "r"(addr));
}
__device__ __forceinline__ void mma16816(float* c,
        uint32_t a0, uint32_t a1, uint32_t a2, uint32_t a3,
        uint32_t b0, uint32_t b1) {
    asm volatile("mma.sync.aligned.m16n8k16.row.col.f32.bf16.bf16.f32 "
                 "{%0,%1,%2,%3}, {%4,%5,%6,%7}, {%8,%9}, {%0,%1,%2,%3};"
                 : "+f"(c[0]), "+f"(c[1]), "+f"(c[2]), "+f"(c[3])
                 : "r"(a0), "r"(a1), "r"(a2), "r"(a3), "r"(b0), "r"(b1));
}
// fp8 e4m3 pack/unpack
__device__ __forceinline__ uint16_t f32x2_to_e4m3x2(float hi, float lo) {
    uint16_t r;
    asm("cvt.rn.satfinite.e4m3x2.f32 %0, %1, %2;" : "=h"(r) : "f"(hi), "f"(lo));
    return r;
}
__device__ __forceinline__ float2 e4m3x2_to_f32x2(uint16_t v) {
    uint32_t h2;
    asm("cvt.rn.f16x2.e4m3x2 %0, %1;" : "=r"(h2) : "h"(v));
    return __half22float2(*(__half2*)&h2);
}
// FMA-pipe exp for small |x|; MUFU fallback for |x|>1 (rare)
__device__ __forceinline__ float fast_exp(float x) {
    if (fabsf(x) > 1.0f) return __expf(x);
    float p = 1.3888889e-3f;
    p = fmaf(p, x, 8.3333333e-3f);
    p = fmaf(p, x, 4.1666667e-2f);
    p = fmaf(p, x, 1.6666667e-1f);
    p = fmaf(p, x, 0.5f);
    p = fmaf(p, x, 1.0f);
    p = fmaf(p, x, 1.0f);
    return p;
}

// ===================== scratch =============================================
__device__ __align__(16) __nv_bfloat16 d_xtA[3 * NN_PAD * DIM];
__device__ __align__(16) __nv_bfloat16 d_relb[NKEY_PAD * DIM];
__device__ __align__(16) __nv_bfloat16 d_WT[5][DIM * DIM];       // W^T [n][k]
__device__ __align__(16) uint8_t d_xt8[3 * NN * DIM];            // fp8 x16
__device__ __align__(16) uint8_t d_me8[3 * EE * DIM];            // fp8 x16
__device__ __align__(16) __nv_bfloat16 d_Kbh[NKEY * DIM];
__device__ __align__(16) __nv_bfloat16 d_Vbh[NKEY * DIM];
__device__ float d_qb  [CC * DIM];
__device__ float d_lsum[NHEAD * CC];
__device__ float d_headout[CC * DIM];
__device__ float d_att [CC * DIM];
__device__ float d_urepr[DIM];

__device__ int d_ecnt[3 * EE];
__device__ int d_eoff[3 * (EE + 1)];
__device__ int d_ecur[3 * EE];
__device__ int d_ncnt[3 * NN];
__device__ int d_noff[3 * (NN + 1)];
__device__ int d_ncur[3 * NN];
__device__ int d_csrE[3 * NNZV];
__device__ int d_csrN[3 * NNZV];

#define TAG_Q   0
#define TAG_HO  1
#define TAG_ATT 2
__device__ __forceinline__ float* tag_f32(int t) {
    switch (t) {
        case TAG_Q:   return d_qb;
        case TAG_HO:  return d_headout;
        case TAG_ATT: return d_att;
    }
    return nullptr;
}

// ===================== init =================================================
__global__ void zero_kernel() {
    int i = blockIdx.x * blockDim.x + threadIdx.x;
    if (i < 3 * EE)       d_ecnt[i] = 0;
    if (i < 3 * NN)       d_ncnt[i] = 0;
    if (i < CC * DIM)     d_headout[i] = 0.f;
    if (i < NHEAD * CC)   d_lsum[i] = 0.f;
    if (i < (NKEY_PAD - NKEY) * DIM / 2)
        ((unsigned*)d_relb)[(size_t)NKEY * DIM / 2 + i] = 0u;
}

// ===================== weight pre-convert (parallel, contiguous stores) =====
// grid (5, 8), 128 thr. Block (w, kc): out[n][kc*16 .. +16] = W[k][n].
__global__ void convW_kernel(const float* __restrict__ w0, const float* __restrict__ w1,
                             const float* __restrict__ w2, const float* __restrict__ w3,
                             const float* __restrict__ w4) {
    const float* W = (blockIdx.x == 0) ? w0 : (blockIdx.x == 1) ? w1 :
                     (blockIdx.x == 2) ? w2 : (blockIdx.x == 3) ? w3 : w4;
    __nv_bfloat16* out = d_WT[blockIdx.x];
    int n = threadIdx.x;
    int k0 = blockIdx.y * 16;
    __nv_bfloat16 tmp[16];
#pragma unroll
    for (int kk = 0; kk < 16; kk++)
        tmp[kk] = __float2bfloat16(W[(size_t)(k0 + kk) * DIM + n]);
    uint4* dst = (uint4*)&out[(size_t)n * DIM + k0];
    dst[0] = ((uint4*)tmp)[0];
    dst[1] = ((uint4*)tmp)[1];
}

// ===================== A pre-convert: fp32 -> bf16 row-major (padded) =======
__global__ void convA_kernel(const float* __restrict__ a0, const float* __restrict__ a1,
                             const float* __restrict__ a2) {
    int gid = blockIdx.x * blockDim.x + threadIdx.x;
    if (gid >= 3 * NN_PAD * 16) return;
    int row = gid >> 4, cg = gid & 15;
    int mod = row / NN_PAD, r = row - mod * NN_PAD;
    __nv_bfloat162 h[4];
    if (r < NN) {
        const float* src = ((mod == 0) ? a0 : (mod == 1) ? a1 : a2) + (size_t)r * DIM + cg * 8;
        float4 v0 = *(const float4*)src;
        float4 v1 = *(const float4*)(src + 4);
        h[0] = __floats2bfloat162_rn(v0.x, v0.y);
        h[1] = __floats2bfloat162_rn(v0.z, v0.w);
        h[2] = __floats2bfloat162_rn(v1.x, v1.y);
        h[3] = __floats2bfloat162_rn(v1.z, v1.w);
    } else {
        h[0] = h[1] = h[2] = h[3] = __floats2bfloat162_rn(0.f, 0.f);
    }
    *(uint4*)((char*)d_xtA + (size_t)gid * 16) = *(uint4*)h;
}

// ===================== persistent bf16 mma GEMM =============================
// mode 0: xt GEMMs. grid (ceil(NT64_NN/TPC), 3). B=WT[y] loaded once;
//         TPC A-tiles of 64 rows each; fp8 out.
// mode 1: fused K+V. grid (ceil(NT64_NKEY/TPC), 1). Both Wk,Wv tiles in smem;
//         A loaded once per tile, used for both outputs; bf16 out + bias.
#define TS 136
__global__ __launch_bounds__(256, 2)
void mmagemm(int mode, const float* __restrict__ bk, const float* __restrict__ bv) {
    __shared__ __align__(16) __nv_bfloat16 As[64 * TS];
    __shared__ __align__(16) __nv_bfloat16 Ws[128 * TS];
    __shared__ __align__(16) __nv_bfloat16 Ws2[128 * TS];
    __shared__ float bias_s[256];
    int y = blockIdx.y;
    int tid = threadIdx.x, wid = tid >> 5, lane = tid & 31;

    const __nv_bfloat16* A;
    int ntiles;
    if (mode == 0) {
        A = d_xtA + (size_t)y * NN_PAD * DIM;
        ntiles = NT64_NN;
        const uint4* src = (const uint4*)d_WT[y];
        for (int c = tid; c < 2048; c += 256) {
            int n = c >> 4, kq = c & 15;
            *(uint4*)&Ws[n * TS + kq * 8] = src[c];
        }
    } else {
        A = d_relb;
        ntiles = NT64_NKEY;
        const uint4* srcK = (const uint4*)d_WT[3];
        const uint4* srcV = (const uint4*)d_WT[4];
        for (int c = tid; c < 2048; c += 256) {
            int n = c >> 4, kq = c & 15;
            *(uint4*)&Ws [n * TS + kq * 8] = srcK[c];
            *(uint4*)&Ws2[n * TS + kq * 8] = srcV[c];
        }
        if (tid < 128) { bias_s[tid] = bk[tid]; bias_s[128 + tid] = bv[tid]; }
    }

    int rg = wid >> 1, nh = wid & 1;
    uint32_t abase = smem_u32(As), wbase = smem_u32(Ws), wbase2 = smem_u32(Ws2);
    int nofs = (lane & 7) + ((lane >> 4) << 3);
    int kofs = lane & 8;
    int arow = rg * 16 + (lane & 15);
    int akof = (lane >> 4) << 3;
    int g = lane >> 2, t2 = (lane & 3) * 2;

    for (int t = 0; t < TPC; t++) {
        int tile = blockIdx.x * TPC + t;
        if (tile >= ntiles) break;
        __syncthreads();                        // prev compute done with As
        {
            const uint4* src = (const uint4*)(A + (size_t)tile * 64 * DIM);
            for (int c = tid; c < 1024; c += 256) {
                int r = c >> 4, kq = c & 15;
                *(uint4*)&As[r * TS + kq * 8] = src[c];
            }
        }
        __syncthreads();

        float acc[2][8][4];
        int npass = (mode == 0) ? 1 : 2;
#pragma unroll
        for (int p = 0; p < 2; p++)
#pragma unroll
            for (int i = 0; i < 8; i++)
#pragma unroll
                for (int j = 0; j < 4; j++) acc[p][i][j] = 0.f;

#pragma unroll
        for (int kc = 0; kc < 8; kc++) {
            int k0 = kc * 16;
            uint32_t a0, a1, a2, a3;
            ldsm4(a0, a1, a2, a3, abase + (uint32_t)((arow * TS + k0 + akof) * 2));
#pragma unroll
            for (int nb = 0; nb < 4; nb++) {
                uint32_t off = (uint32_t)(((nh * 64 + nb * 16 + nofs) * TS + k0 + kofs) * 2);
                uint32_t b0, b1, b2, b3;
                ldsm4(b0, b1, b2, b3, wbase + off);
                mma16816(acc[0][nb * 2],     a0, a1, a2, a3, b0, b1);
                mma16816(acc[0][nb * 2 + 1], a0, a1, a2, a3, b2, b3);
                if (mode == 1) {
                    uint32_t c0, c1, c2, c3;
                    ldsm4(c0, c1, c2, c3, wbase2 + off);
                    mma16816(acc[1][nb * 2],     a0, a1, a2, a3, c0, c1);
                    mma16816(acc[1][nb * 2 + 1], a0, a1, a2, a3, c2, c3);
                }
            }
        }

        int row0 = tile * 64 + rg * 16 + g, row1 = row0 + 8;
        for (int p = 0; p < npass; p++) {
#pragma unroll
            for (int nc = 0; nc < 8; nc++) {
                int col = nh * 64 + nc * 8 + t2;
                if (mode == 0) {
                    float f0 = acc[0][nc][0], f1 = acc[0][nc][1];
                    float f2 = acc[0][nc][2], f3 = acc[0][nc][3];
                    uint8_t* Cout = d_xt8 + (size_t)y * NN * DIM;
                    if (row0 < NN)
                        *(uint16_t*)(Cout + (size_t)row0 * DIM + col) =
                            f32x2_to_e4m3x2(f1 * FP8_SCALE, f0 * FP8_SCALE);
                    if (row1 < NN)
                        *(uint16_t*)(Cout + (size_t)row1 * DIM + col) =
                            f32x2_to_e4m3x2(f3 * FP8_SCALE, f2 * FP8_SCALE);
                } else {
                    __nv_bfloat16* Cout = p ? d_Vbh : d_Kbh;
                    const float* bs = bias_s + p * 128;
                    float f0 = acc[p][nc][0] + bs[col];
                    float f1 = acc[p][nc][1] + bs[col + 1];
                    float f2 = acc[p][nc][2] + bs[col];
                    float f3 = acc[p][nc][3] + bs[col + 1];
                    if (row0 < NKEY)
                        *(__nv_bfloat162*)(Cout + (size_t)row0 * DIM + col) =
                            __floats2bfloat162_rn(f0, f1);
                    if (row1 < NKEY)
                        *(__nv_bfloat162*)(Cout + (size_t)row1 * DIM + col) =
                            __floats2bfloat162_rn(f2, f3);
                }
            }
        }
    }
}

// ===================== CSR build ============================================
__global__ void count_all(const int* __restrict__ n0, const int* __restrict__ e0,
                          const int* __restrict__ n1, const int* __restrict__ e1,
                          const int* __restrict__ n2, const int* __restrict__ e2) {
    int mod = blockIdx.y;
    const int* nodes = (mod == 0) ? n0 : (mod == 1) ? n1 : n2;
    const int* edges = (mod == 0) ? e0 : (mod == 1) ? e1 : e2;
    int i = blockIdx.x * blockDim.x + threadIdx.x;
    if (i >= NNZV) return;
    atomicAdd(&d_ecnt[mod * EE + edges[i]], 1);
    atomicAdd(&d_ncnt[mod * NN + nodes[i]], 1);
}

__device__ __forceinline__ int wscan_incl(int v, int lane) {
#pragma unroll
    for (int o = 1; o < 32; o <<= 1) {
        int t = __shfl_up_sync(0xffffffffu, v, o);
        if (lane >= o) v += t;
    }
    return v;
}

__global__ void scan_kernel() {
    __shared__ int wsum[32];
    __shared__ int srun, stot;
    int b = blockIdx.x;
    int mod = b % 3;
    bool isE = (b < 3);
    int len = isE ? EE : NN;
    const int* cnt = isE ? (d_ecnt + mod * EE) : (d_ncnt + mod * NN);
    int* off = isE ? (d_eoff + mod * (EE + 1)) : (d_noff + mod * (NN + 1));
    int* cur = isE ? (d_ecur + mod * EE) : (d_ncur + mod * NN);
    int tid = threadIdx.x, warp = tid >> 5, lane = tid & 31;
    if (tid == 0) srun = 0;
    __syncthreads();
    for (int base = 0; base < len; base += 1024) {
        int v = (base + tid < len) ? cnt[base + tid] : 0;
        int incl = wscan_incl(v, lane);
        if (lane == 31) wsum[warp] = incl;
        __syncthreads();
        if (warp == 0) {
            int s = wsum[lane];
            int wincl = wscan_incl(s, lane);
            wsum[lane] = wincl - s;
            if (lane == 31) stot = wincl;
        }
        __syncthreads();
        int run = srun;
        int ex = run + wsum[warp] + incl - v;
        if (base + tid < len) { off[base + tid] = ex; cur[base + tid] = ex; }
        __syncthreads();
        if (tid == 0) srun = run + stot;
        __syncthreads();
    }
    if (tid == 0) off[len] = srun;
}

__global__ void scatter_all(const int* __restrict__ n0, const int* __restrict__ e0,
                            const int* __restrict__ n1, const int* __restrict__ e1,
                            const int* __restrict__ n2, const int* __restrict__ e2) {
    int mod = blockIdx.y;
    const int* nodes = (mod == 0) ? n0 : (mod == 1) ? n1 : n2;
    const int* edges = (mod == 0) ? e0 : (mod == 1) ? e1 : e2;
    int i = blockIdx.x * blockDim.x + threadIdx.x;
    if (i >= NNZV) return;
    int e = edges[i], n = nodes[i];
    int pe = atomicAdd(&d_ecur[mod * EE + e], 1);
    d_csrE[mod * NNZV + pe] = n;
    int pn = atomicAdd(&d_ncur[mod * NN + n], 1);
    d_csrN[mod * NNZV + pn] = e;
}

// ===================== small SIMT GEMM (Q / Wo) ==============================
__global__ __launch_bounds__(256, 2)
void gemm_tile(const float* __restrict__ Aext, int Atag,
               const float* __restrict__ W,
               const float* __restrict__ bias, int Ctag, int M, int normA) {
    const float* A = (Aext != nullptr) ? Aext : tag_f32(Atag);
    float* C = tag_f32(Ctag);
    __shared__ float4 As4[8 * 65];
    __shared__ float Ws[32 * 132];
    int tid = threadIdx.x;
    int warp = tid >> 5, lane = tid & 31;
    int row0 = blockIdx.x * 64;
    float4 acc[8];
#pragma unroll
    for (int r = 0; r < 8; r++) acc[r] = make_float4(0.f, 0.f, 0.f, 0.f);
    for (int kt = 0; kt < 4; kt++) {
#pragma unroll
        for (int i = 0; i < 2; i++) {
            int idx = tid + i * 256;
            int r = idx >> 3, cq = idx & 7;
            float4 v = make_float4(0.f, 0.f, 0.f, 0.f);
            if (row0 + r < M) {
                v = *(const float4*)&A[(size_t)(row0 + r) * 128 + kt * 32 + cq * 4];
                if (normA) {
                    int dbase = kt * 32 + cq * 4;
                    float is = 1.f / d_lsum[(dbase >> 4) * CC + (row0 + r)];
                    v.x *= is; v.y *= is; v.z *= is; v.w *= is;
                }
            }
            As4[cq * 65 + r] = v;
        }
#pragma unroll
        for (int i = 0; i < 4; i++) {
            int idx = tid + i * 256;
            int k = idx >> 5, cq = idx & 31;
            *(float4*)&Ws[k * 132 + cq * 4] = *(const float4*)&W[(size_t)(kt * 32 + k) * 128 + cq * 4];
        }
        __syncthreads();
#pragma unroll
        for (int kq = 0; kq < 8; kq++) {
            float4 a[8];
#pragma unroll
            for (int r = 0; r < 8; r++) a[r] = As4[kq * 65 + warp * 8 + r];
#pragma unroll
            for (int j = 0; j < 4; j++) {
                int kk = kq * 4 + j;
                float4 w = *(const float4*)&Ws[kk * 132 + lane * 4];
#pragma unroll
                for (int r = 0; r < 8; r++) {
                    float av = (j == 0) ? a[r].x : (j == 1) ? a[r].y : (j == 2) ? a[r].z : a[r].w;
                    acc[r].x += av * w.x; acc[r].y += av * w.y;
                    acc[r].z += av * w.z; acc[r].w += av * w.w;
                }
            }
        }
        __syncthreads();
    }
    float4 bv = make_float4(0.f, 0.f, 0.f, 0.f);
    if (bias != nullptr) bv = *(const float4*)&bias[lane * 4];
#pragma unroll
    for (int r = 0; r < 8; r++) {
        int row = row0 + warp * 8 + r;
        if (row >= M) continue;
        *(float4*)&C[(size_t)row * 128 + lane * 4] =
            make_float4(acc[r].x + bv.x, acc[r].y + bv.y, acc[r].z + bv.z, acc[r].w + bv.w);
    }
}

// ===================== hypergraph gathers (fp8 payloads) ====================
__global__ void edge_mean_kernel() {
    int gw = (blockIdx.x * blockDim.x + threadIdx.x) >> 5;
    int lane = threadIdx.x & 31;
    if (gw >= 3 * EE) return;
    int mod = gw / EE, e = gw - mod * EE;
    const int* __restrict__ base = d_csrE + mod * NNZV;
    int s0 = d_eoff[mod * (EE + 1) + e];
    int s1 = d_eoff[mod * (EE + 1) + e + 1];
    const uint32_t* __restrict__ xtm = (const uint32_t*)(d_xt8 + (size_t)mod * NN * DIM);
    float a0 = 0.f, a1 = 0.f, a2 = 0.f, a3 = 0.f;
    int j = s0;
    for (; j + 8 <= s1; j += 8) {
        int n[8];
#pragma unroll
        for (int u = 0; u < 8; u++) n[u] = base[j + u];
#pragma unroll
        for (int u = 0; u < 8; u++) {
            uint32_t p = xtm[(size_t)n[u] * 32 + lane];
            float2 f0 = e4m3x2_to_f32x2((uint16_t)(p & 0xFFFF));
            float2 f1 = e4m3x2_to_f32x2((uint16_t)(p >> 16));
            a0 += f0.x; a1 += f0.y; a2 += f1.x; a3 += f1.y;
        }
    }
    for (; j < s1; j++) {
        uint32_t p = xtm[(size_t)base[j] * 32 + lane];
        float2 f0 = e4m3x2_to_f32x2((uint16_t)(p & 0xFFFF));
        float2 f1 = e4m3x2_to_f32x2((uint16_t)(p >> 16));
        a0 += f0.x; a1 += f0.y; a2 += f1.x; a3 += f1.y;
    }
    int deg = s1 - s0; if (deg < 1) deg = 1;
    float inv = 1.f / (float)deg;
    uint16_t w0 = f32x2_to_e4m3x2(a1 * inv, a0 * inv);
    uint16_t w1 = f32x2_to_e4m3x2(a3 * inv, a2 * inv);
    ((uint32_t*)d_me8)[((size_t)mod * EE + e) * 32 + lane] =
        (uint32_t)w0 | ((uint32_t)w1 << 16);
}

__global__ void node_out_kernel(const float* __restrict__ bias_item,
                                const float* __restrict__ bias_entity,
                                const float* __restrict__ bias_word) {
    int gw = (blockIdx.x * blockDim.x + threadIdx.x) >> 5;
    int lane = threadIdx.x & 31;
    if (gw >= 3 * NN) return;
    int mod = gw / NN, n = gw - mod * NN;
    const int* __restrict__ base = d_csrN + mod * NNZV;
    int s0 = d_noff[mod * (NN + 1) + n];
    int s1 = d_noff[mod * (NN + 1) + n + 1];
    const uint32_t* __restrict__ mem = (const uint32_t*)(d_me8 + (size_t)mod * EE * DIM);
    float a0 = 0.f, a1 = 0.f, a2 = 0.f, a3 = 0.f;
    int j = s0;
    for (; j + 8 <= s1; j += 8) {
        int e8[8];
#pragma unroll
        for (int u = 0; u < 8; u++) e8[u] = base[j + u];
#pragma unroll
        for (int u = 0; u < 8; u++) {
            uint32_t p = mem[(size_t)e8[u] * 32 + lane];
            float2 f0 = e4m3x2_to_f32x2((uint16_t)(p & 0xFFFF));
            float2 f1 = e4m3x2_to_f32x2((uint16_t)(p >> 16));
            a0 += f0.x; a1 += f0.y; a2 += f1.x; a3 += f1.y;
        }
    }
    for (; j < s1; j++) {
        uint32_t p = mem[(size_t)base[j] * 32 + lane];
        float2 f0 = e4m3x2_to_f32x2((uint16_t)(p & 0xFFFF));
        float2 f1 = e4m3x2_to_f32x2((uint16_t)(p >> 16));
        a0 += f0.x; a1 += f0.y; a2 += f1.x; a3 += f1.y;
    }
    int deg = s1 - s0; if (deg < 1) deg = 1;
    float inv = 1.f / ((float)deg * FP8_SCALE);
    const float* bias = (mod == 0) ? bias_item : (mod == 1) ? bias_entity : bias_word;
    float4 bv = *(const float4*)&bias[lane * 4];
    __nv_bfloat162 b01 = __floats2bfloat162_rn(a0 * inv + bv.x, a1 * inv + bv.y);
    __nv_bfloat162 b23 = __floats2bfloat162_rn(a2 * inv + bv.z, a3 * inv + bv.w);
    uint2 o; o.x = *(uint32_t*)&b01; o.y = *(uint32_t*)&b23;
    ((uint2*)d_relb)[((size_t)mod * NN + n) * 32 + lane] = o;
}

// ===================== attention: scalar scores + mma P·V ===================
// Block = 256 keys of one head. Phase 1: per-thread scores -> bf16 P in smem.
// Phase 2: mma P[64pad x 256] x Vt[24 x 256] where Vt row16 = ones (lsum col).
#define AT_TILES 235
#define WST 264
#define VST 264
__global__ void attn_kernel() {
    int bx = blockIdx.x;
    int h = bx / AT_TILES;
    int k0 = (bx % AT_TILES) * 256;
    int tid = threadIdx.x;
    int key = k0 + tid;
    __shared__ float qs[CC * DH];
    __shared__ __align__(16) __nv_bfloat16 wsm[64 * WST];
    __shared__ __align__(16) __nv_bfloat16 vsm[24 * VST];
    for (int i = tid; i < CC * DH; i += 256) {
        int q = i / DH, d = i % DH;
        qs[i] = d_qb[q * DIM + h * DH + d];
    }
    // V^T tile: rows 0..15 = V dims, row 16 = ones, rows 17..23 = zeros
    for (int i = tid; i < 512; i += 256) {
        int kk = i >> 1, nc = i & 1;
        __nv_bfloat16 tmp[8];
        if (k0 + kk < NKEY) {
            *(uint4*)tmp = *(const uint4*)&d_Vbh[(size_t)(k0 + kk) * DIM + h * DH + nc * 8];
        } else {
#pragma unroll
            for (int j = 0; j < 8; j++) tmp[j] = __float2bfloat16(0.f);
        }
#pragma unroll
        for (int j = 0; j < 8; j++) vsm[(nc * 8 + j) * VST + kk] = tmp[j];
    }
    {
        vsm[16 * VST + tid] = __float2bfloat16(1.f);
        __nv_bfloat16 zz = __float2bfloat16(0.f);
#pragma unroll
        for (int r = 17; r < 24; r++) vsm[r * VST + tid] = zz;
    }
    float kv[16];
    bool valid = key < NKEY;
    if (valid) {
        const __nv_bfloat16* kr = d_Kbh + (size_t)key * DIM + h * DH;
        uint4 kA = *(const uint4*)kr;
        uint4 kB = *(const uint4*)(kr + 8);
        const uint32_t* kw = (const uint32_t*)&kA;
#pragma unroll
        for (int j = 0; j < 4; j++) {
            float2 f = __bfloat1622float2(*(__nv_bfloat162*)&kw[j]);
            kv[2 * j] = f.x; kv[2 * j + 1] = f.y;
        }
        const uint32_t* kw2 = (const uint32_t*)&kB;
#pragma unroll
        for (int j = 0; j < 4; j++) {
            float2 f = __bfloat1622float2(*(__nv_bfloat162*)&kw2[j]);
            kv[8 + 2 * j] = f.x; kv[8 + 2 * j + 1] = f.y;
        }
    } else {
#pragma unroll
        for (int j = 0; j < 16; j++) kv[j] = 0.f;
    }
    // phase 1: scores
#pragma unroll 5
    for (int q = 0; q < CC; q++) {
        const float* qp = &qs[q * DH];
        float s = 0.f;
#pragma unroll
        for (int j = 0; j < 16; j++) s += qp[j] * kv[j];
        float w = valid ? fast_exp(s * 0.25f) : 0.f;
        wsm[q * WST + tid] = __float2bfloat16(w);
    }
    {   // zero padding rows 50..63
        __nv_bfloat16 zz = __float2bfloat16(0.f);
#pragma unroll
        for (int q = CC; q < 64; q++) wsm[q * WST + tid] = zz;
    }
    __syncthreads();
    // phase 2: mma. Warp w: m-block mb = w>>1; even warps n-blocks {0,1}, odd {2}.
    int wid = tid >> 5, lane = tid & 31;
    int mb = wid >> 1;
    int nnb = (wid & 1) ? 1 : 2;
    int nb0 = (wid & 1) ? 2 : 0;
    uint32_t wbase = smem_u32(wsm), vbase = smem_u32(vsm);
    int ar = mb * 16 + (lane & 15), ak = (lane >> 4) << 3;
    int br = lane & 7, bk = (lane >> 3) << 3;
    float acc[2][4];
#pragma unroll
    for (int t = 0; t < 2; t++)
#pragma unroll
        for (int j = 0; j < 4; j++) acc[t][j] = 0.f;
#pragma unroll
    for (int c = 0; c < 8; c++) {          // 32 k per chunk
        int kc = c * 32;
        uint32_t a00, a01, a02, a03, a10, a11, a12, a13;
        ldsm4(a00, a01, a02, a03, wbase + (uint32_t)((ar * WST + kc + ak) * 2));
        ldsm4(a10, a11, a12, a13, wbase + (uint32_t)((ar * WST + kc + 16 + ak) * 2));
        for (int t = 0; t < nnb; t++) {
            int nb = nb0 + t;
            uint32_t b0, b1, b2, b3;
            ldsm4(b0, b1, b2, b3, vbase + (uint32_t)(((nb * 8 + br) * VST + kc + bk) * 2));
            mma16816(acc[t], a00, a01, a02, a03, b0, b1);
            mma16816(acc[t], a10, a11, a12, a13, b2, b3);
        }
    }
    int g = lane >> 2, t2 = (lane & 3) * 2;
    int q0 = mb * 16 + g, q1 = q0 + 8;
    for (int t = 0; t < nnb; t++) {
        int nb = nb0 + t;
        int col = nb * 8 + t2;
        if (col < 16) {
            if (q0 < CC) {
                atomicAdd(&d_headout[q0 * DIM + h * DH + col],     acc[t][0]);
                atomicAdd(&d_headout[q0 * DIM + h * DH + col + 1], acc[t][1]);
            }
            if (q1 < CC) {
                atomicAdd(&d_headout[q1 * DIM + h * DH + col],     acc[t][2]);
                atomicAdd(&d_headout[q1 * DIM + h * DH + col + 1], acc[t][3]);
            }
        } else if (col == 16) {
            if (q0 < CC) atomicAdd(&d_lsum[h * CC + q0], acc[t][0]);
            if (q1 < CC) atomicAdd(&d_lsum[h * CC + q1], acc[t][2]);
        }
    }
}

// ===================== fused double self-attention ==========================
__global__ void selfattn2_kernel(const float* __restrict__ ctx,
                                 const float* __restrict__ A1, const float* __restrict__ B1,
                                 const float* __restrict__ A2, const float* __restrict__ B2) {
    int tid = threadIdx.x;
    int warp = tid >> 5, lane = tid & 31;
    __shared__ float es[64];
    __shared__ float ws[64];
    __shared__ float u_s[DIM];
    for (int r = warp; r < CC; r += 32) {
        const float* hr = d_att + (size_t)r * DIM;
        float4 acc = make_float4(0, 0, 0, 0);
        for (int k = 0; k < DIM; k++) {
            float hk = hr[k];
            float4 a = *(const float4*)&A1[(size_t)k * DIM + lane * 4];
            acc.x += hk * a.x; acc.y += hk * a.y; acc.z += hk * a.z; acc.w += hk * a.w;
        }
        float4 b4 = *(const float4*)&B1[lane * 4];
        float v = tanhf(acc.x) * b4.x + tanhf(acc.y) * b4.y
                + tanhf(acc.z) * b4.z + tanhf(acc.w) * b4.w;
#pragma unroll
        for (int o = 16; o; o >>= 1) v += __shfl_xor_sync(0xffffffffu, v, o);
        if (lane == 0) es[r] = v;
    }
    __syncthreads();
    if (tid == 0) {
        float m = -1e30f;
        for (int r = 0; r < CC; r++) m = fmaxf(m, es[r]);
        float s = 0.f;
        for (int r = 0; r < CC; r++) { float w = __expf(es[r] - m); ws[r] = w; s += w; }
        float inv = 1.f / s;
        for (int r = 0; r < CC; r++) ws[r] *= inv;
    }
    __syncthreads();
    if (tid < DIM) {
        float o = 0.f;
        for (int r = 0; r < CC; r++) o += ws[r] * d_att[(size_t)r * DIM + tid];
        u_s[tid] = o;
    }
    __syncthreads();
    for (int r = warp; r < CC + 1; r += 32) {
        const float* hr = (r == CC) ? u_s : (ctx + (size_t)r * DIM);
        float4 acc = make_float4(0, 0, 0, 0);
        for (int k = 0; k < DIM; k++) {
            float hk = hr[k];
            float4 a = *(const float4*)&A2[(size_t)k * DIM + lane * 4];
            acc.x += hk * a.x; acc.y += hk * a.y; acc.z += hk * a.z; acc.w += hk * a.w;
        }
        float4 b4 = *(const float4*)&B2[lane * 4];
        float v = tanhf(acc.x) * b4.x + tanhf(acc.y) * b4.y
                + tanhf(acc.z) * b4.z + tanhf(acc.w) * b4.w;
#pragma unroll
        for (int o = 16; o; o >>= 1) v += __shfl_xor_sync(0xffffffffu, v, o);
        if (lane == 0) es[r] = v;
    }
    __syncthreads();
    if (tid == 0) {
        float m = -1e30f;
        for (int r = 0; r < CC + 1; r++) m = fmaxf(m, es[r]);
        float s = 0.f;
        for (int r = 0; r < CC + 1; r++) { float w = __expf(es[r] - m); ws[r] = w; s += w; }
        float inv = 1.f / s;
        for (int r = 0; r < CC + 1; r++) ws[r] *= inv;
    }
    __syncthreads();
    if (tid < DIM) {
        float o = 0.f;
        for (int r = 0; r < CC; r++) o += ws[r] * ctx[(size_t)r * DIM + tid];
        o += ws[CC] * u_s[tid];
        d_urepr[tid] = o;
    }
}

// ===================== final scores =========================================
__global__ void recscore_kernel(const float* __restrict__ W,
                                const float* __restrict__ b,
                                float* __restrict__ out) {
    __shared__ float us[DIM];
    int tid = threadIdx.x;
    if (tid < DIM) us[tid] = d_urepr[tid];
    __syncthreads();
    int j = blockIdx.x * 256 + tid;
    if (j >= NENT) return;
    float a0 = 0.f, a1 = 0.f, a2 = 0.f, a3 = 0.f;
#pragma unroll
    for (int d = 0; d < DIM; d += 4) {
        a0 += us[d + 0] * W[(size_t)(d + 0) * NENT + j];
        a1 += us[d + 1] * W[(size_t)(d + 1) * NENT + j];
        a2 += us[d + 2] * W[(size_t)(d + 2) * NENT + j];
        a3 += us[d + 3] * W[(size_t)(d + 3) * NENT + j];
    }
    out[j] = (a0 + a1) + (a2 + a3) + b[j];
}

// ===================== launch ===============================================
extern "C" void kernel_launch(void* const* d_in, const int* in_sizes, int n_in,
                              void* d_out, int out_size) {
    const float* item_emb     = (const float*)d_in[0];
    const float* entity_emb   = (const float*)d_in[1];
    const float* word_emb     = (const float*)d_in[2];
    const float* context_ent  = (const float*)d_in[3];
    const float* theta_item   = (const float*)d_in[4];
    const float* bias_item    = (const float*)d_in[5];
    const float* theta_entity = (const float*)d_in[6];
    const float* bias_entity  = (const float*)d_in[7];
    const float* theta_word   = (const float*)d_in[8];
    const float* bias_word    = (const float*)d_in[9];
    const float* Wq = (const float*)d_in[10];  const float* bq = (const float*)d_in[11];
    const float* Wk = (const float*)d_in[12];  const float* bk = (const float*)d_in[13];
    const float* Wv = (const float*)d_in[14];  const float* bv = (const float*)d_in[15];
    const float* Wo = (const float*)d_in[16];  const float* bo = (const float*)d_in[17];
    const float* a_his = (const float*)d_in[18]; const float* b_his = (const float*)d_in[19];
    const float* a_kg  = (const float*)d_in[20]; const float* b_kg  = (const float*)d_in[21];
    const float* rec_W = (const float*)d_in[22]; const float* rec_b = (const float*)d_in[23];
    const int* item_nodes   = (const int*)d_in[24];
    const int* item_edges   = (const int*)d_in[25];
    const int* entity_nodes = (const int*)d_in[26];
    const int* entity_edges = (const int*)d_in[27];
    const int* word_nodes   = (const int*)d_in[28];
    const int* word_edges   = (const int*)d_in[29];
    float* out = (float*)d_out;

    zero_kernel<<<(3 * NN + 255) / 256, 256>>>();

    convW_kernel<<<dim3(5, 8), 128>>>(theta_item, theta_entity, theta_word, Wk, Wv);
    convA_kernel<<<(3 * NN_PAD * 16 + 127) / 128, 128>>>(item_emb, entity_emb, word_emb);

    // xt GEMMs (persistent, fp8 out)
    mmagemm<<<dim3((NT64_NN + TPC - 1) / TPC, 3), 256>>>(0, nullptr, nullptr);

    // CSR build
    dim3 cgrid((NNZV + 255) / 256, 3);
    count_all<<<cgrid, 256>>>(item_nodes, item_edges, entity_nodes, entity_edges,
                              word_nodes, word_edges);
    scan_kernel<<<6, 1024>>>();
    scatter_all<<<cgrid, 256>>>(item_nodes, item_edges, entity_nodes, entity_edges,
                                word_nodes, word_edges);

    // hypergraph aggregation
    edge_mean_kernel<<<(3 * EE + 7) / 8, 256>>>();
    node_out_kernel<<<(3 * NN + 7) / 8, 256>>>(bias_item, bias_entity, bias_word);

    // fused K+V projection (persistent)
    mmagemm<<<dim3((NT64_NKEY + TPC - 1) / TPC, 1), 256>>>(1, bk, bv);

    // Q projection
    gemm_tile<<<1, 256>>>(context_ent, -1, Wq, bq, TAG_Q, CC, 0);

    // attention + Wo (fused normalization)
    attn_kernel<<<NHEAD * AT_TILES, 256>>>();
    gemm_tile<<<1, 256>>>(nullptr, TAG_HO, Wo, bo, TAG_ATT, CC, 1);

    // fused double self-attention
    selfattn2_kernel<<<1, 1024>>>(context_ent, a_his, b_his, a_kg, b_kg);

    // final scores
    recscore_kernel<<<(NENT + 255) / 256, 256>>>(rec_W, rec_b, out);
}

// round 12
// speedup vs baseline: 2.4320x; 1.0265x over previous
#include <cuda_runtime.h>
#include <cuda_fp16.h>
#include <cuda_bf16.h>
#include <math.h>
#include <stdint.h>
#include <stddef.h>

#define DIM   128
#define NN    20000
#define NNZV  500000
#define EE    5000
#define CC    50
#define NENT  50000
#define NKEY  60000
#define NHEAD 8
#define DH    16

#define NN_PAD   20096      // 314 * 64
#define NKEY_PAD 60032      // 938 * 64
#define NT64_NN   314
#define NT64_NKEY 938
#define TPC 4               // A-tiles per GEMM CTA

#define FP8_SCALE 16.0f

// ===================== helpers ==============================================
__device__ __forceinline__ uint32_t smem_u32(const void* p) {
    uint32_t a;
    asm("{ .reg .u64 t; cvta.to.shared.u64 t, %1; cvt.u32.u64 %0, t; }"
        : "=r"(a) : "l"(p));
    return a;
}
__device__ __forceinline__ void ldsm4(uint32_t& r0, uint32_t& r1,
                                      uint32_t& r2, uint32_t& r3, uint32_t addr) {
    asm volatile("ldmatrix.sync.aligned.m8n8.x4.shared.b16 {%0,%1,%2,%3}, [%4];"
                 : "=r"(r0), "=r"(r1), "=r"(r2), "=r"(r3) : "r"(addr));
}
__device__ __forceinline__ void mma16816(float* c,
        uint32_t a0, uint32_t a1, uint32_t a2, uint32_t a3,
        uint32_t b0, uint32_t b1) {
    asm volatile("mma.sync.aligned.m16n8k16.row.col.f32.bf16.bf16.f32 "
                 "{%0,%1,%2,%3}, {%4,%5,%6,%7}, {%8,%9}, {%0,%1,%2,%3};"
                 : "+f"(c[0]), "+f"(c[1]), "+f"(c[2]), "+f"(c[3])
                 : "r"(a0), "r"(a1), "r"(a2), "r"(a3), "r"(b0), "r"(b1));
}
__device__ __forceinline__ void cp_async16(uint32_t s, const void* g) {
    asm volatile("cp.async.cg.shared.global [%0], [%1], 16;" :: "r"(s), "l"(g));
}
#define CP_COMMIT() asm volatile("cp.async.commit_group;" ::: "memory")
#define CP_WAIT0()  asm volatile("cp.async.wait_group 0;" ::: "memory")
// fp8 e4m3 pack/unpack
__device__ __forceinline__ uint16_t f32x2_to_e4m3x2(float hi, float lo) {
    uint16_t r;
    asm("cvt.rn.satfinite.e4m3x2.f32 %0, %1, %2;" : "=h"(r) : "f"(hi), "f"(lo));
    return r;
}
__device__ __forceinline__ float2 e4m3x2_to_f32x2(uint16_t v) {
    uint32_t h2;
    asm("cvt.rn.f16x2.e4m3x2 %0, %1;" : "=r"(h2) : "h"(v));
    return __half22float2(*(__half2*)&h2);
}
// FMA-pipe exp for small |x|; MUFU fallback for |x|>1 (rare)
__device__ __forceinline__ float fast_exp(float x) {
    if (fabsf(x) > 1.0f) return __expf(x);
    float p = 1.3888889e-3f;
    p = fmaf(p, x, 8.3333333e-3f);
    p = fmaf(p, x, 4.1666667e-2f);
    p = fmaf(p, x, 1.6666667e-1f);
    p = fmaf(p, x, 0.5f);
    p = fmaf(p, x, 1.0f);
    p = fmaf(p, x, 1.0f);
    return p;
}

// ===================== scratch =============================================
__device__ __align__(16) __nv_bfloat16 d_xtA[3 * NN_PAD * DIM];
__device__ __align__(16) __nv_bfloat16 d_relb[NKEY_PAD * DIM];
__device__ __align__(16) __nv_bfloat16 d_WT[5][DIM * DIM];       // W^T [n][k]
__device__ __align__(16) uint8_t d_xt8[3 * NN * DIM];            // fp8 x16
__device__ __align__(16) uint8_t d_me8[3 * EE * DIM];            // fp8 x16
__device__ __align__(16) __nv_bfloat16 d_Kbh[NKEY * DIM];
__device__ __align__(16) __nv_bfloat16 d_Vbh[NKEY * DIM];
__device__ float d_qb  [CC * DIM];
__device__ float d_lsum[NHEAD * CC];
__device__ float d_headout[CC * DIM];
__device__ float d_att [CC * DIM];
__device__ float d_urepr[DIM];

__device__ int d_ecnt[3 * EE];
__device__ int d_eoff[3 * (EE + 1)];
__device__ int d_ecur[3 * EE];
__device__ int d_ncnt[3 * NN];
__device__ int d_noff[3 * (NN + 1)];
__device__ int d_ncur[3 * NN];
__device__ int d_csrE[3 * NNZV];
__device__ int d_csrN[3 * NNZV];

#define TAG_Q   0
#define TAG_HO  1
#define TAG_ATT 2
__device__ __forceinline__ float* tag_f32(int t) {
    switch (t) {
        case TAG_Q:   return d_qb;
        case TAG_HO:  return d_headout;
        case TAG_ATT: return d_att;
    }
    return nullptr;
}

// ===================== init =================================================
__global__ void zero_kernel() {
    int i = blockIdx.x * blockDim.x + threadIdx.x;
    if (i < 3 * EE)       d_ecnt[i] = 0;
    if (i < 3 * NN)       d_ncnt[i] = 0;
    if (i < CC * DIM)     d_headout[i] = 0.f;
    if (i < NHEAD * CC)   d_lsum[i] = 0.f;
    if (i < (NKEY_PAD - NKEY) * DIM / 2)
        ((unsigned*)d_relb)[(size_t)NKEY * DIM / 2 + i] = 0u;
}

// ===================== weight pre-convert ===================================
__global__ void convW_kernel(const float* __restrict__ w0, const float* __restrict__ w1,
                             const float* __restrict__ w2, const float* __restrict__ w3,
                             const float* __restrict__ w4) {
    const float* W = (blockIdx.x == 0) ? w0 : (blockIdx.x == 1) ? w1 :
                     (blockIdx.x == 2) ? w2 : (blockIdx.x == 3) ? w3 : w4;
    __nv_bfloat16* out = d_WT[blockIdx.x];
    int n = threadIdx.x;
    int k0 = blockIdx.y * 16;
    __nv_bfloat16 tmp[16];
#pragma unroll
    for (int kk = 0; kk < 16; kk++)
        tmp[kk] = __float2bfloat16(W[(size_t)(k0 + kk) * DIM + n]);
    uint4* dst = (uint4*)&out[(size_t)n * DIM + k0];
    dst[0] = ((uint4*)tmp)[0];
    dst[1] = ((uint4*)tmp)[1];
}

// ===================== A pre-convert ========================================
__global__ void convA_kernel(const float* __restrict__ a0, const float* __restrict__ a1,
                             const float* __restrict__ a2) {
    int gid = blockIdx.x * blockDim.x + threadIdx.x;
    if (gid >= 3 * NN_PAD * 16) return;
    int row = gid >> 4, cg = gid & 15;
    int mod = row / NN_PAD, r = row - mod * NN_PAD;
    __nv_bfloat162 h[4];
    if (r < NN) {
        const float* src = ((mod == 0) ? a0 : (mod == 1) ? a1 : a2) + (size_t)r * DIM + cg * 8;
        float4 v0 = *(const float4*)src;
        float4 v1 = *(const float4*)(src + 4);
        h[0] = __floats2bfloat162_rn(v0.x, v0.y);
        h[1] = __floats2bfloat162_rn(v0.z, v0.w);
        h[2] = __floats2bfloat162_rn(v1.x, v1.y);
        h[3] = __floats2bfloat162_rn(v1.z, v1.w);
    } else {
        h[0] = h[1] = h[2] = h[3] = __floats2bfloat162_rn(0.f, 0.f);
    }
    *(uint4*)((char*)d_xtA + (size_t)gid * 16) = *(uint4*)h;
}

// ===================== GEMM core pieces =====================================
#define TS 136
__device__ __forceinline__ void load_a_tile_async(uint32_t abuf,
        const __nv_bfloat16* A, int tile, int tid) {
    const uint4* src = (const uint4*)(A + (size_t)tile * 64 * DIM);
#pragma unroll
    for (int i = 0; i < 4; i++) {
        int c = tid + i * 256;
        int r = c >> 4, kq = c & 15;
        cp_async16(abuf + (uint32_t)((r * TS + kq * 8) * 2), src + c);
    }
}

// ---- xt GEMM: grid (ceil(NT64_NN/TPC), 3); fp8 out; double-buffered A ------
__global__ __launch_bounds__(256, 2)
void mmagemm_x() {
    __shared__ __align__(16) __nv_bfloat16 As[2][64 * TS];
    __shared__ __align__(16) __nv_bfloat16 Ws[128 * TS];
    int y = blockIdx.y;
    int tid = threadIdx.x, wid = tid >> 5, lane = tid & 31;
    const __nv_bfloat16* A = d_xtA + (size_t)y * NN_PAD * DIM;
    uint8_t* Cout = d_xt8 + (size_t)y * NN * DIM;
    {
        const uint4* src = (const uint4*)d_WT[y];
        for (int c = tid; c < 2048; c += 256) {
            int n = c >> 4, kq = c & 15;
            *(uint4*)&Ws[n * TS + kq * 8] = src[c];
        }
    }
    int rg = wid >> 1, nh = wid & 1;
    uint32_t ab0 = smem_u32(As[0]), ab1 = smem_u32(As[1]);
    uint32_t wbase = smem_u32(Ws);
    int nofs = (lane & 7) + ((lane >> 4) << 3);
    int kofs = lane & 8;
    int arow = rg * 16 + (lane & 15);
    int akof = (lane >> 4) << 3;
    int g = lane >> 2, t2 = (lane & 3) * 2;

    int tile0 = blockIdx.x * TPC;
    int tmax = NT64_NN - tile0; if (tmax > TPC) tmax = TPC;
    if (tmax <= 0) return;
    load_a_tile_async(ab0, A, tile0, tid);
    CP_COMMIT(); CP_WAIT0();
    __syncthreads();

    for (int t = 0; t < tmax; t++) {
        uint32_t abase = (t & 1) ? ab1 : ab0;
        if (t + 1 < tmax) {
            load_a_tile_async((t & 1) ? ab0 : ab1, A, tile0 + t + 1, tid);
            CP_COMMIT();
        }
        float acc[8][4];
#pragma unroll
        for (int i = 0; i < 8; i++)
#pragma unroll
            for (int j = 0; j < 4; j++) acc[i][j] = 0.f;
#pragma unroll
        for (int kc = 0; kc < 8; kc++) {
            int k0 = kc * 16;
            uint32_t a0, a1, a2, a3;
            ldsm4(a0, a1, a2, a3, abase + (uint32_t)((arow * TS + k0 + akof) * 2));
#pragma unroll
            for (int nb = 0; nb < 4; nb++) {
                uint32_t b0, b1, b2, b3;
                ldsm4(b0, b1, b2, b3, wbase +
                      (uint32_t)(((nh * 64 + nb * 16 + nofs) * TS + k0 + kofs) * 2));
                mma16816(acc[nb * 2],     a0, a1, a2, a3, b0, b1);
                mma16816(acc[nb * 2 + 1], a0, a1, a2, a3, b2, b3);
            }
        }
        int row0 = (tile0 + t) * 64 + rg * 16 + g, row1 = row0 + 8;
#pragma unroll
        for (int nc = 0; nc < 8; nc++) {
            int col = nh * 64 + nc * 8 + t2;
            if (row0 < NN)
                *(uint16_t*)(Cout + (size_t)row0 * DIM + col) =
                    f32x2_to_e4m3x2(acc[nc][1] * FP8_SCALE, acc[nc][0] * FP8_SCALE);
            if (row1 < NN)
                *(uint16_t*)(Cout + (size_t)row1 * DIM + col) =
                    f32x2_to_e4m3x2(acc[nc][3] * FP8_SCALE, acc[nc][2] * FP8_SCALE);
        }
        CP_WAIT0();
        __syncthreads();
    }
}

// ---- K/V GEMM: grid (ceil(NT64_NKEY/TPC), 2); bf16 out + bias -------------
__global__ __launch_bounds__(256, 2)
void mmagemm_kv(const float* __restrict__ bk, const float* __restrict__ bv) {
    __shared__ __align__(16) __nv_bfloat16 As[2][64 * TS];
    __shared__ __align__(16) __nv_bfloat16 Ws[128 * TS];
    __shared__ float bias_s[128];
    int y = blockIdx.y;                         // 0 = K, 1 = V
    int tid = threadIdx.x, wid = tid >> 5, lane = tid & 31;
    __nv_bfloat16* Cout = y ? d_Vbh : d_Kbh;
    const float* bias = y ? bv : bk;
    if (tid < 128) bias_s[tid] = bias[tid];
    {
        const uint4* src = (const uint4*)d_WT[3 + y];
        for (int c = tid; c < 2048; c += 256) {
            int n = c >> 4, kq = c & 15;
            *(uint4*)&Ws[n * TS + kq * 8] = src[c];
        }
    }
    int rg = wid >> 1, nh = wid & 1;
    uint32_t ab0 = smem_u32(As[0]), ab1 = smem_u32(As[1]);
    uint32_t wbase = smem_u32(Ws);
    int nofs = (lane & 7) + ((lane >> 4) << 3);
    int kofs = lane & 8;
    int arow = rg * 16 + (lane & 15);
    int akof = (lane >> 4) << 3;
    int g = lane >> 2, t2 = (lane & 3) * 2;

    int tile0 = blockIdx.x * TPC;
    int tmax = NT64_NKEY - tile0; if (tmax > TPC) tmax = TPC;
    if (tmax <= 0) return;
    load_a_tile_async(ab0, d_relb, tile0, tid);
    CP_COMMIT(); CP_WAIT0();
    __syncthreads();

    for (int t = 0; t < tmax; t++) {
        uint32_t abase = (t & 1) ? ab1 : ab0;
        if (t + 1 < tmax) {
            load_a_tile_async((t & 1) ? ab0 : ab1, d_relb, tile0 + t + 1, tid);
            CP_COMMIT();
        }
        float acc[8][4];
#pragma unroll
        for (int i = 0; i < 8; i++)
#pragma unroll
            for (int j = 0; j < 4; j++) acc[i][j] = 0.f;
#pragma unroll
        for (int kc = 0; kc < 8; kc++) {
            int k0 = kc * 16;
            uint32_t a0, a1, a2, a3;
            ldsm4(a0, a1, a2, a3, abase + (uint32_t)((arow * TS + k0 + akof) * 2));
#pragma unroll
            for (int nb = 0; nb < 4; nb++) {
                uint32_t b0, b1, b2, b3;
                ldsm4(b0, b1, b2, b3, wbase +
                      (uint32_t)(((nh * 64 + nb * 16 + nofs) * TS + k0 + kofs) * 2));
                mma16816(acc[nb * 2],     a0, a1, a2, a3, b0, b1);
                mma16816(acc[nb * 2 + 1], a0, a1, a2, a3, b2, b3);
            }
        }
        int row0 = (tile0 + t) * 64 + rg * 16 + g, row1 = row0 + 8;
#pragma unroll
        for (int nc = 0; nc < 8; nc++) {
            int col = nh * 64 + nc * 8 + t2;
            float f0 = acc[nc][0] + bias_s[col];
            float f1 = acc[nc][1] + bias_s[col + 1];
            float f2 = acc[nc][2] + bias_s[col];
            float f3 = acc[nc][3] + bias_s[col + 1];
            if (row0 < NKEY)
                *(__nv_bfloat162*)(Cout + (size_t)row0 * DIM + col) =
                    __floats2bfloat162_rn(f0, f1);
            if (row1 < NKEY)
                *(__nv_bfloat162*)(Cout + (size_t)row1 * DIM + col) =
                    __floats2bfloat162_rn(f2, f3);
        }
        CP_WAIT0();
        __syncthreads();
    }
}

// ===================== CSR build ============================================
__global__ void count_all(const int* __restrict__ n0, const int* __restrict__ e0,
                          const int* __restrict__ n1, const int* __restrict__ e1,
                          const int* __restrict__ n2, const int* __restrict__ e2) {
    int mod = blockIdx.y;
    const int* nodes = (mod == 0) ? n0 : (mod == 1) ? n1 : n2;
    const int* edges = (mod == 0) ? e0 : (mod == 1) ? e1 : e2;
    int i = blockIdx.x * blockDim.x + threadIdx.x;
    if (i >= NNZV) return;
    atomicAdd(&d_ecnt[mod * EE + edges[i]], 1);
    atomicAdd(&d_ncnt[mod * NN + nodes[i]], 1);
}

__device__ __forceinline__ int wscan_incl(int v, int lane) {
#pragma unroll
    for (int o = 1; o < 32; o <<= 1) {
        int t = __shfl_up_sync(0xffffffffu, v, o);
        if (lane >= o) v += t;
    }
    return v;
}

__global__ void scan_kernel() {
    __shared__ int wsum[32];
    __shared__ int srun, stot;
    int b = blockIdx.x;
    int mod = b % 3;
    bool isE = (b < 3);
    int len = isE ? EE : NN;
    const int* cnt = isE ? (d_ecnt + mod * EE) : (d_ncnt + mod * NN);
    int* off = isE ? (d_eoff + mod * (EE + 1)) : (d_noff + mod * (NN + 1));
    int* cur = isE ? (d_ecur + mod * EE) : (d_ncur + mod * NN);
    int tid = threadIdx.x, warp = tid >> 5, lane = tid & 31;
    if (tid == 0) srun = 0;
    __syncthreads();
    for (int base = 0; base < len; base += 1024) {
        int v = (base + tid < len) ? cnt[base + tid] : 0;
        int incl = wscan_incl(v, lane);
        if (lane == 31) wsum[warp] = incl;
        __syncthreads();
        if (warp == 0) {
            int s = wsum[lane];
            int wincl = wscan_incl(s, lane);
            wsum[lane] = wincl - s;
            if (lane == 31) stot = wincl;
        }
        __syncthreads();
        int run = srun;
        int ex = run + wsum[warp] + incl - v;
        if (base + tid < len) { off[base + tid] = ex; cur[base + tid] = ex; }
        __syncthreads();
        if (tid == 0) srun = run + stot;
        __syncthreads();
    }
    if (tid == 0) off[len] = srun;
}

__global__ void scatter_all(const int* __restrict__ n0, const int* __restrict__ e0,
                            const int* __restrict__ n1, const int* __restrict__ e1,
                            const int* __restrict__ n2, const int* __restrict__ e2) {
    int mod = blockIdx.y;
    const int* nodes = (mod == 0) ? n0 : (mod == 1) ? n1 : n2;
    const int* edges = (mod == 0) ? e0 : (mod == 1) ? e1 : e2;
    int i = blockIdx.x * blockDim.x + threadIdx.x;
    if (i >= NNZV) return;
    int e = edges[i], n = nodes[i];
    int pe = atomicAdd(&d_ecur[mod * EE + e], 1);
    d_csrE[mod * NNZV + pe] = n;
    int pn = atomicAdd(&d_ncur[mod * NN + n], 1);
    d_csrN[mod * NNZV + pn] = e;
}

// ===================== small SIMT GEMM (Q / Wo) ==============================
__global__ __launch_bounds__(256, 2)
void gemm_tile(const float* __restrict__ Aext, int Atag,
               const float* __restrict__ W,
               const float* __restrict__ bias, int Ctag, int M, int normA) {
    const float* A = (Aext != nullptr) ? Aext : tag_f32(Atag);
    float* C = tag_f32(Ctag);
    __shared__ float4 As4[8 * 65];
    __shared__ float Ws[32 * 132];
    int tid = threadIdx.x;
    int warp = tid >> 5, lane = tid & 31;
    int row0 = blockIdx.x * 64;
    float4 acc[8];
#pragma unroll
    for (int r = 0; r < 8; r++) acc[r] = make_float4(0.f, 0.f, 0.f, 0.f);
    for (int kt = 0; kt < 4; kt++) {
#pragma unroll
        for (int i = 0; i < 2; i++) {
            int idx = tid + i * 256;
            int r = idx >> 3, cq = idx & 7;
            float4 v = make_float4(0.f, 0.f, 0.f, 0.f);
            if (row0 + r < M) {
                v = *(const float4*)&A[(size_t)(row0 + r) * 128 + kt * 32 + cq * 4];
                if (normA) {
                    int dbase = kt * 32 + cq * 4;
                    float is = 1.f / d_lsum[(dbase >> 4) * CC + (row0 + r)];
                    v.x *= is; v.y *= is; v.z *= is; v.w *= is;
                }
            }
            As4[cq * 65 + r] = v;
        }
#pragma unroll
        for (int i = 0; i < 4; i++) {
            int idx = tid + i * 256;
            int k = idx >> 5, cq = idx & 31;
            *(float4*)&Ws[k * 132 + cq * 4] = *(const float4*)&W[(size_t)(kt * 32 + k) * 128 + cq * 4];
        }
        __syncthreads();
#pragma unroll
        for (int kq = 0; kq < 8; kq++) {
            float4 a[8];
#pragma unroll
            for (int r = 0; r < 8; r++) a[r] = As4[kq * 65 + warp * 8 + r];
#pragma unroll
            for (int j = 0; j < 4; j++) {
                int kk = kq * 4 + j;
                float4 w = *(const float4*)&Ws[kk * 132 + lane * 4];
#pragma unroll
                for (int r = 0; r < 8; r++) {
                    float av = (j == 0) ? a[r].x : (j == 1) ? a[r].y : (j == 2) ? a[r].z : a[r].w;
                    acc[r].x += av * w.x; acc[r].y += av * w.y;
                    acc[r].z += av * w.z; acc[r].w += av * w.w;
                }
            }
        }
        __syncthreads();
    }
    float4 bv = make_float4(0.f, 0.f, 0.f, 0.f);
    if (bias != nullptr) bv = *(const float4*)&bias[lane * 4];
#pragma unroll
    for (int r = 0; r < 8; r++) {
        int row = row0 + warp * 8 + r;
        if (row >= M) continue;
        *(float4*)&C[(size_t)row * 128 + lane * 4] =
            make_float4(acc[r].x + bv.x, acc[r].y + bv.y, acc[r].z + bv.z, acc[r].w + bv.w);
    }
}

// ===================== hypergraph gathers (fp8 payloads) ====================
__global__ void edge_mean_kernel() {
    int gw = (blockIdx.x * blockDim.x + threadIdx.x) >> 5;
    int lane = threadIdx.x & 31;
    if (gw >= 3 * EE) return;
    int mod = gw / EE, e = gw - mod * EE;
    const int* __restrict__ base = d_csrE + mod * NNZV;
    int s0 = d_eoff[mod * (EE + 1) + e];
    int s1 = d_eoff[mod * (EE + 1) + e + 1];
    const uint32_t* __restrict__ xtm = (const uint32_t*)(d_xt8 + (size_t)mod * NN * DIM);
    float a0 = 0.f, a1 = 0.f, a2 = 0.f, a3 = 0.f;
    int j = s0;
    for (; j + 8 <= s1; j += 8) {
        int n[8];
#pragma unroll
        for (int u = 0; u < 8; u++) n[u] = base[j + u];
#pragma unroll
        for (int u = 0; u < 8; u++) {
            uint32_t p = xtm[(size_t)n[u] * 32 + lane];
            float2 f0 = e4m3x2_to_f32x2((uint16_t)(p & 0xFFFF));
            float2 f1 = e4m3x2_to_f32x2((uint16_t)(p >> 16));
            a0 += f0.x; a1 += f0.y; a2 += f1.x; a3 += f1.y;
        }
    }
    for (; j < s1; j++) {
        uint32_t p = xtm[(size_t)base[j] * 32 + lane];
        float2 f0 = e4m3x2_to_f32x2((uint16_t)(p & 0xFFFF));
        float2 f1 = e4m3x2_to_f32x2((uint16_t)(p >> 16));
        a0 += f0.x; a1 += f0.y; a2 += f1.x; a3 += f1.y;
    }
    int deg = s1 - s0; if (deg < 1) deg = 1;
    float inv = 1.f / (float)deg;
    uint16_t w0 = f32x2_to_e4m3x2(a1 * inv, a0 * inv);
    uint16_t w1 = f32x2_to_e4m3x2(a3 * inv, a2 * inv);
    ((uint32_t*)d_me8)[((size_t)mod * EE + e) * 32 + lane] =
        (uint32_t)w0 | ((uint32_t)w1 << 16);
}

__global__ void node_out_kernel(const float* __restrict__ bias_item,
                                const float* __restrict__ bias_entity,
                                const float* __restrict__ bias_word) {
    int gw = (blockIdx.x * blockDim.x + threadIdx.x) >> 5;
    int lane = threadIdx.x & 31;
    if (gw >= 3 * NN) return;
    int mod = gw / NN, n = gw - mod * NN;
    const int* __restrict__ base = d_csrN + mod * NNZV;
    int s0 = d_noff[mod * (NN + 1) + n];
    int s1 = d_noff[mod * (NN + 1) + n + 1];
    const uint32_t* __restrict__ mem = (const uint32_t*)(d_me8 + (size_t)mod * EE * DIM);
    float a0 = 0.f, a1 = 0.f, a2 = 0.f, a3 = 0.f;
    int j = s0;
    for (; j + 8 <= s1; j += 8) {
        int e8[8];
#pragma unroll
        for (int u = 0; u < 8; u++) e8[u] = base[j + u];
#pragma unroll
        for (int u = 0; u < 8; u++) {
            uint32_t p = mem[(size_t)e8[u] * 32 + lane];
            float2 f0 = e4m3x2_to_f32x2((uint16_t)(p & 0xFFFF));
            float2 f1 = e4m3x2_to_f32x2((uint16_t)(p >> 16));
            a0 += f0.x; a1 += f0.y; a2 += f1.x; a3 += f1.y;
        }
    }
    for (; j < s1; j++) {
        uint32_t p = mem[(size_t)base[j] * 32 + lane];
        float2 f0 = e4m3x2_to_f32x2((uint16_t)(p & 0xFFFF));
        float2 f1 = e4m3x2_to_f32x2((uint16_t)(p >> 16));
        a0 += f0.x; a1 += f0.y; a2 += f1.x; a3 += f1.y;
    }
    int deg = s1 - s0; if (deg < 1) deg = 1;
    float inv = 1.f / ((float)deg * FP8_SCALE);
    const float* bias = (mod == 0) ? bias_item : (mod == 1) ? bias_entity : bias_word;
    float4 bv = *(const float4*)&bias[lane * 4];
    __nv_bfloat162 b01 = __floats2bfloat162_rn(a0 * inv + bv.x, a1 * inv + bv.y);
    __nv_bfloat162 b23 = __floats2bfloat162_rn(a2 * inv + bv.z, a3 * inv + bv.w);
    uint2 o; o.x = *(uint32_t*)&b01; o.y = *(uint32_t*)&b23;
    ((uint2*)d_relb)[((size_t)mod * NN + n) * 32 + lane] = o;
}

// ===================== attention: scalar scores + mma P·V ===================
#define AT_TILES 235
#define WST 264
#define VST 264
__global__ void attn_kernel() {
    int bx = blockIdx.x;
    int h = bx / AT_TILES;
    int k0 = (bx % AT_TILES) * 256;
    int tid = threadIdx.x;
    int key = k0 + tid;
    __shared__ float qs[CC * DH];
    __shared__ __align__(16) __nv_bfloat16 wsm[64 * WST];
    __shared__ __align__(16) __nv_bfloat16 vsm[24 * VST];
    for (int i = tid; i < CC * DH; i += 256) {
        int q = i / DH, d = i % DH;
        qs[i] = d_qb[q * DIM + h * DH + d];
    }
    for (int i = tid; i < 512; i += 256) {
        int kk = i >> 1, nc = i & 1;
        __nv_bfloat16 tmp[8];
        if (k0 + kk < NKEY) {
            *(uint4*)tmp = *(const uint4*)&d_Vbh[(size_t)(k0 + kk) * DIM + h * DH + nc * 8];
        } else {
#pragma unroll
            for (int j = 0; j < 8; j++) tmp[j] = __float2bfloat16(0.f);
        }
#pragma unroll
        for (int j = 0; j < 8; j++) vsm[(nc * 8 + j) * VST + kk] = tmp[j];
    }
    {
        vsm[16 * VST + tid] = __float2bfloat16(1.f);
        __nv_bfloat16 zz = __float2bfloat16(0.f);
#pragma unroll
        for (int r = 17; r < 24; r++) vsm[r * VST + tid] = zz;
    }
    float kv[16];
    bool valid = key < NKEY;
    if (valid) {
        const __nv_bfloat16* kr = d_Kbh + (size_t)key * DIM + h * DH;
        uint4 kA = *(const uint4*)kr;
        uint4 kB = *(const uint4*)(kr + 8);
        const uint32_t* kw = (const uint32_t*)&kA;
#pragma unroll
        for (int j = 0; j < 4; j++) {
            float2 f = __bfloat1622float2(*(__nv_bfloat162*)&kw[j]);
            kv[2 * j] = f.x; kv[2 * j + 1] = f.y;
        }
        const uint32_t* kw2 = (const uint32_t*)&kB;
#pragma unroll
        for (int j = 0; j < 4; j++) {
            float2 f = __bfloat1622float2(*(__nv_bfloat162*)&kw2[j]);
            kv[8 + 2 * j] = f.x; kv[8 + 2 * j + 1] = f.y;
        }
    } else {
#pragma unroll
        for (int j = 0; j < 16; j++) kv[j] = 0.f;
    }
#pragma unroll 5
    for (int q = 0; q < CC; q++) {
        const float* qp = &qs[q * DH];
        float s = 0.f;
#pragma unroll
        for (int j = 0; j < 16; j++) s += qp[j] * kv[j];
        float w = valid ? fast_exp(s * 0.25f) : 0.f;
        wsm[q * WST + tid] = __float2bfloat16(w);
    }
    {
        __nv_bfloat16 zz = __float2bfloat16(0.f);
#pragma unroll
        for (int q = CC; q < 64; q++) wsm[q * WST + tid] = zz;
    }
    __syncthreads();
    int wid = tid >> 5, lane = tid & 31;
    int mb = wid >> 1;
    int nnb = (wid & 1) ? 1 : 2;
    int nb0 = (wid & 1) ? 2 : 0;
    uint32_t wbase = smem_u32(wsm), vbase = smem_u32(vsm);
    int ar = mb * 16 + (lane & 15), ak = (lane >> 4) << 3;
    int br = lane & 7, bk = (lane >> 3) << 3;
    float acc[2][4];
#pragma unroll
    for (int t = 0; t < 2; t++)
#pragma unroll
        for (int j = 0; j < 4; j++) acc[t][j] = 0.f;
#pragma unroll
    for (int c = 0; c < 8; c++) {
        int kc = c * 32;
        uint32_t a00, a01, a02, a03, a10, a11, a12, a13;
        ldsm4(a00, a01, a02, a03, wbase + (uint32_t)((ar * WST + kc + ak) * 2));
        ldsm4(a10, a11, a12, a13, wbase + (uint32_t)((ar * WST + kc + 16 + ak) * 2));
        for (int t = 0; t < nnb; t++) {
            int nb = nb0 + t;
            uint32_t b0, b1, b2, b3;
            ldsm4(b0, b1, b2, b3, vbase + (uint32_t)(((nb * 8 + br) * VST + kc + bk) * 2));
            mma16816(acc[t], a00, a01, a02, a03, b0, b1);
            mma16816(acc[t], a10, a11, a12, a13, b2, b3);
        }
    }
    int g = lane >> 2, t2 = (lane & 3) * 2;
    int q0 = mb * 16 + g, q1 = q0 + 8;
    for (int t = 0; t < nnb; t++) {
        int nb = nb0 + t;
        int col = nb * 8 + t2;
        if (col < 16) {
            if (q0 < CC) {
                atomicAdd(&d_headout[q0 * DIM + h * DH + col],     acc[t][0]);
                atomicAdd(&d_headout[q0 * DIM + h * DH + col + 1], acc[t][1]);
            }
            if (q1 < CC) {
                atomicAdd(&d_headout[q1 * DIM + h * DH + col],     acc[t][2]);
                atomicAdd(&d_headout[q1 * DIM + h * DH + col + 1], acc[t][3]);
            }
        } else if (col == 16) {
            if (q0 < CC) atomicAdd(&d_lsum[h * CC + q0], acc[t][0]);
            if (q1 < CC) atomicAdd(&d_lsum[h * CC + q1], acc[t][2]);
        }
    }
}

// ===================== fused double self-attention ==========================
__global__ void selfattn2_kernel(const float* __restrict__ ctx,
                                 const float* __restrict__ A1, const float* __restrict__ B1,
                                 const float* __restrict__ A2, const float* __restrict__ B2) {
    int tid = threadIdx.x;
    int warp = tid >> 5, lane = tid & 31;
    __shared__ float es[64];
    __shared__ float ws[64];
    __shared__ float u_s[DIM];
    for (int r = warp; r < CC; r += 32) {
        const float* hr = d_att + (size_t)r * DIM;
        float4 acc = make_float4(0, 0, 0, 0);
        for (int k = 0; k < DIM; k++) {
            float hk = hr[k];
            float4 a = *(const float4*)&A1[(size_t)k * DIM + lane * 4];
            acc.x += hk * a.x; acc.y += hk * a.y; acc.z += hk * a.z; acc.w += hk * a.w;
        }
        float4 b4 = *(const float4*)&B1[lane * 4];
        float v = tanhf(acc.x) * b4.x + tanhf(acc.y) * b4.y
                + tanhf(acc.z) * b4.z + tanhf(acc.w) * b4.w;
#pragma unroll
        for (int o = 16; o; o >>= 1) v += __shfl_xor_sync(0xffffffffu, v, o);
        if (lane == 0) es[r] = v;
    }
    __syncthreads();
    if (tid == 0) {
        float m = -1e30f;
        for (int r = 0; r < CC; r++) m = fmaxf(m, es[r]);
        float s = 0.f;
        for (int r = 0; r < CC; r++) { float w = __expf(es[r] - m); ws[r] = w; s += w; }
        float inv = 1.f / s;
        for (int r = 0; r < CC; r++) ws[r] *= inv;
    }
    __syncthreads();
    if (tid < DIM) {
        float o = 0.f;
        for (int r = 0; r < CC; r++) o += ws[r] * d_att[(size_t)r * DIM + tid];
        u_s[tid] = o;
    }
    __syncthreads();
    for (int r = warp; r < CC + 1; r += 32) {
        const float* hr = (r == CC) ? u_s : (ctx + (size_t)r * DIM);
        float4 acc = make_float4(0, 0, 0, 0);
        for (int k = 0; k < DIM; k++) {
            float hk = hr[k];
            float4 a = *(const float4*)&A2[(size_t)k * DIM + lane * 4];
            acc.x += hk * a.x; acc.y += hk * a.y; acc.z += hk * a.z; acc.w += hk * a.w;
        }
        float4 b4 = *(const float4*)&B2[lane * 4];
        float v = tanhf(acc.x) * b4.x + tanhf(acc.y) * b4.y
                + tanhf(acc.z) * b4.z + tanhf(acc.w) * b4.w;
#pragma unroll
        for (int o = 16; o; o >>= 1) v += __shfl_xor_sync(0xffffffffu, v, o);
        if (lane == 0) es[r] = v;
    }
    __syncthreads();
    if (tid == 0) {
        float m = -1e30f;
        for (int r = 0; r < CC + 1; r++) m = fmaxf(m, es[r]);
        float s = 0.f;
        for (int r = 0; r < CC + 1; r++) { float w = __expf(es[r] - m); ws[r] = w; s += w; }
        float inv = 1.f / s;
        for (int r = 0; r < CC + 1; r++) ws[r] *= inv;
    }
    __syncthreads();
    if (tid < DIM) {
        float o = 0.f;
        for (int r = 0; r < CC; r++) o += ws[r] * ctx[(size_t)r * DIM + tid];
        o += ws[CC] * u_s[tid];
        d_urepr[tid] = o;
    }
}

// ===================== final scores =========================================
__global__ void recscore_kernel(const float* __restrict__ W,
                                const float* __restrict__ b,
                                float* __restrict__ out) {
    __shared__ float us[DIM];
    int tid = threadIdx.x;
    if (tid < DIM) us[tid] = d_urepr[tid];
    __syncthreads();
    int j = blockIdx.x * 256 + tid;
    if (j >= NENT) return;
    float a0 = 0.f, a1 = 0.f, a2 = 0.f, a3 = 0.f;
#pragma unroll
    for (int d = 0; d < DIM; d += 4) {
        a0 += us[d + 0] * W[(size_t)(d + 0) * NENT + j];
        a1 += us[d + 1] * W[(size_t)(d + 1) * NENT + j];
        a2 += us[d + 2] * W[(size_t)(d + 2) * NENT + j];
        a3 += us[d + 3] * W[(size_t)(d + 3) * NENT + j];
    }
    out[j] = (a0 + a1) + (a2 + a3) + b[j];
}

// ===================== launch ===============================================
extern "C" void kernel_launch(void* const* d_in, const int* in_sizes, int n_in,
                              void* d_out, int out_size) {
    const float* item_emb     = (const float*)d_in[0];
    const float* entity_emb   = (const float*)d_in[1];
    const float* word_emb     = (const float*)d_in[2];
    const float* context_ent  = (const float*)d_in[3];
    const float* theta_item   = (const float*)d_in[4];
    const float* bias_item    = (const float*)d_in[5];
    const float* theta_entity = (const float*)d_in[6];
    const float* bias_entity  = (const float*)d_in[7];
    const float* theta_word   = (const float*)d_in[8];
    const float* bias_word    = (const float*)d_in[9];
    const float* Wq = (const float*)d_in[10];  const float* bq = (const float*)d_in[11];
    const float* Wk = (const float*)d_in[12];  const float* bk = (const float*)d_in[13];
    const float* Wv = (const float*)d_in[14];  const float* bv = (const float*)d_in[15];
    const float* Wo = (const float*)d_in[16];  const float* bo = (const float*)d_in[17];
    const float* a_his = (const float*)d_in[18]; const float* b_his = (const float*)d_in[19];
    const float* a_kg  = (const float*)d_in[20]; const float* b_kg  = (const float*)d_in[21];
    const float* rec_W = (const float*)d_in[22]; const float* rec_b = (const float*)d_in[23];
    const int* item_nodes   = (const int*)d_in[24];
    const int* item_edges   = (const int*)d_in[25];
    const int* entity_nodes = (const int*)d_in[26];
    const int* entity_edges = (const int*)d_in[27];
    const int* word_nodes   = (const int*)d_in[28];
    const int* word_edges   = (const int*)d_in[29];
    float* out = (float*)d_out;

    zero_kernel<<<(3 * NN + 255) / 256, 256>>>();

    convW_kernel<<<dim3(5, 8), 128>>>(theta_item, theta_entity, theta_word, Wk, Wv);
    convA_kernel<<<(3 * NN_PAD * 16 + 127) / 128, 128>>>(item_emb, entity_emb, word_emb);

    // xt GEMMs (double-buffered, fp8 out)
    mmagemm_x<<<dim3((NT64_NN + TPC - 1) / TPC, 3), 256>>>();

    // CSR build
    dim3 cgrid((NNZV + 255) / 256, 3);
    count_all<<<cgrid, 256>>>(item_nodes, item_edges, entity_nodes, entity_edges,
                              word_nodes, word_edges);
    scan_kernel<<<6, 1024>>>();
    scatter_all<<<cgrid, 256>>>(item_nodes, item_edges, entity_nodes, entity_edges,
                                word_nodes, word_edges);

    // hypergraph aggregation
    edge_mean_kernel<<<(3 * EE + 7) / 8, 256>>>();
    node_out_kernel<<<(3 * NN + 7) / 8, 256>>>(bias_item, bias_entity, bias_word);

    // K and V projections (double-buffered)
    mmagemm_kv<<<dim3((NT64_NKEY + TPC - 1) / TPC, 2), 256>>>(bk, bv);

    // Q projection
    gemm_tile<<<1, 256>>>(context_ent, -1, Wq, bq, TAG_Q, CC, 0);

    // attention + Wo (fused normalization)
    attn_kernel<<<NHEAD * AT_TILES, 256>>>();
    gemm_tile<<<1, 256>>>(nullptr, TAG_HO, Wo, bo, TAG_ATT, CC, 1);

    // fused double self-attention
    selfattn2_kernel<<<1, 1024>>>(context_ent, a_his, b_his, a_kg, b_kg);

    // final scores
    recscore_kernel<<<(NENT + 255) / 256, 256>>>(rec_W, rec_b, out);
}

// round 14
// speedup vs baseline: 2.6086x; 1.0726x over previous
#include <cuda_runtime.h>
#include <cuda_fp16.h>
#include <cuda_bf16.h>
#include <math.h>
#include <stdint.h>
#include <stddef.h>

#define DIM   128
#define NN    20000
#define NNZV  500000
#define EE    5000
#define CC    50
#define NENT  50000
#define NKEY  60000
#define NHEAD 8
#define DH    16

#define NN_PAD   20096      // 314 * 64
#define NKEY_PAD 60032      // 938 * 64
#define NT64_NN   314
#define NT64_NKEY 938
#define TPCX 2              // A-tiles per CTA (xt GEMM)
#define TPC  4              // A-tiles per CTA (K/V GEMM)

#define FP8_SCALE 16.0f

// ===================== helpers ==============================================
__device__ __forceinline__ uint32_t smem_u32(const void* p) {
    uint32_t a;
    asm("{ .reg .u64 t; cvta.to.shared.u64 t, %1; cvt.u32.u64 %0, t; }"
        : "=r"(a) : "l"(p));
    return a;
}
__device__ __forceinline__ void ldsm4(uint32_t& r0, uint32_t& r1,
                                      uint32_t& r2, uint32_t& r3, uint32_t addr) {
    asm volatile("ldmatrix.sync.aligned.m8n8.x4.shared.b16 {%0,%1,%2,%3}, [%4];"
                 : "=r"(r0), "=r"(r1), "=r"(r2), "=r"(r3) : "r"(addr));
}
__device__ __forceinline__ void mma16816(float* c,
        uint32_t a0, uint32_t a1, uint32_t a2, uint32_t a3,
        uint32_t b0, uint32_t b1) {
    asm volatile("mma.sync.aligned.m16n8k16.row.col.f32.bf16.bf16.f32 "
                 "{%0,%1,%2,%3}, {%4,%5,%6,%7}, {%8,%9}, {%0,%1,%2,%3};"
                 : "+f"(c[0]), "+f"(c[1]), "+f"(c[2]), "+f"(c[3])
                 : "r"(a0), "r"(a1), "r"(a2), "r"(a3), "r"(b0), "r"(b1));
}
__device__ __forceinline__ void cp_async16(uint32_t s, const void* g) {
    asm volatile("cp.async.cg.shared.global [%0], [%1], 16;" :: "r"(s), "l"(g));
}
#define CP_COMMIT() asm volatile("cp.async.commit_group;" ::: "memory")
#define CP_WAIT0()  asm volatile("cp.async.wait_group 0;" ::: "memory")
__device__ __forceinline__ uint16_t f32x2_to_e4m3x2(float hi, float lo) {
    uint16_t r;
    asm("cvt.rn.satfinite.e4m3x2.f32 %0, %1, %2;" : "=h"(r) : "f"(hi), "f"(lo));
    return r;
}
__device__ __forceinline__ float2 e4m3x2_to_f32x2(uint16_t v) {
    uint32_t h2;
    asm("cvt.rn.f16x2.e4m3x2 %0, %1;" : "=r"(h2) : "h"(v));
    return __half22float2(*(__half2*)&h2);
}
__device__ __forceinline__ float fast_exp(float x) {
    if (fabsf(x) > 1.0f) return __expf(x);
    float p = 1.3888889e-3f;
    p = fmaf(p, x, 8.3333333e-3f);
    p = fmaf(p, x, 4.1666667e-2f);
    p = fmaf(p, x, 1.6666667e-1f);
    p = fmaf(p, x, 0.5f);
    p = fmaf(p, x, 1.0f);
    p = fmaf(p, x, 1.0f);
    return p;
}

// ===================== scratch =============================================
__device__ __align__(16) __nv_bfloat16 d_xtA[3 * NN_PAD * DIM];
__device__ __align__(16) __nv_bfloat16 d_relb[NKEY_PAD * DIM];
__device__ __align__(16) __nv_bfloat16 d_WT[5][DIM * DIM];       // W^T [n][k]
__device__ __align__(16) uint8_t d_xt8[3 * NN * DIM];            // fp8 x16
__device__ __align__(16) uint8_t d_me8[3 * EE * DIM];            // fp8 x16
__device__ __align__(16) __nv_bfloat16 d_Kbh[NKEY * DIM];
__device__ __align__(16) __nv_bfloat16 d_Vbh[NKEY * DIM];
__device__ float d_qb  [CC * DIM];
__device__ float d_lsum[NHEAD * CC];
__device__ float d_headout[CC * DIM];
__device__ float d_att [CC * DIM];
__device__ float d_es1[CC];
__device__ float d_es2[CC];
__device__ float d_urepr[DIM];

__device__ int d_ecnt[3 * EE];
__device__ int d_eoff[3 * (EE + 1)];
__device__ int d_ecur[3 * EE];
__device__ int d_ncnt[3 * NN];
__device__ int d_noff[3 * (NN + 1)];
__device__ int d_ncur[3 * NN];
__device__ int d_csrE[3 * NNZV];
__device__ int d_csrN[3 * NNZV];

// ===================== init =================================================
__global__ void zero_kernel() {
    int i = blockIdx.x * blockDim.x + threadIdx.x;
    if (i < 3 * EE)       d_ecnt[i] = 0;
    if (i < 3 * NN)       d_ncnt[i] = 0;
    if (i < CC * DIM)     d_headout[i] = 0.f;
    if (i < NHEAD * CC)   d_lsum[i] = 0.f;
    if (i < (NKEY_PAD - NKEY) * DIM / 2)
        ((unsigned*)d_relb)[(size_t)NKEY * DIM / 2 + i] = 0u;
}

// ===================== weight pre-convert ===================================
__global__ void convW_kernel(const float* __restrict__ w0, const float* __restrict__ w1,
                             const float* __restrict__ w2, const float* __restrict__ w3,
                             const float* __restrict__ w4) {
    const float* W = (blockIdx.x == 0) ? w0 : (blockIdx.x == 1) ? w1 :
                     (blockIdx.x == 2) ? w2 : (blockIdx.x == 3) ? w3 : w4;
    __nv_bfloat16* out = d_WT[blockIdx.x];
    int n = threadIdx.x;
    int k0 = blockIdx.y * 16;
    __nv_bfloat16 tmp[16];
#pragma unroll
    for (int kk = 0; kk < 16; kk++)
        tmp[kk] = __float2bfloat16(W[(size_t)(k0 + kk) * DIM + n]);
    uint4* dst = (uint4*)&out[(size_t)n * DIM + k0];
    dst[0] = ((uint4*)tmp)[0];
    dst[1] = ((uint4*)tmp)[1];
}

// ===================== A pre-convert ========================================
__global__ void convA_kernel(const float* __restrict__ a0, const float* __restrict__ a1,
                             const float* __restrict__ a2) {
    int gid = blockIdx.x * blockDim.x + threadIdx.x;
    if (gid >= 3 * NN_PAD * 16) return;
    int row = gid >> 4, cg = gid & 15;
    int mod = row / NN_PAD, r = row - mod * NN_PAD;
    __nv_bfloat162 h[4];
    if (r < NN) {
        const float* src = ((mod == 0) ? a0 : (mod == 1) ? a1 : a2) + (size_t)r * DIM + cg * 8;
        float4 v0 = *(const float4*)src;
        float4 v1 = *(const float4*)(src + 4);
        h[0] = __floats2bfloat162_rn(v0.x, v0.y);
        h[1] = __floats2bfloat162_rn(v0.z, v0.w);
        h[2] = __floats2bfloat162_rn(v1.x, v1.y);
        h[3] = __floats2bfloat162_rn(v1.z, v1.w);
    } else {
        h[0] = h[1] = h[2] = h[3] = __floats2bfloat162_rn(0.f, 0.f);
    }
    *(uint4*)((char*)d_xtA + (size_t)gid * 16) = *(uint4*)h;
}

// ===================== GEMM core ============================================
#define TS 136
__device__ __forceinline__ void load_a_tile_async(uint32_t abuf,
        const __nv_bfloat16* A, int tile, int tid) {
    const uint4* src = (const uint4*)(A + (size_t)tile * 64 * DIM);
#pragma unroll
    for (int i = 0; i < 4; i++) {
        int c = tid + i * 256;
        int r = c >> 4, kq = c & 15;
        cp_async16(abuf + (uint32_t)((r * TS + kq * 8) * 2), src + c);
    }
}

// ---- xt GEMM: grid (ceil(NT64_NN/TPCX), 3); fp8 out ------------------------
__global__ __launch_bounds__(256, 2)
void mmagemm_x() {
    __shared__ __align__(16) __nv_bfloat16 As[2][64 * TS];
    __shared__ __align__(16) __nv_bfloat16 Ws[128 * TS];
    int y = blockIdx.y;
    int tid = threadIdx.x, wid = tid >> 5, lane = tid & 31;
    const __nv_bfloat16* A = d_xtA + (size_t)y * NN_PAD * DIM;
    uint8_t* Cout = d_xt8 + (size_t)y * NN * DIM;
    {
        const uint4* src = (const uint4*)d_WT[y];
        for (int c = tid; c < 2048; c += 256) {
            int n = c >> 4, kq = c & 15;
            *(uint4*)&Ws[n * TS + kq * 8] = src[c];
        }
    }
    int rg = wid >> 1, nh = wid & 1;
    uint32_t ab0 = smem_u32(As[0]), ab1 = smem_u32(As[1]);
    uint32_t wbase = smem_u32(Ws);
    int nofs = (lane & 7) + ((lane >> 4) << 3);
    int kofs = lane & 8;
    int arow = rg * 16 + (lane & 15);
    int akof = (lane >> 4) << 3;
    int g = lane >> 2, t2 = (lane & 3) * 2;

    int tile0 = blockIdx.x * TPCX;
    int tmax = NT64_NN - tile0; if (tmax > TPCX) tmax = TPCX;
    if (tmax <= 0) return;
    load_a_tile_async(ab0, A, tile0, tid);
    CP_COMMIT(); CP_WAIT0();
    __syncthreads();

    for (int t = 0; t < tmax; t++) {
        uint32_t abase = (t & 1) ? ab1 : ab0;
        if (t + 1 < tmax) {
            load_a_tile_async((t & 1) ? ab0 : ab1, A, tile0 + t + 1, tid);
            CP_COMMIT();
        }
        float acc[8][4];
#pragma unroll
        for (int i = 0; i < 8; i++)
#pragma unroll
            for (int j = 0; j < 4; j++) acc[i][j] = 0.f;
#pragma unroll
        for (int kc = 0; kc < 8; kc++) {
            int k0 = kc * 16;
            uint32_t a0, a1, a2, a3;
            ldsm4(a0, a1, a2, a3, abase + (uint32_t)((arow * TS + k0 + akof) * 2));
#pragma unroll
            for (int nb = 0; nb < 4; nb++) {
                uint32_t b0, b1, b2, b3;
                ldsm4(b0, b1, b2, b3, wbase +
                      (uint32_t)(((nh * 64 + nb * 16 + nofs) * TS + k0 + kofs) * 2));
                mma16816(acc[nb * 2],     a0, a1, a2, a3, b0, b1);
                mma16816(acc[nb * 2 + 1], a0, a1, a2, a3, b2, b3);
            }
        }
        int row0 = (tile0 + t) * 64 + rg * 16 + g, row1 = row0 + 8;
#pragma unroll
        for (int nc = 0; nc < 8; nc++) {
            int col = nh * 64 + nc * 8 + t2;
            if (row0 < NN)
                *(uint16_t*)(Cout + (size_t)row0 * DIM + col) =
                    f32x2_to_e4m3x2(acc[nc][1] * FP8_SCALE, acc[nc][0] * FP8_SCALE);
            if (row1 < NN)
                *(uint16_t*)(Cout + (size_t)row1 * DIM + col) =
                    f32x2_to_e4m3x2(acc[nc][3] * FP8_SCALE, acc[nc][2] * FP8_SCALE);
        }
        CP_WAIT0();
        __syncthreads();
    }
}

// ---- K/V GEMM: grid (ceil(NT64_NKEY/TPC), 2); bf16 out + bias --------------
__global__ __launch_bounds__(256, 2)
void mmagemm_kv(const float* __restrict__ bk, const float* __restrict__ bv) {
    __shared__ __align__(16) __nv_bfloat16 As[2][64 * TS];
    __shared__ __align__(16) __nv_bfloat16 Ws[128 * TS];
    __shared__ float bias_s[128];
    int y = blockIdx.y;
    int tid = threadIdx.x, wid = tid >> 5, lane = tid & 31;
    __nv_bfloat16* Cout = y ? d_Vbh : d_Kbh;
    const float* bias = y ? bv : bk;
    if (tid < 128) bias_s[tid] = bias[tid];
    {
        const uint4* src = (const uint4*)d_WT[3 + y];
        for (int c = tid; c < 2048; c += 256) {
            int n = c >> 4, kq = c & 15;
            *(uint4*)&Ws[n * TS + kq * 8] = src[c];
        }
    }
    int rg = wid >> 1, nh = wid & 1;
    uint32_t ab0 = smem_u32(As[0]), ab1 = smem_u32(As[1]);
    uint32_t wbase = smem_u32(Ws);
    int nofs = (lane & 7) + ((lane >> 4) << 3);
    int kofs = lane & 8;
    int arow = rg * 16 + (lane & 15);
    int akof = (lane >> 4) << 3;
    int g = lane >> 2, t2 = (lane & 3) * 2;

    int tile0 = blockIdx.x * TPC;
    int tmax = NT64_NKEY - tile0; if (tmax > TPC) tmax = TPC;
    if (tmax <= 0) return;
    load_a_tile_async(ab0, d_relb, tile0, tid);
    CP_COMMIT(); CP_WAIT0();
    __syncthreads();

    for (int t = 0; t < tmax; t++) {
        uint32_t abase = (t & 1) ? ab1 : ab0;
        if (t + 1 < tmax) {
            load_a_tile_async((t & 1) ? ab0 : ab1, d_relb, tile0 + t + 1, tid);
            CP_COMMIT();
        }
        float acc[8][4];
#pragma unroll
        for (int i = 0; i < 8; i++)
#pragma unroll
            for (int j = 0; j < 4; j++) acc[i][j] = 0.f;
#pragma unroll
        for (int kc = 0; kc < 8; kc++) {
            int k0 = kc * 16;
            uint32_t a0, a1, a2, a3;
            ldsm4(a0, a1, a2, a3, abase + (uint32_t)((arow * TS + k0 + akof) * 2));
#pragma unroll
            for (int nb = 0; nb < 4; nb++) {
                uint32_t b0, b1, b2, b3;
                ldsm4(b0, b1, b2, b3, wbase +
                      (uint32_t)(((nh * 64 + nb * 16 + nofs) * TS + k0 + kofs) * 2));
                mma16816(acc[nb * 2],     a0, a1, a2, a3, b0, b1);
                mma16816(acc[nb * 2 + 1], a0, a1, a2, a3, b2, b3);
            }
        }
        int row0 = (tile0 + t) * 64 + rg * 16 + g, row1 = row0 + 8;
#pragma unroll
        for (int nc = 0; nc < 8; nc++) {
            int col = nh * 64 + nc * 8 + t2;
            float f0 = acc[nc][0] + bias_s[col];
            float f1 = acc[nc][1] + bias_s[col + 1];
            float f2 = acc[nc][2] + bias_s[col];
            float f3 = acc[nc][3] + bias_s[col + 1];
            if (row0 < NKEY)
                *(__nv_bfloat162*)(Cout + (size_t)row0 * DIM + col) =
                    __floats2bfloat162_rn(f0, f1);
            if (row1 < NKEY)
                *(__nv_bfloat162*)(Cout + (size_t)row1 * DIM + col) =
                    __floats2bfloat162_rn(f2, f3);
        }
        CP_WAIT0();
        __syncthreads();
    }
}

// ===================== CSR build ============================================
__global__ void count_all(const int* __restrict__ n0, const int* __restrict__ e0,
                          const int* __restrict__ n1, const int* __restrict__ e1,
                          const int* __restrict__ n2, const int* __restrict__ e2) {
    int mod = blockIdx.y;
    const int* nodes = (mod == 0) ? n0 : (mod == 1) ? n1 : n2;
    const int* edges = (mod == 0) ? e0 : (mod == 1) ? e1 : e2;
    int i = blockIdx.x * blockDim.x + threadIdx.x;
    if (i >= NNZV) return;
    atomicAdd(&d_ecnt[mod * EE + edges[i]], 1);
    atomicAdd(&d_ncnt[mod * NN + nodes[i]], 1);
}

__device__ __forceinline__ int wscan_incl(int v, int lane) {
#pragma unroll
    for (int o = 1; o < 32; o <<= 1) {
        int t = __shfl_up_sync(0xffffffffu, v, o);
        if (lane >= o) v += t;
    }
    return v;
}

__global__ void scan_kernel() {
    __shared__ int wsum[32];
    __shared__ int srun, stot;
    int b = blockIdx.x;
    int mod = b % 3;
    bool isE = (b < 3);
    int len = isE ? EE : NN;
    const int* cnt = isE ? (d_ecnt + mod * EE) : (d_ncnt + mod * NN);
    int* off = isE ? (d_eoff + mod * (EE + 1)) : (d_noff + mod * (NN + 1));
    int* cur = isE ? (d_ecur + mod * EE) : (d_ncur + mod * NN);
    int tid = threadIdx.x, warp = tid >> 5, lane = tid & 31;
    if (tid == 0) srun = 0;
    __syncthreads();
    for (int base = 0; base < len; base += 1024) {
        int v = (base + tid < len) ? cnt[base + tid] : 0;
        int incl = wscan_incl(v, lane);
        if (lane == 31) wsum[warp] = incl;
        __syncthreads();
        if (warp == 0) {
            int s = wsum[lane];
            int wincl = wscan_incl(s, lane);
            wsum[lane] = wincl - s;
            if (lane == 31) stot = wincl;
        }
        __syncthreads();
        int run = srun;
        int ex = run + wsum[warp] + incl - v;
        if (base + tid < len) { off[base + tid] = ex; cur[base + tid] = ex; }
        __syncthreads();
        if (tid == 0) srun = run + stot;
        __syncthreads();
    }
    if (tid == 0) off[len] = srun;
}

__global__ void scatter_all(const int* __restrict__ n0, const int* __restrict__ e0,
                            const int* __restrict__ n1, const int* __restrict__ e1,
                            const int* __restrict__ n2, const int* __restrict__ e2) {
    int mod = blockIdx.y;
    const int* nodes = (mod == 0) ? n0 : (mod == 1) ? n1 : n2;
    const int* edges = (mod == 0) ? e0 : (mod == 1) ? e1 : e2;
    int i = blockIdx.x * blockDim.x + threadIdx.x;
    if (i >= NNZV) return;
    int e = edges[i], n = nodes[i];
    int pe = atomicAdd(&d_ecur[mod * EE + e], 1);
    d_csrE[mod * NNZV + pe] = n;
    int pn = atomicAdd(&d_ncur[mod * NN + n], 1);
    d_csrN[mod * NNZV + pn] = e;
}

// ===================== small GEMM: C[50,128] = A@W + b (grid 4) =============
// mode 0: A = Aext (ctx) -> d_qb.  mode 1: A = headout/lsum -> d_att.
__global__ void small_nn(int mode, const float* __restrict__ Aext,
                         const float* __restrict__ W, const float* __restrict__ bias) {
    __shared__ float Asm[64 * DIM];    // rows >= CC zeroed
    __shared__ float Wsm[DIM * 32];
    float* Cout = mode ? d_att : d_qb;
    int n0 = blockIdx.x * 32;
    int tid = threadIdx.x;
    for (int i = tid; i < 64 * DIM; i += 256) {
        int q = i >> 7, k = i & 127;
        float v = 0.f;
        if (q < CC) {
            if (mode) v = d_headout[i] / d_lsum[(k >> 4) * CC + q];
            else      v = Aext[i];
        }
        Asm[i] = v;
    }
    for (int i = tid; i < DIM * 32; i += 256) {
        int k = i >> 5, c = i & 31;
        Wsm[i] = W[(size_t)k * DIM + n0 + c];
    }
    __syncthreads();
    int rg = tid >> 4;            // 0..15 -> rows rg*4..+4
    int cp = tid & 15;            // cols cp*2, cp*2+1
    float acc[4][2];
#pragma unroll
    for (int r = 0; r < 4; r++) { acc[r][0] = 0.f; acc[r][1] = 0.f; }
#pragma unroll 4
    for (int k = 0; k < DIM; k++) {
        float w0 = Wsm[k * 32 + cp * 2];
        float w1 = Wsm[k * 32 + cp * 2 + 1];
#pragma unroll
        for (int r = 0; r < 4; r++) {
            float a = Asm[(rg * 4 + r) * DIM + k];
            acc[r][0] += a * w0; acc[r][1] += a * w1;
        }
    }
    float b0 = bias[n0 + cp * 2], b1 = bias[n0 + cp * 2 + 1];
#pragma unroll
    for (int r = 0; r < 4; r++) {
        int row = rg * 4 + r;
        if (row < CC) {
            Cout[row * DIM + n0 + cp * 2]     = acc[r][0] + b0;
            Cout[row * DIM + n0 + cp * 2 + 1] = acc[r][1] + b1;
        }
    }
}

// ===================== hypergraph gathers (fp8 payloads) ====================
__global__ void edge_mean_kernel() {
    int gw = (blockIdx.x * blockDim.x + threadIdx.x) >> 5;
    int lane = threadIdx.x & 31;
    if (gw >= 3 * EE) return;
    int mod = gw / EE, e = gw - mod * EE;
    const int* __restrict__ base = d_csrE + mod * NNZV;
    int s0 = d_eoff[mod * (EE + 1) + e];
    int s1 = d_eoff[mod * (EE + 1) + e + 1];
    const uint32_t* __restrict__ xtm = (const uint32_t*)(d_xt8 + (size_t)mod * NN * DIM);
    float a0 = 0.f, a1 = 0.f, a2 = 0.f, a3 = 0.f;
    int j = s0;
    for (; j + 8 <= s1; j += 8) {
        int n[8];
#pragma unroll
        for (int u = 0; u < 8; u++) n[u] = base[j + u];
#pragma unroll
        for (int u = 0; u < 8; u++) {
            uint32_t p = xtm[(size_t)n[u] * 32 + lane];
            float2 f0 = e4m3x2_to_f32x2((uint16_t)(p & 0xFFFF));
            float2 f1 = e4m3x2_to_f32x2((uint16_t)(p >> 16));
            a0 += f0.x; a1 += f0.y; a2 += f1.x; a3 += f1.y;
        }
    }
    for (; j < s1; j++) {
        uint32_t p = xtm[(size_t)base[j] * 32 + lane];
        float2 f0 = e4m3x2_to_f32x2((uint16_t)(p & 0xFFFF));
        float2 f1 = e4m3x2_to_f32x2((uint16_t)(p >> 16));
        a0 += f0.x; a1 += f0.y; a2 += f1.x; a3 += f1.y;
    }
    int deg = s1 - s0; if (deg < 1) deg = 1;
    float inv = 1.f / (float)deg;
    uint16_t w0 = f32x2_to_e4m3x2(a1 * inv, a0 * inv);
    uint16_t w1 = f32x2_to_e4m3x2(a3 * inv, a2 * inv);
    ((uint32_t*)d_me8)[((size_t)mod * EE + e) * 32 + lane] =
        (uint32_t)w0 | ((uint32_t)w1 << 16);
}

__global__ void node_out_kernel(const float* __restrict__ bias_item,
                                const float* __restrict__ bias_entity,
                                const float* __restrict__ bias_word) {
    int gw = (blockIdx.x * blockDim.x + threadIdx.x) >> 5;
    int lane = threadIdx.x & 31;
    if (gw >= 3 * NN) return;
    int mod = gw / NN, n = gw - mod * NN;
    const int* __restrict__ base = d_csrN + mod * NNZV;
    int s0 = d_noff[mod * (NN + 1) + n];
    int s1 = d_noff[mod * (NN + 1) + n + 1];
    const uint32_t* __restrict__ mem = (const uint32_t*)(d_me8 + (size_t)mod * EE * DIM);
    float a0 = 0.f, a1 = 0.f, a2 = 0.f, a3 = 0.f;
    int j = s0;
    for (; j + 8 <= s1; j += 8) {
        int e8[8];
#pragma unroll
        for (int u = 0; u < 8; u++) e8[u] = base[j + u];
#pragma unroll
        for (int u = 0; u < 8; u++) {
            uint32_t p = mem[(size_t)e8[u] * 32 + lane];
            float2 f0 = e4m3x2_to_f32x2((uint16_t)(p & 0xFFFF));
            float2 f1 = e4m3x2_to_f32x2((uint16_t)(p >> 16));
            a0 += f0.x; a1 += f0.y; a2 += f1.x; a3 += f1.y;
        }
    }
    for (; j < s1; j++) {
        uint32_t p = mem[(size_t)base[j] * 32 + lane];
        float2 f0 = e4m3x2_to_f32x2((uint16_t)(p & 0xFFFF));
        float2 f1 = e4m3x2_to_f32x2((uint16_t)(p >> 16));
        a0 += f0.x; a1 += f0.y; a2 += f1.x; a3 += f1.y;
    }
    int deg = s1 - s0; if (deg < 1) deg = 1;
    float inv = 1.f / ((float)deg * FP8_SCALE);
    const float* bias = (mod == 0) ? bias_item : (mod == 1) ? bias_entity : bias_word;
    float4 bv = *(const float4*)&bias[lane * 4];
    __nv_bfloat162 b01 = __floats2bfloat162_rn(a0 * inv + bv.x, a1 * inv + bv.y);
    __nv_bfloat162 b23 = __floats2bfloat162_rn(a2 * inv + bv.z, a3 * inv + bv.w);
    uint2 o; o.x = *(uint32_t*)&b01; o.y = *(uint32_t*)&b23;
    ((uint2*)d_relb)[((size_t)mod * NN + n) * 32 + lane] = o;
}

// ===================== attention: scalar scores + mma P·V ===================
#define AT_TILES 235
#define WST 264
#define VST 264
__global__ void attn_kernel() {
    int bx = blockIdx.x;
    int h = bx / AT_TILES;
    int k0 = (bx % AT_TILES) * 256;
    int tid = threadIdx.x;
    int key = k0 + tid;
    __shared__ float qs[CC * DH];
    __shared__ __align__(16) __nv_bfloat16 wsm[64 * WST];
    __shared__ __align__(16) __nv_bfloat16 vsm[24 * VST];
    for (int i = tid; i < CC * DH; i += 256) {
        int q = i / DH, d = i % DH;
        qs[i] = d_qb[q * DIM + h * DH + d];
    }
    for (int i = tid; i < 512; i += 256) {
        int kk = i >> 1, nc = i & 1;
        __nv_bfloat16 tmp[8];
        if (k0 + kk < NKEY) {
            *(uint4*)tmp = *(const uint4*)&d_Vbh[(size_t)(k0 + kk) * DIM + h * DH + nc * 8];
        } else {
#pragma unroll
            for (int j = 0; j < 8; j++) tmp[j] = __float2bfloat16(0.f);
        }
#pragma unroll
        for (int j = 0; j < 8; j++) vsm[(nc * 8 + j) * VST + kk] = tmp[j];
    }
    {
        vsm[16 * VST + tid] = __float2bfloat16(1.f);
        __nv_bfloat16 zz = __float2bfloat16(0.f);
#pragma unroll
        for (int r = 17; r < 24; r++) vsm[r * VST + tid] = zz;
    }
    float kv[16];
    bool valid = key < NKEY;
    if (valid) {
        const __nv_bfloat16* kr = d_Kbh + (size_t)key * DIM + h * DH;
        uint4 kA = *(const uint4*)kr;
        uint4 kB = *(const uint4*)(kr + 8);
        const uint32_t* kw = (const uint32_t*)&kA;
#pragma unroll
        for (int j = 0; j < 4; j++) {
            float2 f = __bfloat1622float2(*(__nv_bfloat162*)&kw[j]);
            kv[2 * j] = f.x; kv[2 * j + 1] = f.y;
        }
        const uint32_t* kw2 = (const uint32_t*)&kB;
#pragma unroll
        for (int j = 0; j < 4; j++) {
            float2 f = __bfloat1622float2(*(__nv_bfloat162*)&kw2[j]);
            kv[8 + 2 * j] = f.x; kv[8 + 2 * j + 1] = f.y;
        }
    } else {
#pragma unroll
        for (int j = 0; j < 16; j++) kv[j] = 0.f;
    }
#pragma unroll 5
    for (int q = 0; q < CC; q++) {
        const float* qp = &qs[q * DH];
        float s = 0.f;
#pragma unroll
        for (int j = 0; j < 16; j++) s += qp[j] * kv[j];
        float w = valid ? fast_exp(s * 0.25f) : 0.f;
        wsm[q * WST + tid] = __float2bfloat16(w);
    }
    {
        __nv_bfloat16 zz = __float2bfloat16(0.f);
#pragma unroll
        for (int q = CC; q < 64; q++) wsm[q * WST + tid] = zz;
    }
    __syncthreads();
    int wid = tid >> 5, lane = tid & 31;
    int mb = wid >> 1;
    int nnb = (wid & 1) ? 1 : 2;
    int nb0 = (wid & 1) ? 2 : 0;
    uint32_t wbase = smem_u32(wsm), vbase = smem_u32(vsm);
    int ar = mb * 16 + (lane & 15), ak = (lane >> 4) << 3;
    int br = lane & 7, bk = (lane >> 3) << 3;
    float acc[2][4];
#pragma unroll
    for (int t = 0; t < 2; t++)
#pragma unroll
        for (int j = 0; j < 4; j++) acc[t][j] = 0.f;
#pragma unroll
    for (int c = 0; c < 8; c++) {
        int kc = c * 32;
        uint32_t a00, a01, a02, a03, a10, a11, a12, a13;
        ldsm4(a00, a01, a02, a03, wbase + (uint32_t)((ar * WST + kc + ak) * 2));
        ldsm4(a10, a11, a12, a13, wbase + (uint32_t)((ar * WST + kc + 16 + ak) * 2));
        for (int t = 0; t < nnb; t++) {
            int nb = nb0 + t;
            uint32_t b0, b1, b2, b3;
            ldsm4(b0, b1, b2, b3, vbase + (uint32_t)(((nb * 8 + br) * VST + kc + bk) * 2));
            mma16816(acc[t], a00, a01, a02, a03, b0, b1);
            mma16816(acc[t], a10, a11, a12, a13, b2, b3);
        }
    }
    int g = lane >> 2, t2 = (lane & 3) * 2;
    int q0 = mb * 16 + g, q1 = q0 + 8;
    for (int t = 0; t < nnb; t++) {
        int nb = nb0 + t;
        int col = nb * 8 + t2;
        if (col < 16) {
            if (q0 < CC) {
                atomicAdd(&d_headout[q0 * DIM + h * DH + col],     acc[t][0]);
                atomicAdd(&d_headout[q0 * DIM + h * DH + col + 1], acc[t][1]);
            }
            if (q1 < CC) {
                atomicAdd(&d_headout[q1 * DIM + h * DH + col],     acc[t][2]);
                atomicAdd(&d_headout[q1 * DIM + h * DH + col + 1], acc[t][3]);
            }
        } else if (col == 16) {
            if (q0 < CC) atomicAdd(&d_lsum[h * CC + q0], acc[t][0]);
            if (q1 < CC) atomicAdd(&d_lsum[h * CC + q1], acc[t][2]);
        }
    }
}

// ===================== parallel self-attn energies ==========================
// grid 100: task<50 -> es1[task] from att rows; task>=50 -> es2[task-50] from ctx.
__global__ void energies_kernel(const float* __restrict__ ctx,
                                const float* __restrict__ A1, const float* __restrict__ B1,
                                const float* __restrict__ A2, const float* __restrict__ B2) {
    int task = blockIdx.x;
    int d = threadIdx.x;          // 128 threads
    __shared__ float hs[DIM];
    __shared__ float red[4];
    const float* A; const float* B; const float* h; float* dst;
    if (task < CC) { h = d_att + (size_t)task * DIM; A = A1; B = B1; dst = &d_es1[task]; }
    else { h = ctx + (size_t)(task - CC) * DIM; A = A2; B = B2; dst = &d_es2[task - CC]; }
    hs[d] = h[d];
    __syncthreads();
    float acc = 0.f;
#pragma unroll 4
    for (int k = 0; k < DIM; k++) acc += hs[k] * A[(size_t)k * DIM + d];
    float v = tanhf(acc) * B[d];
#pragma unroll
    for (int o = 16; o; o >>= 1) v += __shfl_xor_sync(0xffffffffu, v, o);
    if ((d & 31) == 0) red[d >> 5] = v;
    __syncthreads();
    if (d == 0) *dst = (red[0] + red[1]) + (red[2] + red[3]);
}

// ===================== tail: softmax1 -> u -> e2[u] -> softmax2 -> urepr ====
__global__ void tail_kernel(const float* __restrict__ ctx,
                            const float* __restrict__ A2, const float* __restrict__ B2) {
    int d = threadIdx.x;          // 128 threads
    __shared__ float ws[64];
    __shared__ float u_s[DIM];
    __shared__ float red[4];
    __shared__ float e2u;
    if (d == 0) {
        float m = -1e30f;
        for (int r = 0; r < CC; r++) m = fmaxf(m, d_es1[r]);
        float s = 0.f;
        for (int r = 0; r < CC; r++) { float w = __expf(d_es1[r] - m); ws[r] = w; s += w; }
        float inv = 1.f / s;
        for (int r = 0; r < CC; r++) ws[r] *= inv;
    }
    __syncthreads();
    float u = 0.f;
    for (int r = 0; r < CC; r++) u += ws[r] * d_att[(size_t)r * DIM + d];
    u_s[d] = u;
    __syncthreads();
    float acc = 0.f;
#pragma unroll 4
    for (int k = 0; k < DIM; k++) acc += u_s[k] * A2[(size_t)k * DIM + d];
    float v = tanhf(acc) * B2[d];
#pragma unroll
    for (int o = 16; o; o >>= 1) v += __shfl_xor_sync(0xffffffffu, v, o);
    if ((d & 31) == 0) red[d >> 5] = v;
    __syncthreads();
    if (d == 0) {
        e2u = (red[0] + red[1]) + (red[2] + red[3]);
        float m = e2u;
        for (int r = 0; r < CC; r++) m = fmaxf(m, d_es2[r]);
        float s = 0.f;
        for (int r = 0; r < CC; r++) { float w = __expf(d_es2[r] - m); ws[r] = w; s += w; }
        float wu = __expf(e2u - m); ws[CC] = wu; s += wu;
        float inv = 1.f / s;
        for (int r = 0; r <= CC; r++) ws[r] *= inv;
    }
    __syncthreads();
    float o = 0.f;
    for (int r = 0; r < CC; r++) o += ws[r] * ctx[(size_t)r * DIM + d];
    o += ws[CC] * u_s[d];
    d_urepr[d] = o;
}

// ===================== final scores =========================================
__global__ void recscore_kernel(const float* __restrict__ W,
                                const float* __restrict__ b,
                                float* __restrict__ out) {
    __shared__ float us[DIM];
    int tid = threadIdx.x;
    if (tid < DIM) us[tid] = d_urepr[tid];
    __syncthreads();
    int j = blockIdx.x * 256 + tid;
    if (j >= NENT) return;
    float a0 = 0.f, a1 = 0.f, a2 = 0.f, a3 = 0.f;
#pragma unroll
    for (int d = 0; d < DIM; d += 4) {
        a0 += us[d + 0] * W[(size_t)(d + 0) * NENT + j];
        a1 += us[d + 1] * W[(size_t)(d + 1) * NENT + j];
        a2 += us[d + 2] * W[(size_t)(d + 2) * NENT + j];
        a3 += us[d + 3] * W[(size_t)(d + 3) * NENT + j];
    }
    out[j] = (a0 + a1) + (a2 + a3) + b[j];
}

// ===================== launch ===============================================
extern "C" void kernel_launch(void* const* d_in, const int* in_sizes, int n_in,
                              void* d_out, int out_size) {
    const float* item_emb     = (const float*)d_in[0];
    const float* entity_emb   = (const float*)d_in[1];
    const float* word_emb     = (const float*)d_in[2];
    const float* context_ent  = (const float*)d_in[3];
    const float* theta_item   = (const float*)d_in[4];
    const float* bias_item    = (const float*)d_in[5];
    const float* theta_entity = (const float*)d_in[6];
    const float* bias_entity  = (const float*)d_in[7];
    const float* theta_word   = (const float*)d_in[8];
    const float* bias_word    = (const float*)d_in[9];
    const float* Wq = (const float*)d_in[10];  const float* bq = (const float*)d_in[11];
    const float* Wk = (const float*)d_in[12];  const float* bk = (const float*)d_in[13];
    const float* Wv = (const float*)d_in[14];  const float* bv = (const float*)d_in[15];
    const float* Wo = (const float*)d_in[16];  const float* bo = (const float*)d_in[17];
    const float* a_his = (const float*)d_in[18]; const float* b_his = (const float*)d_in[19];
    const float* a_kg  = (const float*)d_in[20]; const float* b_kg  = (const float*)d_in[21];
    const float* rec_W = (const float*)d_in[22]; const float* rec_b = (const float*)d_in[23];
    const int* item_nodes   = (const int*)d_in[24];
    const int* item_edges   = (const int*)d_in[25];
    const int* entity_nodes = (const int*)d_in[26];
    const int* entity_edges = (const int*)d_in[27];
    const int* word_nodes   = (const int*)d_in[28];
    const int* word_edges   = (const int*)d_in[29];
    float* out = (float*)d_out;

    zero_kernel<<<(3 * NN + 255) / 256, 256>>>();

    convW_kernel<<<dim3(5, 8), 128>>>(theta_item, theta_entity, theta_word, Wk, Wv);
    convA_kernel<<<(3 * NN_PAD * 16 + 127) / 128, 128>>>(item_emb, entity_emb, word_emb);

    // Q projection (parallel small GEMM)
    small_nn<<<4, 256>>>(0, context_ent, Wq, bq);

    // xt GEMMs
    mmagemm_x<<<dim3((NT64_NN + TPCX - 1) / TPCX, 3), 256>>>();

    // CSR build
    dim3 cgrid((NNZV + 255) / 256, 3);
    count_all<<<cgrid, 256>>>(item_nodes, item_edges, entity_nodes, entity_edges,
                              word_nodes, word_edges);
    scan_kernel<<<6, 1024>>>();
    scatter_all<<<cgrid, 256>>>(item_nodes, item_edges, entity_nodes, entity_edges,
                                word_nodes, word_edges);

    // hypergraph aggregation
    edge_mean_kernel<<<(3 * EE + 7) / 8, 256>>>();
    node_out_kernel<<<(3 * NN + 7) / 8, 256>>>(bias_item, bias_entity, bias_word);

    // K and V projections
    mmagemm_kv<<<dim3((NT64_NKEY + TPC - 1) / TPC, 2), 256>>>(bk, bv);

    // attention
    attn_kernel<<<NHEAD * AT_TILES, 256>>>();

    // Wo (parallel small GEMM, fused normalization)
    small_nn<<<4, 256>>>(1, nullptr, Wo, bo);

    // parallel energies + tail
    energies_kernel<<<2 * CC, 128>>>(context_ent, a_his, b_his, a_kg, b_kg);
    tail_kernel<<<1, 128>>>(context_ent, a_kg, b_kg);

    // final scores
    recscore_kernel<<<(NENT + 255) / 256, 256>>>(rec_W, rec_b, out);
}